// round 5
// baseline (speedup 1.0000x reference)
#include <cuda_runtime.h>
#include <math.h>

#define B_ 2
#define T_ 2048
#define C_ 1024
#define H_ 16
#define D_ 64
#define M_ (B_*T_)
#define SCALE 0.125f   // 1/sqrt(64)

typedef unsigned long long ull;

// Packed fp32x2 helpers (sm_103a FFMA2 path)
#define PACK2(d, lo, hi)  asm("mov.b64 %0, {%1,%2};" : "=l"(d) : "f"(lo), "f"(hi))
#define UNPACK2(lo, hi, s) asm("mov.b64 {%0,%1}, %2;" : "=f"(lo), "=f"(hi) : "l"(s))
#define FMA2(d, a, b)     asm("fma.rn.f32x2 %0, %1, %2, %0;" : "+l"(d) : "l"(a), "l"(b))
#define MUL2(d, a, b)     asm("mul.rn.f32x2 %0, %1, %2;" : "=l"(d) : "l"(a), "l"(b))

// Scratch (allocation-free contract: __device__ globals)
__device__ float  g_q[B_*H_*T_*D_];
__device__ float  g_k[B_*H_*T_*D_];
__device__ float  g_v[B_*H_*T_*D_];
__device__ float  g_att[B_*T_*C_];
__device__ float2 g_cs[T_*32];     // RoPE cos/sin table

// ---------------------------------------------------------------------------
// RoPE table: 65536 threads, fp64 once. cos/sin(t * 10000^(-2i/64))
// ---------------------------------------------------------------------------
__global__ void rope_table(float2* __restrict__ tab)
{
    const int idx = blockIdx.x * blockDim.x + threadIdx.x;
    if (idx >= T_*32) return;
    const int t = idx >> 5, i = idx & 31;
    const double inv = pow(10000.0, -(double)(2*i) / 64.0);
    const double ang = (double)t * inv;
    tab[idx] = make_float2((float)cos(ang), (float)sin(ang));
}

// ---------------------------------------------------------------------------
// GEMM core: out = A[M,1024] @ W[N,1024]^T + bias, 128x128 tile, 8x8/thread,
// transposed smem (k-major), packed f32x2 FMAs.
// mode 0: scatter [B,H,T,D] + RoPE.  mode 1: scatter, no rope.  mode 2: plain.
// ---------------------------------------------------------------------------
__device__ __forceinline__
void gemm_body(const float* __restrict__ A, const float* __restrict__ W,
               const float* __restrict__ bias, float* __restrict__ out,
               const float2* __restrict__ cs, int mode)
{
    __shared__ float As[16][132];
    __shared__ float Ws[16][132];
    const int tid = threadIdx.x;
    const int tx = tid & 15, ty = tid >> 4;
    const int m0 = blockIdx.y << 7, n0 = blockIdx.x << 7;

    ull acc[8][4];
#pragma unroll
    for (int r = 0; r < 8; r++)
#pragma unroll
        for (int p = 0; p < 4; p++) acc[r][p] = 0ull;

    for (int k0 = 0; k0 < C_; k0 += 16) {
        __syncthreads();
#pragma unroll
        for (int ld = 0; ld < 2; ld++) {
            const int job = tid + (ld << 8);
            const int r = job >> 2, v = job & 3;
            const float4 a4 = *(const float4*)&A[(size_t)(m0 + r) * C_ + k0 + 4*v];
            As[4*v+0][r] = a4.x; As[4*v+1][r] = a4.y;
            As[4*v+2][r] = a4.z; As[4*v+3][r] = a4.w;
            const float4 w4 = *(const float4*)&W[(size_t)(n0 + r) * C_ + k0 + 4*v];
            Ws[4*v+0][r] = w4.x; Ws[4*v+1][r] = w4.y;
            Ws[4*v+2][r] = w4.z; Ws[4*v+3][r] = w4.w;
        }
        __syncthreads();
#pragma unroll
        for (int kk = 0; kk < 16; kk++) {
            const float4 aA = *(const float4*)&As[kk][8*ty];
            const float4 aB = *(const float4*)&As[kk][8*ty + 4];
            const ulonglong2 wA = *(const ulonglong2*)&Ws[kk][8*tx];
            const ulonglong2 wB = *(const ulonglong2*)&Ws[kk][8*tx + 4];
            const float a[8] = {aA.x, aA.y, aA.z, aA.w, aB.x, aB.y, aB.z, aB.w};
            ull pa[8];
#pragma unroll
            for (int r = 0; r < 8; r++) PACK2(pa[r], a[r], a[r]);
#pragma unroll
            for (int r = 0; r < 8; r++) {
                FMA2(acc[r][0], pa[r], wA.x);
                FMA2(acc[r][1], pa[r], wA.y);
                FMA2(acc[r][2], pa[r], wB.x);
                FMA2(acc[r][3], pa[r], wB.y);
            }
        }
    }

    const int n_base = n0 + 8*tx;
    const float4 b0 = *(const float4*)&bias[n_base];
    const float4 b1 = *(const float4*)&bias[n_base + 4];
    const float bb[8] = {b0.x, b0.y, b0.z, b0.w, b1.x, b1.y, b1.z, b1.w};

#pragma unroll
    for (int r = 0; r < 8; r++) {
        const int m = m0 + 8*ty + r;
        float o[8];
#pragma unroll
        for (int p = 0; p < 4; p++) UNPACK2(o[2*p], o[2*p+1], acc[r][p]);
#pragma unroll
        for (int j = 0; j < 8; j++) o[j] += bb[j];

        if (mode == 0) {  // RoPE on (even,odd) pairs
            const int t = m & (T_-1);
#pragma unroll
            for (int p = 0; p < 4; p++) {
                const int i = ((n_base + 2*p) & 63) >> 1;
                const float2 csv = cs[t*32 + i];
                const float x1 = o[2*p], x2 = o[2*p+1];
                o[2*p]   = x1*csv.x - x2*csv.y;
                o[2*p+1] = x1*csv.y + x2*csv.x;
            }
        }

        float4 o0 = {o[0], o[1], o[2], o[3]};
        float4 o1 = {o[4], o[5], o[6], o[7]};
        if (mode <= 1) {  // scatter to [B,H,T,D]
            const int b = m >> 11, t = m & (T_-1);
            const int h = n_base >> 6, d = n_base & 63;
            float* dst = out + (((size_t)(b*H_ + h) * T_) + t) * D_ + d;
            *(float4*)dst = o0;
            *(float4*)(dst + 4) = o1;
        } else {
            float* dst = out + (size_t)m * C_ + n_base;
            *(float4*)dst = o0;
            *(float4*)(dst + 4) = o1;
        }
    }
}

__global__ __launch_bounds__(256, 2)
void qkv_gemm(const float* __restrict__ x,
              const float* __restrict__ Wq, const float* __restrict__ bq,
              const float* __restrict__ Wk, const float* __restrict__ bk,
              const float* __restrict__ Wv, const float* __restrict__ bv,
              float* __restrict__ q, float* __restrict__ k, float* __restrict__ v,
              const float2* __restrict__ cs)
{
    const int z = blockIdx.z;
    const float* W = (z == 0) ? Wq : (z == 1) ? Wk : Wv;
    const float* b = (z == 0) ? bq : (z == 1) ? bk : bv;
    float* o       = (z == 0) ? q  : (z == 1) ? k  : v;
    gemm_body(x, W, b, o, cs, (z < 2) ? 0 : 1);
}

__global__ __launch_bounds__(256, 2)
void out_gemm(const float* __restrict__ A, const float* __restrict__ W,
              const float* __restrict__ bias, float* __restrict__ out)
{
    gemm_body(A, W, bias, out, nullptr, 2);
}

// ---------------------------------------------------------------------------
// Flash attention, causal. 64 queries x 64 keys per tile, 256 threads,
// 4x4/thread with packed f32x2. Q, K, P transposed in smem for LDS.128.
// ---------------------------------------------------------------------------
__global__ __launch_bounds__(256)
void attn_kernel(const float* __restrict__ q, const float* __restrict__ k,
                 const float* __restrict__ v, float* __restrict__ out)
{
    extern __shared__ float smem[];
    float (*Qt)[68] = (float(*)[68]) smem;                      // Qt[d][row]
    float (*Kt)[68] = (float(*)[68])(smem + 64*68);             // Kt[d][col]
    float (*Vs)[64] = (float(*)[64])(smem + 2*64*68);           // Vs[j][d]
    float (*Pt)[68] = (float(*)[68])(smem + 2*64*68 + 64*64);   // Pt[j][row]

    const int tid = threadIdx.x;
    const int tx = tid & 15, ty = tid >> 4;
    const int bh = blockIdx.y;
    const int b = bh >> 4, h = bh & (H_-1);
    const int q0 = blockIdx.x << 6;

    const float* qb = q + (size_t)bh * T_ * D_;
    const float* kb = k + (size_t)bh * T_ * D_;
    const float* vb = v + (size_t)bh * T_ * D_;

    // load Q tile transposed
#pragma unroll
    for (int ld = 0; ld < 4; ld++) {
        const int job = tid + (ld << 8);
        const int r = job >> 4, vv = job & 15;
        const float4 q4 = *(const float4*)&qb[(size_t)(q0 + r) * D_ + 4*vv];
        Qt[4*vv+0][r] = q4.x; Qt[4*vv+1][r] = q4.y;
        Qt[4*vv+2][r] = q4.z; Qt[4*vv+3][r] = q4.w;
    }

    float m_r[4], l_r[4];
    ull acc[2][4];  // packed along rows: pairs (r0,r1),(r2,r3) x 4 cols
#pragma unroll
    for (int r = 0; r < 4; r++) { m_r[r] = -1e30f; l_r[r] = 0.f; }
#pragma unroll
    for (int g = 0; g < 2; g++)
#pragma unroll
        for (int c = 0; c < 4; c++) acc[g][c] = 0ull;

    const int ntiles = (q0 >> 6) + 1;
    for (int kt = 0; kt < ntiles; kt++) {
        const int k0 = kt << 6;
        __syncthreads();
#pragma unroll
        for (int ld = 0; ld < 4; ld++) {
            const int job = tid + (ld << 8);
            const int r = job >> 4, vv = job & 15;
            const float4 k4 = *(const float4*)&kb[(size_t)(k0 + r) * D_ + 4*vv];
            Kt[4*vv+0][r] = k4.x; Kt[4*vv+1][r] = k4.y;
            Kt[4*vv+2][r] = k4.z; Kt[4*vv+3][r] = k4.w;
            *(float4*)&Vs[r][4*vv] = *(const float4*)&vb[(size_t)(k0 + r) * D_ + 4*vv];
        }
        __syncthreads();

        // scores (packed along cols)
        ull sp[4][2];
#pragma unroll
        for (int r = 0; r < 4; r++) { sp[r][0] = 0ull; sp[r][1] = 0ull; }
#pragma unroll 4
        for (int d = 0; d < D_; d++) {
            const ulonglong2 kv = *(const ulonglong2*)&Kt[d][4*tx];
            const float4 qv = *(const float4*)&Qt[d][4*ty];
            const float qa[4] = {qv.x, qv.y, qv.z, qv.w};
            ull pq[4];
#pragma unroll
            for (int r = 0; r < 4; r++) PACK2(pq[r], qa[r], qa[r]);
#pragma unroll
            for (int r = 0; r < 4; r++) {
                FMA2(sp[r][0], pq[r], kv.x);
                FMA2(sp[r][1], pq[r], kv.y);
            }
        }

        // unpack, mask, online softmax
        float s[4][4], alpha[4];
#pragma unroll
        for (int r = 0; r < 4; r++) {
            UNPACK2(s[r][0], s[r][1], sp[r][0]);
            UNPACK2(s[r][2], s[r][3], sp[r][1]);
            const int qi = q0 + 4*ty + r;
            float rm = -1e30f;
#pragma unroll
            for (int c = 0; c < 4; c++) {
                const int kj = k0 + 4*tx + c;
                s[r][c] = (kj <= qi) ? s[r][c] * SCALE : -1e30f;
                rm = fmaxf(rm, s[r][c]);
            }
#pragma unroll
            for (int off = 8; off > 0; off >>= 1)
                rm = fmaxf(rm, __shfl_xor_sync(0xffffffffu, rm, off));
            const float mnew = fmaxf(m_r[r], rm);
            alpha[r] = __expf(m_r[r] - mnew);
            m_r[r] = mnew;
            float rs = 0.f;
#pragma unroll
            for (int c = 0; c < 4; c++) {
                const float p = __expf(s[r][c] - mnew);
                s[r][c] = p;
                rs += p;
            }
#pragma unroll
            for (int off = 8; off > 0; off >>= 1)
                rs += __shfl_xor_sync(0xffffffffu, rs, off);
            l_r[r] = l_r[r] * alpha[r] + rs;
        }

        // rescale packed accumulator
        ull pal0, pal1;
        PACK2(pal0, alpha[0], alpha[1]);
        PACK2(pal1, alpha[2], alpha[3]);
#pragma unroll
        for (int c = 0; c < 4; c++) {
            MUL2(acc[0][c], acc[0][c], pal0);
            MUL2(acc[1][c], acc[1][c], pal1);
        }

        // store P transposed: column vectors are contiguous -> STS.128
#pragma unroll
        for (int c = 0; c < 4; c++) {
            float4 col = {s[0][c], s[1][c], s[2][c], s[3][c]};
            *(float4*)&Pt[4*tx + c][4*ty] = col;
        }
        __syncthreads();

        // PV (acc packed along rows)
#pragma unroll 4
        for (int j = 0; j < 64; j++) {
            const ulonglong2 pv = *(const ulonglong2*)&Pt[j][4*ty];
            const float4 vv = *(const float4*)&Vs[j][4*tx];
            const float va[4] = {vv.x, vv.y, vv.z, vv.w};
            ull pw[4];
#pragma unroll
            for (int c = 0; c < 4; c++) PACK2(pw[c], va[c], va[c]);
#pragma unroll
            for (int c = 0; c < 4; c++) {
                FMA2(acc[0][c], pv.x, pw[c]);
                FMA2(acc[1][c], pv.y, pw[c]);
            }
        }
    }

    // epilogue: normalize and write [B,T,C]
    float oacc[4][4];
#pragma unroll
    for (int c = 0; c < 4; c++) {
        UNPACK2(oacc[0][c], oacc[1][c], acc[0][c]);
        UNPACK2(oacc[2][c], oacc[3][c], acc[1][c]);
    }
#pragma unroll
    for (int r = 0; r < 4; r++) {
        const int qi = q0 + 4*ty + r;
        const float inv_l = 1.f / l_r[r];
        float4 o = {oacc[r][0]*inv_l, oacc[r][1]*inv_l, oacc[r][2]*inv_l, oacc[r][3]*inv_l};
        *(float4*)&out[((size_t)(b*T_ + qi)) * C_ + h*D_ + 4*tx] = o;
    }
}

// ---------------------------------------------------------------------------
extern "C" void kernel_launch(void* const* d_in, const int* in_sizes, int n_in,
                              void* d_out, int out_size)
{
    const float* x  = (const float*)d_in[0];
    const float* Wq = (const float*)d_in[1];
    const float* bq = (const float*)d_in[2];
    const float* Wk = (const float*)d_in[3];
    const float* bk = (const float*)d_in[4];
    const float* Wv = (const float*)d_in[5];
    const float* bv = (const float*)d_in[6];
    const float* Wo = (const float*)d_in[7];
    const float* bo = (const float*)d_in[8];
    float* out = (float*)d_out;

    float *qp, *kp, *vp, *attp;
    float2* csp;
    cudaGetSymbolAddress((void**)&qp,   g_q);
    cudaGetSymbolAddress((void**)&kp,   g_k);
    cudaGetSymbolAddress((void**)&vp,   g_v);
    cudaGetSymbolAddress((void**)&attp, g_att);
    cudaGetSymbolAddress((void**)&csp,  g_cs);

    rope_table<<<(T_*32)/256, 256>>>(csp);

    qkv_gemm<<<dim3(C_/128, M_/128, 3), 256>>>(x, Wq, bq, Wk, bk, Wv, bv,
                                               qp, kp, vp, csp);

    const size_t smem = (size_t)(64*68*3 + 64*64) * sizeof(float);
    cudaFuncSetAttribute(attn_kernel, cudaFuncAttributeMaxDynamicSharedMemorySize, (int)smem);
    attn_kernel<<<dim3(T_/64, B_*H_), 256, smem>>>(qp, kp, vp, attp);

    out_gemm<<<dim3(C_/128, M_/128), 256>>>(attp, Wo, bo, out);
}

// round 8
// speedup vs baseline: 1.3466x; 1.3466x over previous
#include <cuda_runtime.h>
#include <cuda_bf16.h>
#include <mma.h>
#include <math.h>
#include <stdint.h>

using namespace nvcuda;

#define B_ 2
#define T_ 2048
#define C_ 1024
#define H_ 16
#define D_ 64
#define M_ (B_*T_)
#define SCALE 0.125f   // 1/sqrt(64)

typedef unsigned long long ull;

// Packed fp32x2 helpers (attention kernel)
#define PACK2(d, lo, hi)  asm("mov.b64 %0, {%1,%2};" : "=l"(d) : "f"(lo), "f"(hi))
#define UNPACK2(lo, hi, s) asm("mov.b64 {%0,%1}, %2;" : "=f"(lo), "=f"(hi) : "l"(s))
#define FMA2(d, a, b)     asm("fma.rn.f32x2 %0, %1, %2, %0;" : "+l"(d) : "l"(a), "l"(b))
#define MUL2(d, a, b)     asm("mul.rn.f32x2 %0, %1, %2;" : "=l"(d) : "l"(a), "l"(b))

// ---------------------------------------------------------------------------
// Scratch (allocation-free contract: __device__ globals)
// ---------------------------------------------------------------------------
__device__ float  g_q[B_*H_*T_*D_];
__device__ float  g_k[B_*H_*T_*D_];
__device__ float  g_v[B_*H_*T_*D_];
__device__ float  g_att[B_*T_*C_];
__device__ float2 g_cs[T_*32];     // RoPE cos/sin table
// bf16 split-precision operands
__device__ __nv_bfloat16 g_x_hi[M_*C_],  g_x_lo[M_*C_];
__device__ __nv_bfloat16 g_a_hi[M_*C_],  g_a_lo[M_*C_];
__device__ __nv_bfloat16 g_w_hi[4][C_*C_], g_w_lo[4][C_*C_];

// ---------------------------------------------------------------------------
// RoPE table
// ---------------------------------------------------------------------------
__global__ void rope_table(float2* __restrict__ tab)
{
    const int idx = blockIdx.x * blockDim.x + threadIdx.x;
    if (idx >= T_*32) return;
    const int t = idx >> 5, i = idx & 31;
    const double inv = pow(10000.0, -(double)(2*i) / 64.0);
    const double ang = (double)t * inv;
    tab[idx] = make_float2((float)cos(ang), (float)sin(ang));
}

// ---------------------------------------------------------------------------
// fp32 -> (bf16 hi, bf16 lo) split
// ---------------------------------------------------------------------------
__global__ __launch_bounds__(256)
void cvt_split(const float* __restrict__ in, __nv_bfloat16* __restrict__ hi,
               __nv_bfloat16* __restrict__ lo, int n4)
{
    const int i = blockIdx.x * blockDim.x + threadIdx.x;
    if (i >= n4) return;
    const float4 v = ((const float4*)in)[i];
    float f[4] = {v.x, v.y, v.z, v.w};
    __nv_bfloat16 h[4], l[4];
#pragma unroll
    for (int j = 0; j < 4; j++) {
        h[j] = __float2bfloat16(f[j]);
        l[j] = __float2bfloat16(f[j] - __bfloat162float(h[j]));
    }
    ((__nv_bfloat162*)hi)[2*i]   = __nv_bfloat162(h[0], h[1]);
    ((__nv_bfloat162*)hi)[2*i+1] = __nv_bfloat162(h[2], h[3]);
    ((__nv_bfloat162*)lo)[2*i]   = __nv_bfloat162(l[0], l[1]);
    ((__nv_bfloat162*)lo)[2*i+1] = __nv_bfloat162(l[2], l[3]);
}

// ---------------------------------------------------------------------------
// wmma bf16 GEMM: 128x128 CTA tile of out = A[M,1024] @ W[N,1024]^T + bias.
// Split precision: D = Ah*Wh + Ah*Wl + Al*Wh, fp32 accum (HMMA).
// 8 warps: warp tile 64x32 (wm in {0,1}, wn in {0..3}).
// mode 0: scatter [B,H,T,D] + RoPE.  mode 1: scatter.  mode 2: plain [M,N].
// ---------------------------------------------------------------------------
#define LDB 72      // bf16 smem leading dim (144B rows -> conflict-free ldmatrix)
#define LDE 132     // epilogue float leading dim
#define KC  64      // K elements staged per chunk
#define NCHUNK (C_/KC)
#define TILE_ELEMS (128*LDB)                 // per operand tile
#define STAGE_B (4*TILE_ELEMS*2)             // 73728 bytes

__device__ __forceinline__
void mma_gemm_body(const __nv_bfloat16* __restrict__ Ah, const __nv_bfloat16* __restrict__ Al,
                   const __nv_bfloat16* __restrict__ Wh, const __nv_bfloat16* __restrict__ Wl,
                   const float* __restrict__ bias, float* __restrict__ out,
                   const float2* __restrict__ cs, int mode)
{
    extern __shared__ char smem[];
    __nv_bfloat16* sT   = (__nv_bfloat16*)smem;          // 4 tiles contiguous
    float*         sEpi = (float*)smem;                  // reused post-compute
    float*         bias_s = (float*)(smem + STAGE_B);

    const int tid = threadIdx.x;
    const int wid = tid >> 5;
    const int wm = wid >> 2;       // 0..1 -> m offset wm*64
    const int wn = wid & 3;        // 0..3 -> n offset wn*32
    const int m0 = blockIdx.y << 7, n0 = blockIdx.x << 7;

    if (tid < 128) bias_s[tid] = bias[n0 + tid];

    const __nv_bfloat16* srcs[4] = {Ah, Al, Wh, Wl};
    const int row0[4] = {m0, m0, n0, n0};

    wmma::fragment<wmma::accumulator, 16, 16, 16, float> acc[4][2];
#pragma unroll
    for (int mt = 0; mt < 4; mt++)
#pragma unroll
        for (int nt = 0; nt < 2; nt++) wmma::fill_fragment(acc[mt][nt], 0.f);

    for (int kc = 0; kc < NCHUNK; kc++) {
        __syncthreads();
        // stage 4 tiles of [128 rows x 64 bf16]
#pragma unroll
        for (int it = 0; it < 16; it++) {
            const int job = it * 256 + tid;
            const int v = job & 7;           // 16B vec within row
            const int r = (job >> 3) & 127;  // row
            const int tile = job >> 10;      // 0..3
            const uint4 val = *(const uint4*)&srcs[tile][(size_t)(row0[tile] + r) * C_ + kc*KC + v*8];
            *(uint4*)(sT + tile*TILE_ELEMS + r*LDB + v*8) = val;
        }
        __syncthreads();

#pragma unroll
        for (int ks = 0; ks < 4; ks++) {
            wmma::fragment<wmma::matrix_b, 16, 16, 16, __nv_bfloat16, wmma::col_major> wh[2], wl[2];
#pragma unroll
            for (int nt = 0; nt < 2; nt++) {
                wmma::load_matrix_sync(wh[nt], sT + 2*TILE_ELEMS + (wn*32 + nt*16)*LDB + ks*16, LDB);
                wmma::load_matrix_sync(wl[nt], sT + 3*TILE_ELEMS + (wn*32 + nt*16)*LDB + ks*16, LDB);
            }
#pragma unroll
            for (int mt = 0; mt < 4; mt++) {
                wmma::fragment<wmma::matrix_a, 16, 16, 16, __nv_bfloat16, wmma::row_major> ah, al;
                wmma::load_matrix_sync(ah, sT + 0*TILE_ELEMS + (wm*64 + mt*16)*LDB + ks*16, LDB);
                wmma::load_matrix_sync(al, sT + 1*TILE_ELEMS + (wm*64 + mt*16)*LDB + ks*16, LDB);
#pragma unroll
                for (int nt = 0; nt < 2; nt++) {
                    wmma::mma_sync(acc[mt][nt], ah, wh[nt], acc[mt][nt]);
                    wmma::mma_sync(acc[mt][nt], ah, wl[nt], acc[mt][nt]);
                    wmma::mma_sync(acc[mt][nt], al, wh[nt], acc[mt][nt]);
                }
            }
        }
    }

    __syncthreads();  // all warps done reading staging before epilogue overwrite
#pragma unroll
    for (int mt = 0; mt < 4; mt++)
#pragma unroll
        for (int nt = 0; nt < 2; nt++)
            wmma::store_matrix_sync(sEpi + (wm*64 + mt*16)*LDE + wn*32 + nt*16,
                                    acc[mt][nt], LDE, wmma::mem_row_major);
    __syncthreads();

    // epilogue: tx handles 8 cols, ty handles 8 rows
    const int tx = tid & 15, ty = tid >> 4;
    const int n_base = n0 + 8*tx;
    const float4 b0 = *(const float4*)&bias_s[8*tx];
    const float4 b1 = *(const float4*)&bias_s[8*tx + 4];
    const float bb[8] = {b0.x, b0.y, b0.z, b0.w, b1.x, b1.y, b1.z, b1.w};

#pragma unroll
    for (int r = 0; r < 8; r++) {
        const int lrow = 8*ty + r;
        const int m = m0 + lrow;
        float o[8];
#pragma unroll
        for (int j = 0; j < 8; j++) o[j] = sEpi[lrow*LDE + 8*tx + j] + bb[j];

        if (mode == 0) {  // RoPE on (even,odd) pairs
            const int t = m & (T_-1);
#pragma unroll
            for (int p = 0; p < 4; p++) {
                const int i = ((n_base + 2*p) & 63) >> 1;
                const float2 csv = cs[t*32 + i];
                const float x1 = o[2*p], x2 = o[2*p+1];
                o[2*p]   = x1*csv.x - x2*csv.y;
                o[2*p+1] = x1*csv.y + x2*csv.x;
            }
        }

        float4 o0 = {o[0], o[1], o[2], o[3]};
        float4 o1 = {o[4], o[5], o[6], o[7]};
        if (mode <= 1) {  // scatter to [B,H,T,D]
            const int b = m >> 11, t = m & (T_-1);
            const int h = n_base >> 6, d = n_base & 63;
            float* dst = out + (((size_t)(b*H_ + h) * T_) + t) * D_ + d;
            *(float4*)dst = o0;
            *(float4*)(dst + 4) = o1;
        } else {
            float* dst = out + (size_t)m * C_ + n_base;
            *(float4*)dst = o0;
            *(float4*)(dst + 4) = o1;
        }
    }
}

__global__ __launch_bounds__(256, 2)
void qkv_mma(const __nv_bfloat16* __restrict__ xh, const __nv_bfloat16* __restrict__ xl,
             const float* __restrict__ bq, const float* __restrict__ bk,
             const float* __restrict__ bv,
             float* __restrict__ q, float* __restrict__ k, float* __restrict__ v,
             const float2* __restrict__ cs)
{
    const int z = blockIdx.z;
    const float* bias = (z == 0) ? bq : (z == 1) ? bk : bv;
    float* o          = (z == 0) ? q  : (z == 1) ? k  : v;
    mma_gemm_body(xh, xl, g_w_hi[z], g_w_lo[z], bias, o, cs, (z < 2) ? 0 : 1);
}

__global__ __launch_bounds__(256, 2)
void out_mma(const __nv_bfloat16* __restrict__ ah, const __nv_bfloat16* __restrict__ al,
             const float* __restrict__ bias, float* __restrict__ out)
{
    mma_gemm_body(ah, al, g_w_hi[3], g_w_lo[3], bias, out, nullptr, 2);
}

// ---------------------------------------------------------------------------
// Flash attention (proven round-5 version, unchanged)
// ---------------------------------------------------------------------------
__global__ __launch_bounds__(256)
void attn_kernel(const float* __restrict__ q, const float* __restrict__ k,
                 const float* __restrict__ v, float* __restrict__ out)
{
    extern __shared__ float fsm[];
    float (*Qt)[68] = (float(*)[68]) fsm;
    float (*Kt)[68] = (float(*)[68])(fsm + 64*68);
    float (*Vs)[64] = (float(*)[64])(fsm + 2*64*68);
    float (*Pt)[68] = (float(*)[68])(fsm + 2*64*68 + 64*64);

    const int tid = threadIdx.x;
    const int tx = tid & 15, ty = tid >> 4;
    const int bh = blockIdx.y;
    const int b = bh >> 4, h = bh & (H_-1);
    const int q0 = blockIdx.x << 6;

    const float* qb = q + (size_t)bh * T_ * D_;
    const float* kb = k + (size_t)bh * T_ * D_;
    const float* vb = v + (size_t)bh * T_ * D_;

#pragma unroll
    for (int ld = 0; ld < 4; ld++) {
        const int job = tid + (ld << 8);
        const int r = job >> 4, vv = job & 15;
        const float4 q4 = *(const float4*)&qb[(size_t)(q0 + r) * D_ + 4*vv];
        Qt[4*vv+0][r] = q4.x; Qt[4*vv+1][r] = q4.y;
        Qt[4*vv+2][r] = q4.z; Qt[4*vv+3][r] = q4.w;
    }

    float m_r[4], l_r[4];
    ull acc[2][4];
#pragma unroll
    for (int r = 0; r < 4; r++) { m_r[r] = -1e30f; l_r[r] = 0.f; }
#pragma unroll
    for (int g = 0; g < 2; g++)
#pragma unroll
        for (int c = 0; c < 4; c++) acc[g][c] = 0ull;

    const int ntiles = (q0 >> 6) + 1;
    for (int kt = 0; kt < ntiles; kt++) {
        const int k0 = kt << 6;
        __syncthreads();
#pragma unroll
        for (int ld = 0; ld < 4; ld++) {
            const int job = tid + (ld << 8);
            const int r = job >> 4, vv = job & 15;
            const float4 k4 = *(const float4*)&kb[(size_t)(k0 + r) * D_ + 4*vv];
            Kt[4*vv+0][r] = k4.x; Kt[4*vv+1][r] = k4.y;
            Kt[4*vv+2][r] = k4.z; Kt[4*vv+3][r] = k4.w;
            *(float4*)&Vs[r][4*vv] = *(const float4*)&vb[(size_t)(k0 + r) * D_ + 4*vv];
        }
        __syncthreads();

        ull sp[4][2];
#pragma unroll
        for (int r = 0; r < 4; r++) { sp[r][0] = 0ull; sp[r][1] = 0ull; }
#pragma unroll 4
        for (int d = 0; d < D_; d++) {
            const ulonglong2 kv = *(const ulonglong2*)&Kt[d][4*tx];
            const float4 qv = *(const float4*)&Qt[d][4*ty];
            const float qa[4] = {qv.x, qv.y, qv.z, qv.w};
            ull pq[4];
#pragma unroll
            for (int r = 0; r < 4; r++) PACK2(pq[r], qa[r], qa[r]);
#pragma unroll
            for (int r = 0; r < 4; r++) {
                FMA2(sp[r][0], pq[r], kv.x);
                FMA2(sp[r][1], pq[r], kv.y);
            }
        }

        float s[4][4], alpha[4];
#pragma unroll
        for (int r = 0; r < 4; r++) {
            UNPACK2(s[r][0], s[r][1], sp[r][0]);
            UNPACK2(s[r][2], s[r][3], sp[r][1]);
            const int qi = q0 + 4*ty + r;
            float rm = -1e30f;
#pragma unroll
            for (int c = 0; c < 4; c++) {
                const int kj = k0 + 4*tx + c;
                s[r][c] = (kj <= qi) ? s[r][c] * SCALE : -1e30f;
                rm = fmaxf(rm, s[r][c]);
            }
#pragma unroll
            for (int off = 8; off > 0; off >>= 1)
                rm = fmaxf(rm, __shfl_xor_sync(0xffffffffu, rm, off));
            const float mnew = fmaxf(m_r[r], rm);
            alpha[r] = __expf(m_r[r] - mnew);
            m_r[r] = mnew;
            float rs = 0.f;
#pragma unroll
            for (int c = 0; c < 4; c++) {
                const float p = __expf(s[r][c] - mnew);
                s[r][c] = p;
                rs += p;
            }
#pragma unroll
            for (int off = 8; off > 0; off >>= 1)
                rs += __shfl_xor_sync(0xffffffffu, rs, off);
            l_r[r] = l_r[r] * alpha[r] + rs;
        }

        ull pal0, pal1;
        PACK2(pal0, alpha[0], alpha[1]);
        PACK2(pal1, alpha[2], alpha[3]);
#pragma unroll
        for (int c = 0; c < 4; c++) {
            MUL2(acc[0][c], acc[0][c], pal0);
            MUL2(acc[1][c], acc[1][c], pal1);
        }

#pragma unroll
        for (int c = 0; c < 4; c++) {
            float4 col = {s[0][c], s[1][c], s[2][c], s[3][c]};
            *(float4*)&Pt[4*tx + c][4*ty] = col;
        }
        __syncthreads();

#pragma unroll 4
        for (int j = 0; j < 64; j++) {
            const ulonglong2 pv = *(const ulonglong2*)&Pt[j][4*ty];
            const float4 vv = *(const float4*)&Vs[j][4*tx];
            const float va[4] = {vv.x, vv.y, vv.z, vv.w};
            ull pw[4];
#pragma unroll
            for (int c = 0; c < 4; c++) PACK2(pw[c], va[c], va[c]);
#pragma unroll
            for (int c = 0; c < 4; c++) {
                FMA2(acc[0][c], pv.x, pw[c]);
                FMA2(acc[1][c], pv.y, pw[c]);
            }
        }
    }

    float oacc[4][4];
#pragma unroll
    for (int c = 0; c < 4; c++) {
        UNPACK2(oacc[0][c], oacc[1][c], acc[0][c]);
        UNPACK2(oacc[2][c], oacc[3][c], acc[1][c]);
    }
#pragma unroll
    for (int r = 0; r < 4; r++) {
        const int qi = q0 + 4*ty + r;
        const float inv_l = 1.f / l_r[r];
        float4 o = {oacc[r][0]*inv_l, oacc[r][1]*inv_l, oacc[r][2]*inv_l, oacc[r][3]*inv_l};
        *(float4*)&out[((size_t)(b*T_ + qi)) * C_ + h*D_ + 4*tx] = o;
    }
}

// ---------------------------------------------------------------------------
extern "C" void kernel_launch(void* const* d_in, const int* in_sizes, int n_in,
                              void* d_out, int out_size)
{
    const float* x  = (const float*)d_in[0];
    const float* Wq = (const float*)d_in[1];
    const float* bq = (const float*)d_in[2];
    const float* Wk = (const float*)d_in[3];
    const float* bk = (const float*)d_in[4];
    const float* Wv = (const float*)d_in[5];
    const float* bv = (const float*)d_in[6];
    const float* Wo = (const float*)d_in[7];
    const float* bo = (const float*)d_in[8];
    float* out = (float*)d_out;

    float *qp, *kp, *vp, *attp;
    float2* csp;
    __nv_bfloat16 *xh, *xl, *ah, *al, *wh, *wl;
    cudaGetSymbolAddress((void**)&qp,   g_q);
    cudaGetSymbolAddress((void**)&kp,   g_k);
    cudaGetSymbolAddress((void**)&vp,   g_v);
    cudaGetSymbolAddress((void**)&attp, g_att);
    cudaGetSymbolAddress((void**)&csp,  g_cs);
    cudaGetSymbolAddress((void**)&xh,   g_x_hi);
    cudaGetSymbolAddress((void**)&xl,   g_x_lo);
    cudaGetSymbolAddress((void**)&ah,   g_a_hi);
    cudaGetSymbolAddress((void**)&al,   g_a_lo);
    cudaGetSymbolAddress((void**)&wh,   g_w_hi);
    cudaGetSymbolAddress((void**)&wl,   g_w_lo);

    rope_table<<<(T_*32)/256, 256>>>(csp);

    // split conversions
    cvt_split<<<(M_*C_/4)/256, 256>>>(x,  xh, xl, M_*C_/4);
    cvt_split<<<(C_*C_/4)/256, 256>>>(Wq, wh + 0*(size_t)C_*C_, wl + 0*(size_t)C_*C_, C_*C_/4);
    cvt_split<<<(C_*C_/4)/256, 256>>>(Wk, wh + 1*(size_t)C_*C_, wl + 1*(size_t)C_*C_, C_*C_/4);
    cvt_split<<<(C_*C_/4)/256, 256>>>(Wv, wh + 2*(size_t)C_*C_, wl + 2*(size_t)C_*C_, C_*C_/4);
    cvt_split<<<(C_*C_/4)/256, 256>>>(Wo, wh + 3*(size_t)C_*C_, wl + 3*(size_t)C_*C_, C_*C_/4);

    const size_t gsmem = STAGE_B + 512;  // 74240 bytes
    cudaFuncSetAttribute(qkv_mma, cudaFuncAttributeMaxDynamicSharedMemorySize, (int)gsmem);
    cudaFuncSetAttribute(out_mma, cudaFuncAttributeMaxDynamicSharedMemorySize, (int)gsmem);

    qkv_mma<<<dim3(C_/128, M_/128, 3), 256, gsmem>>>(xh, xl, bq, bk, bv, qp, kp, vp, csp);

    const size_t asmem = (size_t)(64*68*3 + 64*64) * sizeof(float);
    cudaFuncSetAttribute(attn_kernel, cudaFuncAttributeMaxDynamicSharedMemorySize, (int)asmem);
    attn_kernel<<<dim3(T_/64, B_*H_), 256, asmem>>>(qp, kp, vp, attp);

    cvt_split<<<(M_*C_/4)/256, 256>>>(attp, ah, al, M_*C_/4);
    out_mma<<<dim3(C_/128, M_/128), 256, gsmem>>>(ah, al, bo, out);
}

// round 9
// speedup vs baseline: 1.8313x; 1.3599x over previous
#include <cuda_runtime.h>
#include <cuda_bf16.h>
#include <mma.h>
#include <math.h>
#include <stdint.h>

using namespace nvcuda;

#define B_ 2
#define T_ 2048
#define C_ 1024
#define H_ 16
#define D_ 64
#define M_ (B_*T_)
#define QSCALE 0.1803368801111437f  // (1/sqrt(64)) * log2(e)

typedef unsigned long long ull;
typedef __nv_bfloat16 bf16;

// ---------------------------------------------------------------------------
// Scratch (allocation-free contract: __device__ globals)
// ---------------------------------------------------------------------------
__device__ float2 g_cs[T_*32];     // RoPE cos/sin table
__device__ bf16 g_x_hi[M_*C_],  g_x_lo[M_*C_];
__device__ bf16 g_a_hi[M_*C_],  g_a_lo[M_*C_];
__device__ bf16 g_w_hi[4][C_*C_], g_w_lo[4][C_*C_];
__device__ bf16 g_qh[B_*H_*T_*D_], g_ql[B_*H_*T_*D_];
__device__ bf16 g_kh[B_*H_*T_*D_], g_kl[B_*H_*T_*D_];
__device__ bf16 g_vh[B_*H_*T_*D_], g_vl[B_*H_*T_*D_];

// ---------------------------------------------------------------------------
// FMA-pipe exp2: x <= 0, |rel err| ~2.4e-6. No MUFU.
// ---------------------------------------------------------------------------
__device__ __forceinline__ float exp2p(float x)
{
    x = fmaxf(x, -125.0f);
    const float r = rintf(x);
    const float f = x - r;               // [-0.5, 0.5]
    float p = 0.0013333558f;
    p = fmaf(p, f, 0.0096181291f);
    p = fmaf(p, f, 0.0555041087f);
    p = fmaf(p, f, 0.2402265070f);
    p = fmaf(p, f, 0.6931471806f);
    p = fmaf(p, f, 1.0f);
    const int e = (int)r;
    return p * __int_as_float((e + 127) << 23);
}

// ---------------------------------------------------------------------------
// RoPE table
// ---------------------------------------------------------------------------
__global__ void rope_table(float2* __restrict__ tab)
{
    const int idx = blockIdx.x * blockDim.x + threadIdx.x;
    if (idx >= T_*32) return;
    const int t = idx >> 5, i = idx & 31;
    const double inv = pow(10000.0, -(double)(2*i) / 64.0);
    const double ang = (double)t * inv;
    tab[idx] = make_float2((float)cos(ang), (float)sin(ang));
}

// ---------------------------------------------------------------------------
// fp32 -> (bf16 hi, bf16 lo) split
// ---------------------------------------------------------------------------
__global__ __launch_bounds__(256)
void cvt_split(const float* __restrict__ in, bf16* __restrict__ hi,
               bf16* __restrict__ lo, int n4)
{
    const int i = blockIdx.x * blockDim.x + threadIdx.x;
    if (i >= n4) return;
    const float4 v = ((const float4*)in)[i];
    float f[4] = {v.x, v.y, v.z, v.w};
    bf16 h[4], l[4];
#pragma unroll
    for (int j = 0; j < 4; j++) {
        h[j] = __float2bfloat16(f[j]);
        l[j] = __float2bfloat16(f[j] - __bfloat162float(h[j]));
    }
    ((__nv_bfloat162*)hi)[2*i]   = __nv_bfloat162(h[0], h[1]);
    ((__nv_bfloat162*)hi)[2*i+1] = __nv_bfloat162(h[2], h[3]);
    ((__nv_bfloat162*)lo)[2*i]   = __nv_bfloat162(l[0], l[1]);
    ((__nv_bfloat162*)lo)[2*i+1] = __nv_bfloat162(l[2], l[3]);
}

// ---------------------------------------------------------------------------
// wmma bf16 GEMM (split precision). z=0: q (rope+qscale, split->scatter),
// z=1: k (rope, split->scatter), z=2: v (split->scatter), z=3: plain fp32.
// ---------------------------------------------------------------------------
#define LDB 72
#define LDE 132
#define KC  64
#define NCHUNK (C_/KC)
#define TILE_ELEMS (128*LDB)
#define STAGE_B (4*TILE_ELEMS*2)

__device__ __forceinline__
void mma_gemm_body(const bf16* __restrict__ Ah, const bf16* __restrict__ Al,
                   const bf16* __restrict__ Wh, const bf16* __restrict__ Wl,
                   const float* __restrict__ bias,
                   bf16* __restrict__ oh, bf16* __restrict__ ol,
                   float* __restrict__ of,
                   const float2* __restrict__ cs, int z)
{
    extern __shared__ char smem[];
    bf16*  sT     = (bf16*)smem;
    float* sEpi   = (float*)smem;
    float* bias_s = (float*)(smem + STAGE_B);

    const int tid = threadIdx.x;
    const int wid = tid >> 5;
    const int wm = wid >> 2;
    const int wn = wid & 3;
    const int m0 = blockIdx.y << 7, n0 = blockIdx.x << 7;

    if (tid < 128) bias_s[tid] = bias[n0 + tid];

    const bf16* srcs[4] = {Ah, Al, Wh, Wl};
    const int row0[4] = {m0, m0, n0, n0};

    wmma::fragment<wmma::accumulator, 16, 16, 16, float> acc[4][2];
#pragma unroll
    for (int mt = 0; mt < 4; mt++)
#pragma unroll
        for (int nt = 0; nt < 2; nt++) wmma::fill_fragment(acc[mt][nt], 0.f);

    for (int kc = 0; kc < NCHUNK; kc++) {
        __syncthreads();
#pragma unroll
        for (int it = 0; it < 16; it++) {
            const int job = it * 256 + tid;
            const int v = job & 7;
            const int r = (job >> 3) & 127;
            const int tile = job >> 10;
            const uint4 val = *(const uint4*)&srcs[tile][(size_t)(row0[tile] + r) * C_ + kc*KC + v*8];
            *(uint4*)(sT + tile*TILE_ELEMS + r*LDB + v*8) = val;
        }
        __syncthreads();

#pragma unroll
        for (int ks = 0; ks < 4; ks++) {
            wmma::fragment<wmma::matrix_b, 16, 16, 16, bf16, wmma::col_major> wh[2], wl[2];
#pragma unroll
            for (int nt = 0; nt < 2; nt++) {
                wmma::load_matrix_sync(wh[nt], sT + 2*TILE_ELEMS + (wn*32 + nt*16)*LDB + ks*16, LDB);
                wmma::load_matrix_sync(wl[nt], sT + 3*TILE_ELEMS + (wn*32 + nt*16)*LDB + ks*16, LDB);
            }
#pragma unroll
            for (int mt = 0; mt < 4; mt++) {
                wmma::fragment<wmma::matrix_a, 16, 16, 16, bf16, wmma::row_major> ah, al;
                wmma::load_matrix_sync(ah, sT + 0*TILE_ELEMS + (wm*64 + mt*16)*LDB + ks*16, LDB);
                wmma::load_matrix_sync(al, sT + 1*TILE_ELEMS + (wm*64 + mt*16)*LDB + ks*16, LDB);
#pragma unroll
                for (int nt = 0; nt < 2; nt++) {
                    wmma::mma_sync(acc[mt][nt], ah, wh[nt], acc[mt][nt]);
                    wmma::mma_sync(acc[mt][nt], ah, wl[nt], acc[mt][nt]);
                    wmma::mma_sync(acc[mt][nt], al, wh[nt], acc[mt][nt]);
                }
            }
        }
    }

    __syncthreads();
#pragma unroll
    for (int mt = 0; mt < 4; mt++)
#pragma unroll
        for (int nt = 0; nt < 2; nt++)
            wmma::store_matrix_sync(sEpi + (wm*64 + mt*16)*LDE + wn*32 + nt*16,
                                    acc[mt][nt], LDE, wmma::mem_row_major);
    __syncthreads();

    const int tx = tid & 15, ty = tid >> 4;
    const int n_base = n0 + 8*tx;
    const float4 b0 = *(const float4*)&bias_s[8*tx];
    const float4 b1 = *(const float4*)&bias_s[8*tx + 4];
    const float bb[8] = {b0.x, b0.y, b0.z, b0.w, b1.x, b1.y, b1.z, b1.w};

#pragma unroll
    for (int r = 0; r < 8; r++) {
        const int lrow = 8*ty + r;
        const int m = m0 + lrow;
        float o[8];
#pragma unroll
        for (int j = 0; j < 8; j++) o[j] = sEpi[lrow*LDE + 8*tx + j] + bb[j];

        if (z < 2) {  // RoPE
            const int t = m & (T_-1);
#pragma unroll
            for (int p = 0; p < 4; p++) {
                const int i = ((n_base + 2*p) & 63) >> 1;
                const float2 csv = cs[t*32 + i];
                const float x1 = o[2*p], x2 = o[2*p+1];
                o[2*p]   = x1*csv.x - x2*csv.y;
                o[2*p+1] = x1*csv.y + x2*csv.x;
            }
        }
        if (z == 0) {
#pragma unroll
            for (int j = 0; j < 8; j++) o[j] *= QSCALE;
        }

        if (z <= 2) {  // split -> scatter [B,H,T,D]
            bf16 h8[8], l8[8];
#pragma unroll
            for (int j = 0; j < 8; j++) {
                h8[j] = __float2bfloat16(o[j]);
                l8[j] = __float2bfloat16(o[j] - __bfloat162float(h8[j]));
            }
            const int b = m >> 11, t = m & (T_-1);
            const int h = n_base >> 6, d = n_base & 63;
            const size_t doff = (((size_t)(b*H_ + h) * T_) + t) * D_ + d;
            *(uint4*)(oh + doff) = *(uint4*)h8;
            *(uint4*)(ol + doff) = *(uint4*)l8;
        } else {
            float* dst = of + (size_t)m * C_ + n_base;
            *(float4*)dst = make_float4(o[0], o[1], o[2], o[3]);
            *(float4*)(dst + 4) = make_float4(o[4], o[5], o[6], o[7]);
        }
    }
}

__global__ __launch_bounds__(256, 2)
void qkv_mma(const bf16* __restrict__ xh, const bf16* __restrict__ xl,
             const float* __restrict__ bq, const float* __restrict__ bk,
             const float* __restrict__ bv, const float2* __restrict__ cs)
{
    const int z = blockIdx.z;
    const float* bias = (z == 0) ? bq : (z == 1) ? bk : bv;
    bf16* oh = (z == 0) ? g_qh : (z == 1) ? g_kh : g_vh;
    bf16* ol = (z == 0) ? g_ql : (z == 1) ? g_kl : g_vl;
    mma_gemm_body(xh, xl, g_w_hi[z], g_w_lo[z], bias, oh, ol, nullptr, cs, z);
}

__global__ __launch_bounds__(256, 2)
void out_mma(const bf16* __restrict__ ah, const bf16* __restrict__ al,
             const float* __restrict__ bias, float* __restrict__ out)
{
    mma_gemm_body(ah, al, g_w_hi[3], g_w_lo[3], bias, nullptr, nullptr, out, nullptr, 3);
}

// ---------------------------------------------------------------------------
// wmma flash attention, causal. 128 queries x 128 keys per tile, 256 threads.
// Split bf16 3-term for QK and PV, fp32 accum, poly exp on FMA pipe.
// Scores arrive in log2 domain (QSCALE folded into Q).
// ---------------------------------------------------------------------------
#define AQ_LD 72
#define AS_LD 132
#define AP_LD 136
#define AO_LD 68
// smem byte offsets
#define OFF_QH 0
#define OFF_QL 18432
#define OFF_KP 36864          // Kh/Kl (36864B) aliased with Ph/Pl (69632B)
#define OFF_KL (OFF_KP + 18432)
#define OFF_PL (OFF_KP + 34816)
#define OFF_V  106496
#define OFF_VL (OFF_V + 18432)
#define OFF_S  143360          // scores fp32 (67584B), reused for O-tile
#define OFF_AL 210944          // alpha_s [128] float
#define OFF_LS 211456          // l_s [128] float
#define ATTN_SMEM 211968

__global__ __launch_bounds__(256)
void attn_wmma(const bf16* __restrict__ qh, const bf16* __restrict__ ql,
               const bf16* __restrict__ kh, const bf16* __restrict__ kl,
               const bf16* __restrict__ vh, const bf16* __restrict__ vl,
               bf16* __restrict__ ah_out, bf16* __restrict__ al_out)
{
    extern __shared__ char smem[];
    bf16*  Qh = (bf16*)(smem + OFF_QH);
    bf16*  Ql = (bf16*)(smem + OFF_QL);
    bf16*  Kh = (bf16*)(smem + OFF_KP);
    bf16*  Kl = (bf16*)(smem + OFF_KL);
    bf16*  Ph = (bf16*)(smem + OFF_KP);
    bf16*  Pl = (bf16*)(smem + OFF_PL);
    bf16*  Vh = (bf16*)(smem + OFF_V);
    bf16*  Vl = (bf16*)(smem + OFF_VL);
    float* S  = (float*)(smem + OFF_S);
    float* alpha_s = (float*)(smem + OFF_AL);
    float* l_s     = (float*)(smem + OFF_LS);

    const int tid = threadIdx.x;
    const int wid = tid >> 5;
    const int bh = blockIdx.y;
    const int b = bh >> 4, h = bh & (H_-1);
    const int qt = gridDim.x - 1 - blockIdx.x;   // heavy tiles first
    const int q0 = qt << 7;

    const size_t hb = (size_t)bh * T_ * D_;
    const bf16* qhb = qh + hb; const bf16* qlb = ql + hb;
    const bf16* khb = kh + hb; const bf16* klb = kl + hb;
    const bf16* vhb = vh + hb; const bf16* vlb = vl + hb;

    // load Q tiles (hi/lo): 2048 vec jobs
#pragma unroll
    for (int it = 0; it < 8; it++) {
        const int job = it * 256 + tid;
        const int v = job & 7;
        const int r = (job >> 3) & 127;
        const int tile = job >> 10;
        const uint4 val = *(const uint4*)((tile ? qlb : qhb) + (size_t)(q0 + r) * D_ + v*8);
        *(uint4*)((tile ? Ql : Qh) + r*AQ_LD + v*8) = val;
    }

    // per-thread output tile: rows 8*ty+r, cols 4*tx+c
    const int tx = tid & 15, ty = tid >> 4;
    float o_acc[8][4];
#pragma unroll
    for (int r = 0; r < 8; r++)
#pragma unroll
        for (int c = 0; c < 4; c++) o_acc[r][c] = 0.f;

    // softmax state: row = tid>>1, half = tid&1 (pair shares a row)
    const int srow = tid >> 1, shalf = tid & 1;
    const int qi = q0 + srow;
    float m2 = -1e30f, lsum = 0.f;

    const int wm = wid >> 2, wn = wid & 3;     // QK warp tile 64x32
    const int wm2 = wid >> 1, wn2 = wid & 1;   // PV warp tile 32x32

    for (int kt = 0; kt <= qt; kt++) {
        const int k0 = kt << 7;
        __syncthreads();
        // load Kh,Kl,Vh,Vl
#pragma unroll
        for (int it = 0; it < 16; it++) {
            const int job = it * 256 + tid;
            const int v = job & 7;
            const int r = (job >> 3) & 127;
            const int tile = job >> 10;
            const bf16* src = (tile == 0) ? khb : (tile == 1) ? klb : (tile == 2) ? vhb : vlb;
            bf16* dst = (tile == 0) ? Kh : (tile == 1) ? Kl : (tile == 2) ? Vh : Vl;
            const uint4 val = *(const uint4*)(src + (size_t)(k0 + r) * D_ + v*8);
            *(uint4*)(dst + r*AQ_LD + v*8) = val;
        }
        __syncthreads();

        // ---- QK^T (3-term) ----
        {
            wmma::fragment<wmma::accumulator, 16, 16, 16, float> acc[4][2];
#pragma unroll
            for (int mt = 0; mt < 4; mt++)
#pragma unroll
                for (int nt = 0; nt < 2; nt++) wmma::fill_fragment(acc[mt][nt], 0.f);
#pragma unroll
            for (int ks = 0; ks < 4; ks++) {
                wmma::fragment<wmma::matrix_b, 16, 16, 16, bf16, wmma::col_major> fkh[2], fkl[2];
#pragma unroll
                for (int nt = 0; nt < 2; nt++) {
                    wmma::load_matrix_sync(fkh[nt], Kh + (wn*32 + nt*16)*AQ_LD + ks*16, AQ_LD);
                    wmma::load_matrix_sync(fkl[nt], Kl + (wn*32 + nt*16)*AQ_LD + ks*16, AQ_LD);
                }
#pragma unroll
                for (int mt = 0; mt < 4; mt++) {
                    wmma::fragment<wmma::matrix_a, 16, 16, 16, bf16, wmma::row_major> fqh, fql;
                    wmma::load_matrix_sync(fqh, Qh + (wm*64 + mt*16)*AQ_LD + ks*16, AQ_LD);
                    wmma::load_matrix_sync(fql, Ql + (wm*64 + mt*16)*AQ_LD + ks*16, AQ_LD);
#pragma unroll
                    for (int nt = 0; nt < 2; nt++) {
                        wmma::mma_sync(acc[mt][nt], fqh, fkh[nt], acc[mt][nt]);
                        wmma::mma_sync(acc[mt][nt], fqh, fkl[nt], acc[mt][nt]);
                        wmma::mma_sync(acc[mt][nt], fql, fkh[nt], acc[mt][nt]);
                    }
                }
            }
#pragma unroll
            for (int mt = 0; mt < 4; mt++)
#pragma unroll
                for (int nt = 0; nt < 2; nt++)
                    wmma::store_matrix_sync(S + (wm*64 + mt*16)*AS_LD + wn*32 + nt*16,
                                            acc[mt][nt], AS_LD, wmma::mem_row_major);
        }
        __syncthreads();

        // ---- online softmax (log2 domain), write P hi/lo ----
        {
            float* Srow = S + srow*AS_LD + shalf*64;
            float rmax = -1e30f;
            if (kt == qt) {  // diagonal: mask and write back
#pragma unroll
                for (int c4 = 0; c4 < 64; c4 += 4) {
                    float4 s4 = *(float4*)&Srow[c4];
                    const int kj = k0 + shalf*64 + c4;
                    if (kj + 0 > qi) s4.x = -1e30f;
                    if (kj + 1 > qi) s4.y = -1e30f;
                    if (kj + 2 > qi) s4.z = -1e30f;
                    if (kj + 3 > qi) s4.w = -1e30f;
                    *(float4*)&Srow[c4] = s4;
                    rmax = fmaxf(rmax, fmaxf(fmaxf(s4.x, s4.y), fmaxf(s4.z, s4.w)));
                }
            } else {
#pragma unroll
                for (int c4 = 0; c4 < 64; c4 += 4) {
                    const float4 s4 = *(float4*)&Srow[c4];
                    rmax = fmaxf(rmax, fmaxf(fmaxf(s4.x, s4.y), fmaxf(s4.z, s4.w)));
                }
            }
            rmax = fmaxf(rmax, __shfl_xor_sync(0xffffffffu, rmax, 1));
            const float mnew = fmaxf(m2, rmax);
            const float alpha = exp2p(m2 - mnew);
            m2 = mnew;

            float rs = 0.f;
            bf16* PhRow = Ph + srow*AP_LD + shalf*64;
            bf16* PlRow = Pl + srow*AP_LD + shalf*64;
#pragma unroll
            for (int c4 = 0; c4 < 64; c4 += 4) {
                const float4 s4 = *(float4*)&Srow[c4];
                float p[4] = {exp2p(s4.x - mnew), exp2p(s4.y - mnew),
                              exp2p(s4.z - mnew), exp2p(s4.w - mnew)};
                rs += (p[0] + p[1]) + (p[2] + p[3]);
                bf16 h4[4], l4[4];
#pragma unroll
                for (int j = 0; j < 4; j++) {
                    h4[j] = __float2bfloat16(p[j]);
                    l4[j] = __float2bfloat16(p[j] - __bfloat162float(h4[j]));
                }
                *(uint2*)&PhRow[c4] = *(uint2*)h4;
                *(uint2*)&PlRow[c4] = *(uint2*)l4;
            }
            rs += __shfl_xor_sync(0xffffffffu, rs, 1);
            lsum = lsum * alpha + rs;
            if (shalf == 0) alpha_s[srow] = alpha;
        }
        __syncthreads();

        // ---- PV (3-term), O-tile into S buffer ----
        {
            wmma::fragment<wmma::accumulator, 16, 16, 16, float> accO[2][2];
#pragma unroll
            for (int mt = 0; mt < 2; mt++)
#pragma unroll
                for (int nt = 0; nt < 2; nt++) wmma::fill_fragment(accO[mt][nt], 0.f);
#pragma unroll
            for (int ks = 0; ks < 8; ks++) {
                wmma::fragment<wmma::matrix_b, 16, 16, 16, bf16, wmma::row_major> fvh[2], fvl[2];
#pragma unroll
                for (int nt = 0; nt < 2; nt++) {
                    wmma::load_matrix_sync(fvh[nt], Vh + (ks*16)*AQ_LD + wn2*32 + nt*16, AQ_LD);
                    wmma::load_matrix_sync(fvl[nt], Vl + (ks*16)*AQ_LD + wn2*32 + nt*16, AQ_LD);
                }
#pragma unroll
                for (int mt = 0; mt < 2; mt++) {
                    wmma::fragment<wmma::matrix_a, 16, 16, 16, bf16, wmma::row_major> fph, fpl;
                    wmma::load_matrix_sync(fph, Ph + (wm2*32 + mt*16)*AP_LD + ks*16, AP_LD);
                    wmma::load_matrix_sync(fpl, Pl + (wm2*32 + mt*16)*AP_LD + ks*16, AP_LD);
#pragma unroll
                    for (int nt = 0; nt < 2; nt++) {
                        wmma::mma_sync(accO[mt][nt], fph, fvh[nt], accO[mt][nt]);
                        wmma::mma_sync(accO[mt][nt], fph, fvl[nt], accO[mt][nt]);
                        wmma::mma_sync(accO[mt][nt], fpl, fvh[nt], accO[mt][nt]);
                    }
                }
            }
#pragma unroll
            for (int mt = 0; mt < 2; mt++)
#pragma unroll
                for (int nt = 0; nt < 2; nt++)
                    wmma::store_matrix_sync(S + (wm2*32 + mt*16)*AO_LD + wn2*32 + nt*16,
                                            accO[mt][nt], AO_LD, wmma::mem_row_major);
        }
        __syncthreads();

        // ---- O update: o = o*alpha + pv ----
#pragma unroll
        for (int r = 0; r < 8; r++) {
            const int row = 8*ty + r;
            const float a = alpha_s[row];
            const float4 pv = *(float4*)&S[row*AO_LD + 4*tx];
            o_acc[r][0] = fmaf(o_acc[r][0], a, pv.x);
            o_acc[r][1] = fmaf(o_acc[r][1], a, pv.y);
            o_acc[r][2] = fmaf(o_acc[r][2], a, pv.z);
            o_acc[r][3] = fmaf(o_acc[r][3], a, pv.w);
        }
    }

    if (shalf == 0) l_s[srow] = lsum;
    __syncthreads();

    // epilogue: normalize, split, write [M, C] bf16 hi/lo
#pragma unroll
    for (int r = 0; r < 8; r++) {
        const int row = 8*ty + r;
        const float il = 1.f / l_s[row];
        bf16 h4[4], l4[4];
#pragma unroll
        for (int c = 0; c < 4; c++) {
            const float val = o_acc[r][c] * il;
            h4[c] = __float2bfloat16(val);
            l4[c] = __float2bfloat16(val - __bfloat162float(h4[c]));
        }
        const size_t doff = ((size_t)(b*T_ + q0 + row)) * C_ + h*D_ + 4*tx;
        *(uint2*)(ah_out + doff) = *(uint2*)h4;
        *(uint2*)(al_out + doff) = *(uint2*)l4;
    }
}

// ---------------------------------------------------------------------------
extern "C" void kernel_launch(void* const* d_in, const int* in_sizes, int n_in,
                              void* d_out, int out_size)
{
    const float* x  = (const float*)d_in[0];
    const float* Wq = (const float*)d_in[1];
    const float* bq = (const float*)d_in[2];
    const float* Wk = (const float*)d_in[3];
    const float* bk = (const float*)d_in[4];
    const float* Wv = (const float*)d_in[5];
    const float* bv = (const float*)d_in[6];
    const float* Wo = (const float*)d_in[7];
    const float* bo = (const float*)d_in[8];
    float* out = (float*)d_out;

    float2* csp;
    bf16 *xh, *xl, *ah, *al, *wh, *wl;
    bf16 *qhp, *qlp, *khp, *klp, *vhp, *vlp;
    cudaGetSymbolAddress((void**)&csp,  g_cs);
    cudaGetSymbolAddress((void**)&xh,   g_x_hi);
    cudaGetSymbolAddress((void**)&xl,   g_x_lo);
    cudaGetSymbolAddress((void**)&ah,   g_a_hi);
    cudaGetSymbolAddress((void**)&al,   g_a_lo);
    cudaGetSymbolAddress((void**)&wh,   g_w_hi);
    cudaGetSymbolAddress((void**)&wl,   g_w_lo);
    cudaGetSymbolAddress((void**)&qhp,  g_qh);
    cudaGetSymbolAddress((void**)&qlp,  g_ql);
    cudaGetSymbolAddress((void**)&khp,  g_kh);
    cudaGetSymbolAddress((void**)&klp,  g_kl);
    cudaGetSymbolAddress((void**)&vhp,  g_vh);
    cudaGetSymbolAddress((void**)&vlp,  g_vl);

    rope_table<<<(T_*32)/256, 256>>>(csp);

    cvt_split<<<(M_*C_/4)/256, 256>>>(x,  xh, xl, M_*C_/4);
    cvt_split<<<(C_*C_/4)/256, 256>>>(Wq, wh + 0*(size_t)C_*C_, wl + 0*(size_t)C_*C_, C_*C_/4);
    cvt_split<<<(C_*C_/4)/256, 256>>>(Wk, wh + 1*(size_t)C_*C_, wl + 1*(size_t)C_*C_, C_*C_/4);
    cvt_split<<<(C_*C_/4)/256, 256>>>(Wv, wh + 2*(size_t)C_*C_, wl + 2*(size_t)C_*C_, C_*C_/4);
    cvt_split<<<(C_*C_/4)/256, 256>>>(Wo, wh + 3*(size_t)C_*C_, wl + 3*(size_t)C_*C_, C_*C_/4);

    const size_t gsmem = STAGE_B + 512;
    cudaFuncSetAttribute(qkv_mma, cudaFuncAttributeMaxDynamicSharedMemorySize, (int)gsmem);
    cudaFuncSetAttribute(out_mma, cudaFuncAttributeMaxDynamicSharedMemorySize, (int)gsmem);
    cudaFuncSetAttribute(attn_wmma, cudaFuncAttributeMaxDynamicSharedMemorySize, ATTN_SMEM);

    qkv_mma<<<dim3(C_/128, M_/128, 3), 256, gsmem>>>(xh, xl, bq, bk, bv, csp);

    attn_wmma<<<dim3(T_/128, B_*H_), 256, ATTN_SMEM>>>(qhp, qlp, khp, klp, vhp, vlp, ah, al);

    out_mma<<<dim3(C_/128, M_/128), 256, gsmem>>>(ah, al, bo, out);
}

// round 10
// speedup vs baseline: 1.9620x; 1.0714x over previous
#include <cuda_runtime.h>
#include <cuda_bf16.h>
#include <mma.h>
#include <math.h>
#include <stdint.h>

using namespace nvcuda;

#define B_ 2
#define T_ 2048
#define C_ 1024
#define H_ 16
#define D_ 64
#define M_ (B_*T_)
#define QSCALE 0.1803368801111437f  // (1/sqrt(64)) * log2(e)

typedef __nv_bfloat16 bf16;

// ---------------------------------------------------------------------------
// Scratch (allocation-free contract: __device__ globals)
// ---------------------------------------------------------------------------
__device__ float2 g_cs[T_*32];     // RoPE cos/sin table
__device__ bf16 g_x_hi[M_*C_],  g_x_lo[M_*C_];
__device__ bf16 g_a_hi[M_*C_],  g_a_lo[M_*C_];
__device__ bf16 g_w_hi[4][C_*C_], g_w_lo[4][C_*C_];
__device__ bf16 g_qh[B_*H_*T_*D_], g_ql[B_*H_*T_*D_];
__device__ bf16 g_kh[B_*H_*T_*D_], g_kl[B_*H_*T_*D_];
__device__ bf16 g_vh[B_*H_*T_*D_], g_vl[B_*H_*T_*D_];

// ---------------------------------------------------------------------------
// cp.async helpers
// ---------------------------------------------------------------------------
#define CP_ASYNC16(dst, src) \
    asm volatile("cp.async.cg.shared.global [%0], [%1], 16;" :: "r"(dst), "l"(src) : "memory")
#define CP_COMMIT() asm volatile("cp.async.commit_group;" ::: "memory")
#define CP_WAIT0()  asm volatile("cp.async.wait_group 0;" ::: "memory")
#define CP_WAIT1()  asm volatile("cp.async.wait_group 1;" ::: "memory")

__device__ __forceinline__ uint32_t smem_u32(const void* p) {
    uint32_t a;
    asm("{ .reg .u64 t; cvta.to.shared.u64 t, %1; cvt.u32.u64 %0, t; }" : "=r"(a) : "l"(p));
    return a;
}

// ---------------------------------------------------------------------------
// FMA-pipe exp2: x <= 0, |rel err| ~2.4e-6. No MUFU.
// ---------------------------------------------------------------------------
__device__ __forceinline__ float exp2p(float x)
{
    x = fmaxf(x, -125.0f);
    const float r = rintf(x);
    const float f = x - r;
    float p = 0.0013333558f;
    p = fmaf(p, f, 0.0096181291f);
    p = fmaf(p, f, 0.0555041087f);
    p = fmaf(p, f, 0.2402265070f);
    p = fmaf(p, f, 0.6931471806f);
    p = fmaf(p, f, 1.0f);
    const int e = (int)r;
    return p * __int_as_float((e + 127) << 23);
}

// ---------------------------------------------------------------------------
// RoPE table
// ---------------------------------------------------------------------------
__global__ void rope_table(float2* __restrict__ tab)
{
    const int idx = blockIdx.x * blockDim.x + threadIdx.x;
    if (idx >= T_*32) return;
    const int t = idx >> 5, i = idx & 31;
    const double inv = pow(10000.0, -(double)(2*i) / 64.0);
    const double ang = (double)t * inv;
    tab[idx] = make_float2((float)cos(ang), (float)sin(ang));
}

// ---------------------------------------------------------------------------
// fp32 -> (bf16 hi, bf16 lo) split
// ---------------------------------------------------------------------------
__global__ __launch_bounds__(256)
void cvt_split(const float* __restrict__ in, bf16* __restrict__ hi,
               bf16* __restrict__ lo, int n4)
{
    const int i = blockIdx.x * blockDim.x + threadIdx.x;
    if (i >= n4) return;
    const float4 v = ((const float4*)in)[i];
    float f[4] = {v.x, v.y, v.z, v.w};
    bf16 h[4], l[4];
#pragma unroll
    for (int j = 0; j < 4; j++) {
        h[j] = __float2bfloat16(f[j]);
        l[j] = __float2bfloat16(f[j] - __bfloat162float(h[j]));
    }
    ((__nv_bfloat162*)hi)[2*i]   = __nv_bfloat162(h[0], h[1]);
    ((__nv_bfloat162*)hi)[2*i+1] = __nv_bfloat162(h[2], h[3]);
    ((__nv_bfloat162*)lo)[2*i]   = __nv_bfloat162(l[0], l[1]);
    ((__nv_bfloat162*)lo)[2*i+1] = __nv_bfloat162(l[2], l[3]);
}

// ---------------------------------------------------------------------------
// Pipelined wmma bf16 GEMM (cp.async double buffer).
// 128x128 CTA tile, KC=32 chunks, 2 stages. Split precision 3-term.
// z=0: q (rope+qscale, split->scatter), z=1: k (rope, split),
// z=2: v (split), z=3: plain fp32 out.
// ---------------------------------------------------------------------------
#define SLDB 40                        // bf16 leading dim (80B rows)
#define TILE_BG (128*SLDB*2)           // 10240 B per operand tile
#define STAGE_BG (4*TILE_BG)           // 40960 B per stage
#define LDE 132
#define NCH2 (C_/32)                   // 32 chunks

__device__ __forceinline__
void mma_gemm_body(const bf16* __restrict__ Ah, const bf16* __restrict__ Al,
                   const bf16* __restrict__ Wh, const bf16* __restrict__ Wl,
                   const float* __restrict__ bias,
                   bf16* __restrict__ oh, bf16* __restrict__ ol,
                   float* __restrict__ of,
                   const float2* __restrict__ cs, int z)
{
    extern __shared__ char smem[];
    const uint32_t sbase = smem_u32(smem);
    float* sEpi   = (float*)smem;
    float* bias_s = (float*)(smem + 2*STAGE_BG);

    const int tid = threadIdx.x;
    const int wid = tid >> 5;
    const int wm = wid >> 2;
    const int wn = wid & 3;
    const int m0 = blockIdx.y << 7, n0 = blockIdx.x << 7;

    if (tid < 128) bias_s[tid] = bias[n0 + tid];

    const bf16* srcs[4] = {Ah, Al, Wh, Wl};
    const int row0[4] = {m0, m0, n0, n0};

    // decode load job once: 2048 16B-vecs/chunk, 8 per thread
    int jtile[8], jr[8], jv[8];
#pragma unroll
    for (int it = 0; it < 8; it++) {
        const int job = it * 256 + tid;
        jtile[it] = job >> 9;
        const int idx = job & 511;
        jr[it] = idx >> 2;
        jv[it] = idx & 3;
    }

    // prologue: stage 0 <- chunk 0
#pragma unroll
    for (int it = 0; it < 8; it++) {
        const bf16* g = srcs[jtile[it]] + (size_t)(row0[jtile[it]] + jr[it]) * C_ + jv[it]*8;
        CP_ASYNC16(sbase + jtile[it]*TILE_BG + jr[it]*80 + jv[it]*16, g);
    }
    CP_COMMIT();

    wmma::fragment<wmma::accumulator, 16, 16, 16, float> acc[4][2];
#pragma unroll
    for (int mt = 0; mt < 4; mt++)
#pragma unroll
        for (int nt = 0; nt < 2; nt++) wmma::fill_fragment(acc[mt][nt], 0.f);

    for (int kc = 0; kc < NCH2; kc++) {
        const int s = kc & 1;
        if (kc + 1 < NCH2) {
            const uint32_t db = sbase + (s^1)*STAGE_BG;
            const int koff = (kc+1)*32;
#pragma unroll
            for (int it = 0; it < 8; it++) {
                const bf16* g = srcs[jtile[it]] + (size_t)(row0[jtile[it]] + jr[it]) * C_ + koff + jv[it]*8;
                CP_ASYNC16(db + jtile[it]*TILE_BG + jr[it]*80 + jv[it]*16, g);
            }
            CP_COMMIT();
            CP_WAIT1();
        } else {
            CP_WAIT0();
        }
        __syncthreads();

        bf16* sT = (bf16*)(smem + s*STAGE_BG);
#pragma unroll
        for (int ks = 0; ks < 2; ks++) {
            wmma::fragment<wmma::matrix_b, 16, 16, 16, bf16, wmma::col_major> fwh[2], fwl[2];
#pragma unroll
            for (int nt = 0; nt < 2; nt++) {
                wmma::load_matrix_sync(fwh[nt], sT + 2*(128*SLDB) + (wn*32 + nt*16)*SLDB + ks*16, SLDB);
                wmma::load_matrix_sync(fwl[nt], sT + 3*(128*SLDB) + (wn*32 + nt*16)*SLDB + ks*16, SLDB);
            }
#pragma unroll
            for (int mt = 0; mt < 4; mt++) {
                wmma::fragment<wmma::matrix_a, 16, 16, 16, bf16, wmma::row_major> fah, fal;
                wmma::load_matrix_sync(fah, sT + 0*(128*SLDB) + (wm*64 + mt*16)*SLDB + ks*16, SLDB);
                wmma::load_matrix_sync(fal, sT + 1*(128*SLDB) + (wm*64 + mt*16)*SLDB + ks*16, SLDB);
#pragma unroll
                for (int nt = 0; nt < 2; nt++) {
                    wmma::mma_sync(acc[mt][nt], fah, fwh[nt], acc[mt][nt]);
                    wmma::mma_sync(acc[mt][nt], fah, fwl[nt], acc[mt][nt]);
                    wmma::mma_sync(acc[mt][nt], fal, fwh[nt], acc[mt][nt]);
                }
            }
        }
        __syncthreads();
    }

    // epilogue via smem (aliases staging)
#pragma unroll
    for (int mt = 0; mt < 4; mt++)
#pragma unroll
        for (int nt = 0; nt < 2; nt++)
            wmma::store_matrix_sync(sEpi + (wm*64 + mt*16)*LDE + wn*32 + nt*16,
                                    acc[mt][nt], LDE, wmma::mem_row_major);
    __syncthreads();

    const int tx = tid & 15, ty = tid >> 4;
    const int n_base = n0 + 8*tx;
    const float4 b0 = *(const float4*)&bias_s[8*tx];
    const float4 b1 = *(const float4*)&bias_s[8*tx + 4];
    const float bb[8] = {b0.x, b0.y, b0.z, b0.w, b1.x, b1.y, b1.z, b1.w};

#pragma unroll
    for (int r = 0; r < 8; r++) {
        const int lrow = 8*ty + r;
        const int m = m0 + lrow;
        float o[8];
#pragma unroll
        for (int j = 0; j < 8; j++) o[j] = sEpi[lrow*LDE + 8*tx + j] + bb[j];

        if (z < 2) {  // RoPE
            const int t = m & (T_-1);
#pragma unroll
            for (int p = 0; p < 4; p++) {
                const int i = ((n_base + 2*p) & 63) >> 1;
                const float2 csv = cs[t*32 + i];
                const float x1 = o[2*p], x2 = o[2*p+1];
                o[2*p]   = x1*csv.x - x2*csv.y;
                o[2*p+1] = x1*csv.y + x2*csv.x;
            }
        }
        if (z == 0) {
#pragma unroll
            for (int j = 0; j < 8; j++) o[j] *= QSCALE;
        }

        if (z <= 2) {  // split -> scatter [B,H,T,D]
            bf16 h8[8], l8[8];
#pragma unroll
            for (int j = 0; j < 8; j++) {
                h8[j] = __float2bfloat16(o[j]);
                l8[j] = __float2bfloat16(o[j] - __bfloat162float(h8[j]));
            }
            const int b = m >> 11, t = m & (T_-1);
            const int h = n_base >> 6, d = n_base & 63;
            const size_t doff = (((size_t)(b*H_ + h) * T_) + t) * D_ + d;
            *(uint4*)(oh + doff) = *(uint4*)h8;
            *(uint4*)(ol + doff) = *(uint4*)l8;
        } else {
            float* dst = of + (size_t)m * C_ + n_base;
            *(float4*)dst = make_float4(o[0], o[1], o[2], o[3]);
            *(float4*)(dst + 4) = make_float4(o[4], o[5], o[6], o[7]);
        }
    }
}

__global__ __launch_bounds__(256, 2)
void qkv_mma(const bf16* __restrict__ xh, const bf16* __restrict__ xl,
             const float* __restrict__ bq, const float* __restrict__ bk,
             const float* __restrict__ bv, const float2* __restrict__ cs)
{
    const int z = blockIdx.z;
    const float* bias = (z == 0) ? bq : (z == 1) ? bk : bv;
    bf16* oh = (z == 0) ? g_qh : (z == 1) ? g_kh : g_vh;
    bf16* ol = (z == 0) ? g_ql : (z == 1) ? g_kl : g_vl;
    mma_gemm_body(xh, xl, g_w_hi[z], g_w_lo[z], bias, oh, ol, nullptr, cs, z);
}

__global__ __launch_bounds__(256, 2)
void out_mma(const bf16* __restrict__ ah, const bf16* __restrict__ al,
             const float* __restrict__ bias, float* __restrict__ out)
{
    mma_gemm_body(ah, al, g_w_hi[3], g_w_lo[3], bias, nullptr, nullptr, out, nullptr, 3);
}

// ---------------------------------------------------------------------------
// wmma flash attention, causal. 128x128 tiles, 256 threads.
// Split bf16 3-term for QK and PV, fp32 accum, poly exp on FMA pipe.
// ---------------------------------------------------------------------------
#define AQ_LD 72
#define AS_LD 132
#define AP_LD 136
#define AO_LD 68
#define OFF_QH 0
#define OFF_QL 18432
#define OFF_KP 36864
#define OFF_KL (OFF_KP + 18432)
#define OFF_PL (OFF_KP + 34816)
#define OFF_V  106496
#define OFF_VL (OFF_V + 18432)
#define OFF_S  143360
#define OFF_AL 210944
#define OFF_LS 211456
#define ATTN_SMEM 211968

__global__ __launch_bounds__(256)
void attn_wmma(const bf16* __restrict__ qh, const bf16* __restrict__ ql,
               const bf16* __restrict__ kh, const bf16* __restrict__ kl,
               const bf16* __restrict__ vh, const bf16* __restrict__ vl,
               bf16* __restrict__ ah_out, bf16* __restrict__ al_out)
{
    extern __shared__ char smem[];
    bf16*  Qh = (bf16*)(smem + OFF_QH);
    bf16*  Ql = (bf16*)(smem + OFF_QL);
    bf16*  Kh = (bf16*)(smem + OFF_KP);
    bf16*  Kl = (bf16*)(smem + OFF_KL);
    bf16*  Ph = (bf16*)(smem + OFF_KP);
    bf16*  Pl = (bf16*)(smem + OFF_PL);
    bf16*  Vh = (bf16*)(smem + OFF_V);
    bf16*  Vl = (bf16*)(smem + OFF_VL);
    float* S  = (float*)(smem + OFF_S);
    float* alpha_s = (float*)(smem + OFF_AL);
    float* l_s     = (float*)(smem + OFF_LS);

    const int tid = threadIdx.x;
    const int wid = tid >> 5;
    const int bh = blockIdx.y;
    const int b = bh >> 4, h = bh & (H_-1);
    const int qt = gridDim.x - 1 - blockIdx.x;
    const int q0 = qt << 7;

    const size_t hb = (size_t)bh * T_ * D_;
    const bf16* qhb = qh + hb; const bf16* qlb = ql + hb;
    const bf16* khb = kh + hb; const bf16* klb = kl + hb;
    const bf16* vhb = vh + hb; const bf16* vlb = vl + hb;

#pragma unroll
    for (int it = 0; it < 8; it++) {
        const int job = it * 256 + tid;
        const int v = job & 7;
        const int r = (job >> 3) & 127;
        const int tile = job >> 10;
        const uint4 val = *(const uint4*)((tile ? qlb : qhb) + (size_t)(q0 + r) * D_ + v*8);
        *(uint4*)((tile ? Ql : Qh) + r*AQ_LD + v*8) = val;
    }

    const int tx = tid & 15, ty = tid >> 4;
    float o_acc[8][4];
#pragma unroll
    for (int r = 0; r < 8; r++)
#pragma unroll
        for (int c = 0; c < 4; c++) o_acc[r][c] = 0.f;

    const int srow = tid >> 1, shalf = tid & 1;
    const int qi = q0 + srow;
    float m2 = -1e30f, lsum = 0.f;

    const int wm = wid >> 2, wn = wid & 3;
    const int wm2 = wid >> 1, wn2 = wid & 1;

    for (int kt = 0; kt <= qt; kt++) {
        const int k0 = kt << 7;
        __syncthreads();
#pragma unroll
        for (int it = 0; it < 16; it++) {
            const int job = it * 256 + tid;
            const int v = job & 7;
            const int r = (job >> 3) & 127;
            const int tile = job >> 10;
            const bf16* src = (tile == 0) ? khb : (tile == 1) ? klb : (tile == 2) ? vhb : vlb;
            bf16* dst = (tile == 0) ? Kh : (tile == 1) ? Kl : (tile == 2) ? Vh : Vl;
            const uint4 val = *(const uint4*)(src + (size_t)(k0 + r) * D_ + v*8);
            *(uint4*)(dst + r*AQ_LD + v*8) = val;
        }
        __syncthreads();

        // ---- QK^T (3-term) ----
        {
            wmma::fragment<wmma::accumulator, 16, 16, 16, float> acc[4][2];
#pragma unroll
            for (int mt = 0; mt < 4; mt++)
#pragma unroll
                for (int nt = 0; nt < 2; nt++) wmma::fill_fragment(acc[mt][nt], 0.f);
#pragma unroll
            for (int ks = 0; ks < 4; ks++) {
                wmma::fragment<wmma::matrix_b, 16, 16, 16, bf16, wmma::col_major> fkh[2], fkl[2];
#pragma unroll
                for (int nt = 0; nt < 2; nt++) {
                    wmma::load_matrix_sync(fkh[nt], Kh + (wn*32 + nt*16)*AQ_LD + ks*16, AQ_LD);
                    wmma::load_matrix_sync(fkl[nt], Kl + (wn*32 + nt*16)*AQ_LD + ks*16, AQ_LD);
                }
#pragma unroll
                for (int mt = 0; mt < 4; mt++) {
                    wmma::fragment<wmma::matrix_a, 16, 16, 16, bf16, wmma::row_major> fqh, fql;
                    wmma::load_matrix_sync(fqh, Qh + (wm*64 + mt*16)*AQ_LD + ks*16, AQ_LD);
                    wmma::load_matrix_sync(fql, Ql + (wm*64 + mt*16)*AQ_LD + ks*16, AQ_LD);
#pragma unroll
                    for (int nt = 0; nt < 2; nt++) {
                        wmma::mma_sync(acc[mt][nt], fqh, fkh[nt], acc[mt][nt]);
                        wmma::mma_sync(acc[mt][nt], fqh, fkl[nt], acc[mt][nt]);
                        wmma::mma_sync(acc[mt][nt], fql, fkh[nt], acc[mt][nt]);
                    }
                }
            }
#pragma unroll
            for (int mt = 0; mt < 4; mt++)
#pragma unroll
                for (int nt = 0; nt < 2; nt++)
                    wmma::store_matrix_sync(S + (wm*64 + mt*16)*AS_LD + wn*32 + nt*16,
                                            acc[mt][nt], AS_LD, wmma::mem_row_major);
        }
        __syncthreads();

        // ---- online softmax (log2 domain) ----
        {
            float* Srow = S + srow*AS_LD + shalf*64;
            float rmax = -1e30f;
            if (kt == qt) {
#pragma unroll
                for (int c4 = 0; c4 < 64; c4 += 4) {
                    float4 s4 = *(float4*)&Srow[c4];
                    const int kj = k0 + shalf*64 + c4;
                    if (kj + 0 > qi) s4.x = -1e30f;
                    if (kj + 1 > qi) s4.y = -1e30f;
                    if (kj + 2 > qi) s4.z = -1e30f;
                    if (kj + 3 > qi) s4.w = -1e30f;
                    *(float4*)&Srow[c4] = s4;
                    rmax = fmaxf(rmax, fmaxf(fmaxf(s4.x, s4.y), fmaxf(s4.z, s4.w)));
                }
            } else {
#pragma unroll
                for (int c4 = 0; c4 < 64; c4 += 4) {
                    const float4 s4 = *(float4*)&Srow[c4];
                    rmax = fmaxf(rmax, fmaxf(fmaxf(s4.x, s4.y), fmaxf(s4.z, s4.w)));
                }
            }
            rmax = fmaxf(rmax, __shfl_xor_sync(0xffffffffu, rmax, 1));
            const float mnew = fmaxf(m2, rmax);
            const float alpha = exp2p(m2 - mnew);
            m2 = mnew;

            float rs = 0.f;
            bf16* PhRow = Ph + srow*AP_LD + shalf*64;
            bf16* PlRow = Pl + srow*AP_LD + shalf*64;
#pragma unroll
            for (int c4 = 0; c4 < 64; c4 += 4) {
                const float4 s4 = *(float4*)&Srow[c4];
                float p[4] = {exp2p(s4.x - mnew), exp2p(s4.y - mnew),
                              exp2p(s4.z - mnew), exp2p(s4.w - mnew)};
                rs += (p[0] + p[1]) + (p[2] + p[3]);
                bf16 h4[4], l4[4];
#pragma unroll
                for (int j = 0; j < 4; j++) {
                    h4[j] = __float2bfloat16(p[j]);
                    l4[j] = __float2bfloat16(p[j] - __bfloat162float(h4[j]));
                }
                *(uint2*)&PhRow[c4] = *(uint2*)h4;
                *(uint2*)&PlRow[c4] = *(uint2*)l4;
            }
            rs += __shfl_xor_sync(0xffffffffu, rs, 1);
            lsum = lsum * alpha + rs;
            if (shalf == 0) alpha_s[srow] = alpha;
        }
        __syncthreads();

        // ---- PV (3-term) ----
        {
            wmma::fragment<wmma::accumulator, 16, 16, 16, float> accO[2][2];
#pragma unroll
            for (int mt = 0; mt < 2; mt++)
#pragma unroll
                for (int nt = 0; nt < 2; nt++) wmma::fill_fragment(accO[mt][nt], 0.f);
#pragma unroll
            for (int ks = 0; ks < 8; ks++) {
                wmma::fragment<wmma::matrix_b, 16, 16, 16, bf16, wmma::row_major> fvh[2], fvl[2];
#pragma unroll
                for (int nt = 0; nt < 2; nt++) {
                    wmma::load_matrix_sync(fvh[nt], Vh + (ks*16)*AQ_LD + wn2*32 + nt*16, AQ_LD);
                    wmma::load_matrix_sync(fvl[nt], Vl + (ks*16)*AQ_LD + wn2*32 + nt*16, AQ_LD);
                }
#pragma unroll
                for (int mt = 0; mt < 2; mt++) {
                    wmma::fragment<wmma::matrix_a, 16, 16, 16, bf16, wmma::row_major> fph, fpl;
                    wmma::load_matrix_sync(fph, Ph + (wm2*32 + mt*16)*AP_LD + ks*16, AP_LD);
                    wmma::load_matrix_sync(fpl, Pl + (wm2*32 + mt*16)*AP_LD + ks*16, AP_LD);
#pragma unroll
                    for (int nt = 0; nt < 2; nt++) {
                        wmma::mma_sync(accO[mt][nt], fph, fvh[nt], accO[mt][nt]);
                        wmma::mma_sync(accO[mt][nt], fph, fvl[nt], accO[mt][nt]);
                        wmma::mma_sync(accO[mt][nt], fpl, fvh[nt], accO[mt][nt]);
                    }
                }
            }
#pragma unroll
            for (int mt = 0; mt < 2; mt++)
#pragma unroll
                for (int nt = 0; nt < 2; nt++)
                    wmma::store_matrix_sync(S + (wm2*32 + mt*16)*AO_LD + wn2*32 + nt*16,
                                            accO[mt][nt], AO_LD, wmma::mem_row_major);
        }
        __syncthreads();

#pragma unroll
        for (int r = 0; r < 8; r++) {
            const int row = 8*ty + r;
            const float a = alpha_s[row];
            const float4 pv = *(float4*)&S[row*AO_LD + 4*tx];
            o_acc[r][0] = fmaf(o_acc[r][0], a, pv.x);
            o_acc[r][1] = fmaf(o_acc[r][1], a, pv.y);
            o_acc[r][2] = fmaf(o_acc[r][2], a, pv.z);
            o_acc[r][3] = fmaf(o_acc[r][3], a, pv.w);
        }
    }

    if (shalf == 0) l_s[srow] = lsum;
    __syncthreads();

#pragma unroll
    for (int r = 0; r < 8; r++) {
        const int row = 8*ty + r;
        const float il = 1.f / l_s[row];
        bf16 h4[4], l4[4];
#pragma unroll
        for (int c = 0; c < 4; c++) {
            const float val = o_acc[r][c] * il;
            h4[c] = __float2bfloat16(val);
            l4[c] = __float2bfloat16(val - __bfloat162float(h4[c]));
        }
        const size_t doff = ((size_t)(b*T_ + q0 + row)) * C_ + h*D_ + 4*tx;
        *(uint2*)(ah_out + doff) = *(uint2*)h4;
        *(uint2*)(al_out + doff) = *(uint2*)l4;
    }
}

// ---------------------------------------------------------------------------
extern "C" void kernel_launch(void* const* d_in, const int* in_sizes, int n_in,
                              void* d_out, int out_size)
{
    const float* x  = (const float*)d_in[0];
    const float* Wq = (const float*)d_in[1];
    const float* bq = (const float*)d_in[2];
    const float* Wk = (const float*)d_in[3];
    const float* bk = (const float*)d_in[4];
    const float* Wv = (const float*)d_in[5];
    const float* bv = (const float*)d_in[6];
    const float* Wo = (const float*)d_in[7];
    const float* bo = (const float*)d_in[8];
    float* out = (float*)d_out;

    float2* csp;
    bf16 *xh, *xl, *ah, *al, *wh, *wl;
    bf16 *qhp, *qlp, *khp, *klp, *vhp, *vlp;
    cudaGetSymbolAddress((void**)&csp,  g_cs);
    cudaGetSymbolAddress((void**)&xh,   g_x_hi);
    cudaGetSymbolAddress((void**)&xl,   g_x_lo);
    cudaGetSymbolAddress((void**)&ah,   g_a_hi);
    cudaGetSymbolAddress((void**)&al,   g_a_lo);
    cudaGetSymbolAddress((void**)&wh,   g_w_hi);
    cudaGetSymbolAddress((void**)&wl,   g_w_lo);
    cudaGetSymbolAddress((void**)&qhp,  g_qh);
    cudaGetSymbolAddress((void**)&qlp,  g_ql);
    cudaGetSymbolAddress((void**)&khp,  g_kh);
    cudaGetSymbolAddress((void**)&klp,  g_kl);
    cudaGetSymbolAddress((void**)&vhp,  g_vh);
    cudaGetSymbolAddress((void**)&vlp,  g_vl);

    rope_table<<<(T_*32)/256, 256>>>(csp);

    cvt_split<<<(M_*C_/4)/256, 256>>>(x,  xh, xl, M_*C_/4);
    cvt_split<<<(C_*C_/4)/256, 256>>>(Wq, wh + 0*(size_t)C_*C_, wl + 0*(size_t)C_*C_, C_*C_/4);
    cvt_split<<<(C_*C_/4)/256, 256>>>(Wk, wh + 1*(size_t)C_*C_, wl + 1*(size_t)C_*C_, C_*C_/4);
    cvt_split<<<(C_*C_/4)/256, 256>>>(Wv, wh + 2*(size_t)C_*C_, wl + 2*(size_t)C_*C_, C_*C_/4);
    cvt_split<<<(C_*C_/4)/256, 256>>>(Wo, wh + 3*(size_t)C_*C_, wl + 3*(size_t)C_*C_, C_*C_/4);

    const size_t gsmem = 2*STAGE_BG + 512;  // 82432 B
    cudaFuncSetAttribute(qkv_mma, cudaFuncAttributeMaxDynamicSharedMemorySize, (int)gsmem);
    cudaFuncSetAttribute(out_mma, cudaFuncAttributeMaxDynamicSharedMemorySize, (int)gsmem);
    cudaFuncSetAttribute(attn_wmma, cudaFuncAttributeMaxDynamicSharedMemorySize, ATTN_SMEM);

    qkv_mma<<<dim3(C_/128, M_/128, 3), 256, gsmem>>>(xh, xl, bq, bk, bv, csp);

    attn_wmma<<<dim3(T_/128, B_*H_), 256, ATTN_SMEM>>>(qhp, qlp, khp, klp, vhp, vlp, ah, al);

    out_mma<<<dim3(C_/128, M_/128), 256, gsmem>>>(ah, al, bo, out);
}

// round 11
// speedup vs baseline: 2.0093x; 1.0241x over previous
#include <cuda_runtime.h>
#include <cuda_bf16.h>
#include <mma.h>
#include <math.h>
#include <stdint.h>

using namespace nvcuda;

#define B_ 2
#define T_ 2048
#define C_ 1024
#define H_ 16
#define D_ 64
#define M_ (B_*T_)
#define QSCALE 0.1803368801111437f  // (1/sqrt(64)) * log2(e)

typedef __nv_bfloat16 bf16;

// ---------------------------------------------------------------------------
// Scratch (allocation-free contract: __device__ globals)
// ---------------------------------------------------------------------------
__device__ float2 g_cs[T_*32];     // RoPE cos/sin table
__device__ bf16 g_x_hi[M_*C_],  g_x_lo[M_*C_];
__device__ bf16 g_a_hi[M_*C_],  g_a_lo[M_*C_];
__device__ bf16 g_w_hi[4][C_*C_], g_w_lo[4][C_*C_];
__device__ bf16 g_qh[B_*H_*T_*D_], g_ql[B_*H_*T_*D_];
__device__ bf16 g_kh[B_*H_*T_*D_], g_kl[B_*H_*T_*D_];
__device__ bf16 g_vh[B_*H_*T_*D_], g_vl[B_*H_*T_*D_];

// ---------------------------------------------------------------------------
// cp.async helpers
// ---------------------------------------------------------------------------
#define CP_ASYNC16(dst, src) \
    asm volatile("cp.async.cg.shared.global [%0], [%1], 16;" :: "r"(dst), "l"(src) : "memory")
#define CP_COMMIT() asm volatile("cp.async.commit_group;" ::: "memory")
#define CP_WAIT0()  asm volatile("cp.async.wait_group 0;" ::: "memory")
#define CP_WAIT1()  asm volatile("cp.async.wait_group 1;" ::: "memory")

__device__ __forceinline__ uint32_t smem_u32(const void* p) {
    uint32_t a;
    asm("{ .reg .u64 t; cvta.to.shared.u64 t, %1; cvt.u32.u64 %0, t; }" : "=r"(a) : "l"(p));
    return a;
}

// ---------------------------------------------------------------------------
// FMA-pipe exp2: x <= 0, |rel err| ~2.4e-6. No MUFU.
// ---------------------------------------------------------------------------
__device__ __forceinline__ float exp2p(float x)
{
    x = fmaxf(x, -125.0f);
    const float r = rintf(x);
    const float f = x - r;
    float p = 0.0013333558f;
    p = fmaf(p, f, 0.0096181291f);
    p = fmaf(p, f, 0.0555041087f);
    p = fmaf(p, f, 0.2402265070f);
    p = fmaf(p, f, 0.6931471806f);
    p = fmaf(p, f, 1.0f);
    const int e = (int)r;
    return p * __int_as_float((e + 127) << 23);
}

// ---------------------------------------------------------------------------
// RoPE table
// ---------------------------------------------------------------------------
__global__ void rope_table(float2* __restrict__ tab)
{
    const int idx = blockIdx.x * blockDim.x + threadIdx.x;
    if (idx >= T_*32) return;
    const int t = idx >> 5, i = idx & 31;
    const double inv = pow(10000.0, -(double)(2*i) / 64.0);
    const double ang = (double)t * inv;
    tab[idx] = make_float2((float)cos(ang), (float)sin(ang));
}

// ---------------------------------------------------------------------------
// fp32 -> (bf16 hi, bf16 lo) split
// ---------------------------------------------------------------------------
__global__ __launch_bounds__(256)
void cvt_split(const float* __restrict__ in, bf16* __restrict__ hi,
               bf16* __restrict__ lo, int n4)
{
    const int i = blockIdx.x * blockDim.x + threadIdx.x;
    if (i >= n4) return;
    const float4 v = ((const float4*)in)[i];
    float f[4] = {v.x, v.y, v.z, v.w};
    bf16 h[4], l[4];
#pragma unroll
    for (int j = 0; j < 4; j++) {
        h[j] = __float2bfloat16(f[j]);
        l[j] = __float2bfloat16(f[j] - __bfloat162float(h[j]));
    }
    ((__nv_bfloat162*)hi)[2*i]   = __nv_bfloat162(h[0], h[1]);
    ((__nv_bfloat162*)hi)[2*i+1] = __nv_bfloat162(h[2], h[3]);
    ((__nv_bfloat162*)lo)[2*i]   = __nv_bfloat162(l[0], l[1]);
    ((__nv_bfloat162*)lo)[2*i+1] = __nv_bfloat162(l[2], l[3]);
}

// ---------------------------------------------------------------------------
// Pipelined wmma bf16 GEMM (cp.async double buffer) — unchanged from R10.
// ---------------------------------------------------------------------------
#define SLDB 40
#define TILE_BG (128*SLDB*2)
#define STAGE_BG (4*TILE_BG)
#define LDE 132
#define NCH2 (C_/32)

__device__ __forceinline__
void mma_gemm_body(const bf16* __restrict__ Ah, const bf16* __restrict__ Al,
                   const bf16* __restrict__ Wh, const bf16* __restrict__ Wl,
                   const float* __restrict__ bias,
                   bf16* __restrict__ oh, bf16* __restrict__ ol,
                   float* __restrict__ of,
                   const float2* __restrict__ cs, int z)
{
    extern __shared__ char smem[];
    const uint32_t sbase = smem_u32(smem);
    float* sEpi   = (float*)smem;
    float* bias_s = (float*)(smem + 2*STAGE_BG);

    const int tid = threadIdx.x;
    const int wid = tid >> 5;
    const int wm = wid >> 2;
    const int wn = wid & 3;
    const int m0 = blockIdx.y << 7, n0 = blockIdx.x << 7;

    if (tid < 128) bias_s[tid] = bias[n0 + tid];

    const bf16* srcs[4] = {Ah, Al, Wh, Wl};
    const int row0[4] = {m0, m0, n0, n0};

    int jtile[8], jr[8], jv[8];
#pragma unroll
    for (int it = 0; it < 8; it++) {
        const int job = it * 256 + tid;
        jtile[it] = job >> 9;
        const int idx = job & 511;
        jr[it] = idx >> 2;
        jv[it] = idx & 3;
    }

#pragma unroll
    for (int it = 0; it < 8; it++) {
        const bf16* g = srcs[jtile[it]] + (size_t)(row0[jtile[it]] + jr[it]) * C_ + jv[it]*8;
        CP_ASYNC16(sbase + jtile[it]*TILE_BG + jr[it]*80 + jv[it]*16, g);
    }
    CP_COMMIT();

    wmma::fragment<wmma::accumulator, 16, 16, 16, float> acc[4][2];
#pragma unroll
    for (int mt = 0; mt < 4; mt++)
#pragma unroll
        for (int nt = 0; nt < 2; nt++) wmma::fill_fragment(acc[mt][nt], 0.f);

    for (int kc = 0; kc < NCH2; kc++) {
        const int s = kc & 1;
        if (kc + 1 < NCH2) {
            const uint32_t db = sbase + (s^1)*STAGE_BG;
            const int koff = (kc+1)*32;
#pragma unroll
            for (int it = 0; it < 8; it++) {
                const bf16* g = srcs[jtile[it]] + (size_t)(row0[jtile[it]] + jr[it]) * C_ + koff + jv[it]*8;
                CP_ASYNC16(db + jtile[it]*TILE_BG + jr[it]*80 + jv[it]*16, g);
            }
            CP_COMMIT();
            CP_WAIT1();
        } else {
            CP_WAIT0();
        }
        __syncthreads();

        bf16* sT = (bf16*)(smem + s*STAGE_BG);
#pragma unroll
        for (int ks = 0; ks < 2; ks++) {
            wmma::fragment<wmma::matrix_b, 16, 16, 16, bf16, wmma::col_major> fwh[2], fwl[2];
#pragma unroll
            for (int nt = 0; nt < 2; nt++) {
                wmma::load_matrix_sync(fwh[nt], sT + 2*(128*SLDB) + (wn*32 + nt*16)*SLDB + ks*16, SLDB);
                wmma::load_matrix_sync(fwl[nt], sT + 3*(128*SLDB) + (wn*32 + nt*16)*SLDB + ks*16, SLDB);
            }
#pragma unroll
            for (int mt = 0; mt < 4; mt++) {
                wmma::fragment<wmma::matrix_a, 16, 16, 16, bf16, wmma::row_major> fah, fal;
                wmma::load_matrix_sync(fah, sT + 0*(128*SLDB) + (wm*64 + mt*16)*SLDB + ks*16, SLDB);
                wmma::load_matrix_sync(fal, sT + 1*(128*SLDB) + (wm*64 + mt*16)*SLDB + ks*16, SLDB);
#pragma unroll
                for (int nt = 0; nt < 2; nt++) {
                    wmma::mma_sync(acc[mt][nt], fah, fwh[nt], acc[mt][nt]);
                    wmma::mma_sync(acc[mt][nt], fah, fwl[nt], acc[mt][nt]);
                    wmma::mma_sync(acc[mt][nt], fal, fwh[nt], acc[mt][nt]);
                }
            }
        }
        __syncthreads();
    }

#pragma unroll
    for (int mt = 0; mt < 4; mt++)
#pragma unroll
        for (int nt = 0; nt < 2; nt++)
            wmma::store_matrix_sync(sEpi + (wm*64 + mt*16)*LDE + wn*32 + nt*16,
                                    acc[mt][nt], LDE, wmma::mem_row_major);
    __syncthreads();

    const int tx = tid & 15, ty = tid >> 4;
    const int n_base = n0 + 8*tx;
    const float4 b0 = *(const float4*)&bias_s[8*tx];
    const float4 b1 = *(const float4*)&bias_s[8*tx + 4];
    const float bb[8] = {b0.x, b0.y, b0.z, b0.w, b1.x, b1.y, b1.z, b1.w};

#pragma unroll
    for (int r = 0; r < 8; r++) {
        const int lrow = 8*ty + r;
        const int m = m0 + lrow;
        float o[8];
#pragma unroll
        for (int j = 0; j < 8; j++) o[j] = sEpi[lrow*LDE + 8*tx + j] + bb[j];

        if (z < 2) {
            const int t = m & (T_-1);
#pragma unroll
            for (int p = 0; p < 4; p++) {
                const int i = ((n_base + 2*p) & 63) >> 1;
                const float2 csv = cs[t*32 + i];
                const float x1 = o[2*p], x2 = o[2*p+1];
                o[2*p]   = x1*csv.x - x2*csv.y;
                o[2*p+1] = x1*csv.y + x2*csv.x;
            }
        }
        if (z == 0) {
#pragma unroll
            for (int j = 0; j < 8; j++) o[j] *= QSCALE;
        }

        if (z <= 2) {
            bf16 h8[8], l8[8];
#pragma unroll
            for (int j = 0; j < 8; j++) {
                h8[j] = __float2bfloat16(o[j]);
                l8[j] = __float2bfloat16(o[j] - __bfloat162float(h8[j]));
            }
            const int b = m >> 11, t = m & (T_-1);
            const int h = n_base >> 6, d = n_base & 63;
            const size_t doff = (((size_t)(b*H_ + h) * T_) + t) * D_ + d;
            *(uint4*)(oh + doff) = *(uint4*)h8;
            *(uint4*)(ol + doff) = *(uint4*)l8;
        } else {
            float* dst = of + (size_t)m * C_ + n_base;
            *(float4*)dst = make_float4(o[0], o[1], o[2], o[3]);
            *(float4*)(dst + 4) = make_float4(o[4], o[5], o[6], o[7]);
        }
    }
}

__global__ __launch_bounds__(256, 2)
void qkv_mma(const bf16* __restrict__ xh, const bf16* __restrict__ xl,
             const float* __restrict__ bq, const float* __restrict__ bk,
             const float* __restrict__ bv, const float2* __restrict__ cs)
{
    const int z = blockIdx.z;
    const float* bias = (z == 0) ? bq : (z == 1) ? bk : bv;
    bf16* oh = (z == 0) ? g_qh : (z == 1) ? g_kh : g_vh;
    bf16* ol = (z == 0) ? g_ql : (z == 1) ? g_kl : g_vl;
    mma_gemm_body(xh, xl, g_w_hi[z], g_w_lo[z], bias, oh, ol, nullptr, cs, z);
}

__global__ __launch_bounds__(256, 2)
void out_mma(const bf16* __restrict__ ah, const bf16* __restrict__ al,
             const float* __restrict__ bias, float* __restrict__ out)
{
    mma_gemm_body(ah, al, g_w_hi[3], g_w_lo[3], bias, nullptr, nullptr, out, nullptr, 3);
}

// ---------------------------------------------------------------------------
// wmma flash attention, causal. 64q x 64k tiles, 128 threads (4 warps),
// 71.5 KB smem -> 3 CTAs/SM for cross-CTA phase overlap.
// ---------------------------------------------------------------------------
#define AQ_LD 72     // bf16 tiles leading dim (144B rows)
#define AP_LD 72
#define AS_LD 68     // fp32 S / O staging leading dim
// byte offsets
#define AOFF_QH 0
#define AOFF_QL 9216
#define AOFF_K  18432          // Kh/Kl; aliased with Ph/Pl
#define AOFF_KL (AOFF_K + 9216)
#define AOFF_V  36864
#define AOFF_VL (AOFF_V + 9216)
#define AOFF_S  55296          // 64*68*4 = 17408
#define AOFF_AL 72704
#define AOFF_LS 72960
#define ATTN_SMEM 73216

__global__ __launch_bounds__(128, 3)
void attn_wmma(const bf16* __restrict__ qh, const bf16* __restrict__ ql,
               const bf16* __restrict__ kh, const bf16* __restrict__ kl,
               const bf16* __restrict__ vh, const bf16* __restrict__ vl,
               bf16* __restrict__ ah_out, bf16* __restrict__ al_out)
{
    extern __shared__ char smem[];
    bf16*  Qh = (bf16*)(smem + AOFF_QH);
    bf16*  Ql = (bf16*)(smem + AOFF_QL);
    bf16*  Kh = (bf16*)(smem + AOFF_K);
    bf16*  Kl = (bf16*)(smem + AOFF_KL);
    bf16*  Ph = (bf16*)(smem + AOFF_K);    // alias (P written after QK reads K)
    bf16*  Pl = (bf16*)(smem + AOFF_KL);
    bf16*  Vh = (bf16*)(smem + AOFF_V);
    bf16*  Vl = (bf16*)(smem + AOFF_VL);
    float* S  = (float*)(smem + AOFF_S);
    float* alpha_s = (float*)(smem + AOFF_AL);
    float* l_s     = (float*)(smem + AOFF_LS);

    const int tid = threadIdx.x;
    const int wid = tid >> 5;
    const int bh = blockIdx.y;
    const int b = bh >> 4, h = bh & (H_-1);
    const int qt = gridDim.x - 1 - blockIdx.x;   // heavy tiles first
    const int q0 = qt << 6;

    const size_t hb = (size_t)bh * T_ * D_;
    const bf16* qhb = qh + hb; const bf16* qlb = ql + hb;
    const bf16* khb = kh + hb; const bf16* klb = kl + hb;
    const bf16* vhb = vh + hb; const bf16* vlb = vl + hb;

    // load Q tiles (hi/lo): 1024 16B jobs, 8 per thread
#pragma unroll
    for (int it = 0; it < 8; it++) {
        const int job = it * 128 + tid;
        const int v = job & 7;
        const int r = (job >> 3) & 63;
        const int tile = job >> 9;
        const uint4 val = *(const uint4*)((tile ? qlb : qhb) + (size_t)(q0 + r) * D_ + v*8);
        *(uint4*)((tile ? Ql : Qh) + r*AQ_LD + v*8) = val;
    }

    const int tx = tid & 15, ty = tid >> 4;
    float o_acc[8][4];
#pragma unroll
    for (int r = 0; r < 8; r++)
#pragma unroll
        for (int c = 0; c < 4; c++) o_acc[r][c] = 0.f;

    // softmax state: row = tid>>1 (0..63), half = tid&1 (32 cols each)
    const int srow = tid >> 1, shalf = tid & 1;
    const int qi = q0 + srow;
    float m2 = -1e30f, lsum = 0.f;

    // warp tiling: 2x2 warps, 32x32 tiles
    const int wm = wid >> 1, wn = wid & 1;

    for (int kt = 0; kt <= qt; kt++) {
        const int k0 = kt << 6;
        __syncthreads();
        // load Kh,Kl,Vh,Vl: 2048 16B jobs, 16 per thread
#pragma unroll
        for (int it = 0; it < 16; it++) {
            const int job = it * 128 + tid;
            const int v = job & 7;
            const int r = (job >> 3) & 63;
            const int tile = job >> 9;
            const bf16* src = (tile == 0) ? khb : (tile == 1) ? klb : (tile == 2) ? vhb : vlb;
            bf16* dst = (tile == 0) ? Kh : (tile == 1) ? Kl : (tile == 2) ? Vh : Vl;
            const uint4 val = *(const uint4*)(src + (size_t)(k0 + r) * D_ + v*8);
            *(uint4*)(dst + r*AQ_LD + v*8) = val;
        }
        __syncthreads();

        // ---- QK^T (3-term): S[64x64] ----
        {
            wmma::fragment<wmma::accumulator, 16, 16, 16, float> acc[2][2];
#pragma unroll
            for (int mt = 0; mt < 2; mt++)
#pragma unroll
                for (int nt = 0; nt < 2; nt++) wmma::fill_fragment(acc[mt][nt], 0.f);
#pragma unroll
            for (int ks = 0; ks < 4; ks++) {
                wmma::fragment<wmma::matrix_b, 16, 16, 16, bf16, wmma::col_major> fkh[2], fkl[2];
#pragma unroll
                for (int nt = 0; nt < 2; nt++) {
                    wmma::load_matrix_sync(fkh[nt], Kh + (wn*32 + nt*16)*AQ_LD + ks*16, AQ_LD);
                    wmma::load_matrix_sync(fkl[nt], Kl + (wn*32 + nt*16)*AQ_LD + ks*16, AQ_LD);
                }
#pragma unroll
                for (int mt = 0; mt < 2; mt++) {
                    wmma::fragment<wmma::matrix_a, 16, 16, 16, bf16, wmma::row_major> fqh, fql;
                    wmma::load_matrix_sync(fqh, Qh + (wm*32 + mt*16)*AQ_LD + ks*16, AQ_LD);
                    wmma::load_matrix_sync(fql, Ql + (wm*32 + mt*16)*AQ_LD + ks*16, AQ_LD);
#pragma unroll
                    for (int nt = 0; nt < 2; nt++) {
                        wmma::mma_sync(acc[mt][nt], fqh, fkh[nt], acc[mt][nt]);
                        wmma::mma_sync(acc[mt][nt], fqh, fkl[nt], acc[mt][nt]);
                        wmma::mma_sync(acc[mt][nt], fql, fkh[nt], acc[mt][nt]);
                    }
                }
            }
#pragma unroll
            for (int mt = 0; mt < 2; mt++)
#pragma unroll
                for (int nt = 0; nt < 2; nt++)
                    wmma::store_matrix_sync(S + (wm*32 + mt*16)*AS_LD + wn*32 + nt*16,
                                            acc[mt][nt], AS_LD, wmma::mem_row_major);
        }
        __syncthreads();

        // ---- online softmax (log2 domain) ----
        {
            float* Srow = S + srow*AS_LD + shalf*32;
            float rmax = -1e30f;
            if (kt == qt) {
#pragma unroll
                for (int c4 = 0; c4 < 32; c4 += 4) {
                    float4 s4 = *(float4*)&Srow[c4];
                    const int kj = k0 + shalf*32 + c4;
                    if (kj + 0 > qi) s4.x = -1e30f;
                    if (kj + 1 > qi) s4.y = -1e30f;
                    if (kj + 2 > qi) s4.z = -1e30f;
                    if (kj + 3 > qi) s4.w = -1e30f;
                    *(float4*)&Srow[c4] = s4;
                    rmax = fmaxf(rmax, fmaxf(fmaxf(s4.x, s4.y), fmaxf(s4.z, s4.w)));
                }
            } else {
#pragma unroll
                for (int c4 = 0; c4 < 32; c4 += 4) {
                    const float4 s4 = *(float4*)&Srow[c4];
                    rmax = fmaxf(rmax, fmaxf(fmaxf(s4.x, s4.y), fmaxf(s4.z, s4.w)));
                }
            }
            rmax = fmaxf(rmax, __shfl_xor_sync(0xffffffffu, rmax, 1));
            const float mnew = fmaxf(m2, rmax);
            const float alpha = exp2p(m2 - mnew);
            m2 = mnew;

            float rs = 0.f;
            bf16* PhRow = Ph + srow*AP_LD + shalf*32;
            bf16* PlRow = Pl + srow*AP_LD + shalf*32;
#pragma unroll
            for (int c4 = 0; c4 < 32; c4 += 4) {
                const float4 s4 = *(float4*)&Srow[c4];
                float p[4] = {exp2p(s4.x - mnew), exp2p(s4.y - mnew),
                              exp2p(s4.z - mnew), exp2p(s4.w - mnew)};
                rs += (p[0] + p[1]) + (p[2] + p[3]);
                bf16 h4[4], l4[4];
#pragma unroll
                for (int j = 0; j < 4; j++) {
                    h4[j] = __float2bfloat16(p[j]);
                    l4[j] = __float2bfloat16(p[j] - __bfloat162float(h4[j]));
                }
                *(uint2*)&PhRow[c4] = *(uint2*)h4;
                *(uint2*)&PlRow[c4] = *(uint2*)l4;
            }
            rs += __shfl_xor_sync(0xffffffffu, rs, 1);
            lsum = lsum * alpha + rs;
            if (shalf == 0) alpha_s[srow] = alpha;
        }
        __syncthreads();

        // ---- PV (3-term): O-tile[64x64] into S ----
        {
            wmma::fragment<wmma::accumulator, 16, 16, 16, float> accO[2][2];
#pragma unroll
            for (int mt = 0; mt < 2; mt++)
#pragma unroll
                for (int nt = 0; nt < 2; nt++) wmma::fill_fragment(accO[mt][nt], 0.f);
#pragma unroll
            for (int ks = 0; ks < 4; ks++) {
                wmma::fragment<wmma::matrix_b, 16, 16, 16, bf16, wmma::row_major> fvh[2], fvl[2];
#pragma unroll
                for (int nt = 0; nt < 2; nt++) {
                    wmma::load_matrix_sync(fvh[nt], Vh + (ks*16)*AQ_LD + wn*32 + nt*16, AQ_LD);
                    wmma::load_matrix_sync(fvl[nt], Vl + (ks*16)*AQ_LD + wn*32 + nt*16, AQ_LD);
                }
#pragma unroll
                for (int mt = 0; mt < 2; mt++) {
                    wmma::fragment<wmma::matrix_a, 16, 16, 16, bf16, wmma::row_major> fph, fpl;
                    wmma::load_matrix_sync(fph, Ph + (wm*32 + mt*16)*AP_LD + ks*16, AP_LD);
                    wmma::load_matrix_sync(fpl, Pl + (wm*32 + mt*16)*AP_LD + ks*16, AP_LD);
#pragma unroll
                    for (int nt = 0; nt < 2; nt++) {
                        wmma::mma_sync(accO[mt][nt], fph, fvh[nt], accO[mt][nt]);
                        wmma::mma_sync(accO[mt][nt], fph, fvl[nt], accO[mt][nt]);
                        wmma::mma_sync(accO[mt][nt], fpl, fvh[nt], accO[mt][nt]);
                    }
                }
            }
            __syncthreads();  // softmax reads of S complete (all threads past it)
#pragma unroll
            for (int mt = 0; mt < 2; mt++)
#pragma unroll
                for (int nt = 0; nt < 2; nt++)
                    wmma::store_matrix_sync(S + (wm*32 + mt*16)*AS_LD + wn*32 + nt*16,
                                            accO[mt][nt], AS_LD, wmma::mem_row_major);
        }
        __syncthreads();

        // ---- O update ----
#pragma unroll
        for (int r = 0; r < 8; r++) {
            const int row = 8*ty + r;
            const float a = alpha_s[row];
            const float4 pv = *(float4*)&S[row*AS_LD + 4*tx];
            o_acc[r][0] = fmaf(o_acc[r][0], a, pv.x);
            o_acc[r][1] = fmaf(o_acc[r][1], a, pv.y);
            o_acc[r][2] = fmaf(o_acc[r][2], a, pv.z);
            o_acc[r][3] = fmaf(o_acc[r][3], a, pv.w);
        }
    }

    if (shalf == 0) l_s[srow] = lsum;
    __syncthreads();

    // epilogue: normalize, split, write [M, C] bf16 hi/lo
#pragma unroll
    for (int r = 0; r < 8; r++) {
        const int row = 8*ty + r;
        const float il = 1.f / l_s[row];
        bf16 h4[4], l4[4];
#pragma unroll
        for (int c = 0; c < 4; c++) {
            const float val = o_acc[r][c] * il;
            h4[c] = __float2bfloat16(val);
            l4[c] = __float2bfloat16(val - __bfloat162float(h4[c]));
        }
        const size_t doff = ((size_t)(b*T_ + q0 + row)) * C_ + h*D_ + 4*tx;
        *(uint2*)(ah_out + doff) = *(uint2*)h4;
        *(uint2*)(al_out + doff) = *(uint2*)l4;
    }
}

// ---------------------------------------------------------------------------
extern "C" void kernel_launch(void* const* d_in, const int* in_sizes, int n_in,
                              void* d_out, int out_size)
{
    const float* x  = (const float*)d_in[0];
    const float* Wq = (const float*)d_in[1];
    const float* bq = (const float*)d_in[2];
    const float* Wk = (const float*)d_in[3];
    const float* bk = (const float*)d_in[4];
    const float* Wv = (const float*)d_in[5];
    const float* bv = (const float*)d_in[6];
    const float* Wo = (const float*)d_in[7];
    const float* bo = (const float*)d_in[8];
    float* out = (float*)d_out;

    float2* csp;
    bf16 *xh, *xl, *ah, *al, *wh, *wl;
    bf16 *qhp, *qlp, *khp, *klp, *vhp, *vlp;
    cudaGetSymbolAddress((void**)&csp,  g_cs);
    cudaGetSymbolAddress((void**)&xh,   g_x_hi);
    cudaGetSymbolAddress((void**)&xl,   g_x_lo);
    cudaGetSymbolAddress((void**)&ah,   g_a_hi);
    cudaGetSymbolAddress((void**)&al,   g_a_lo);
    cudaGetSymbolAddress((void**)&wh,   g_w_hi);
    cudaGetSymbolAddress((void**)&wl,   g_w_lo);
    cudaGetSymbolAddress((void**)&qhp,  g_qh);
    cudaGetSymbolAddress((void**)&qlp,  g_ql);
    cudaGetSymbolAddress((void**)&khp,  g_kh);
    cudaGetSymbolAddress((void**)&klp,  g_kl);
    cudaGetSymbolAddress((void**)&vhp,  g_vh);
    cudaGetSymbolAddress((void**)&vlp,  g_vl);

    rope_table<<<(T_*32)/256, 256>>>(csp);

    cvt_split<<<(M_*C_/4)/256, 256>>>(x,  xh, xl, M_*C_/4);
    cvt_split<<<(C_*C_/4)/256, 256>>>(Wq, wh + 0*(size_t)C_*C_, wl + 0*(size_t)C_*C_, C_*C_/4);
    cvt_split<<<(C_*C_/4)/256, 256>>>(Wk, wh + 1*(size_t)C_*C_, wl + 1*(size_t)C_*C_, C_*C_/4);
    cvt_split<<<(C_*C_/4)/256, 256>>>(Wv, wh + 2*(size_t)C_*C_, wl + 2*(size_t)C_*C_, C_*C_/4);
    cvt_split<<<(C_*C_/4)/256, 256>>>(Wo, wh + 3*(size_t)C_*C_, wl + 3*(size_t)C_*C_, C_*C_/4);

    const size_t gsmem = 2*STAGE_BG + 512;
    cudaFuncSetAttribute(qkv_mma, cudaFuncAttributeMaxDynamicSharedMemorySize, (int)gsmem);
    cudaFuncSetAttribute(out_mma, cudaFuncAttributeMaxDynamicSharedMemorySize, (int)gsmem);
    cudaFuncSetAttribute(attn_wmma, cudaFuncAttributeMaxDynamicSharedMemorySize, ATTN_SMEM);

    qkv_mma<<<dim3(C_/128, M_/128, 3), 256, gsmem>>>(xh, xl, bq, bk, bv, csp);

    attn_wmma<<<dim3(T_/64, B_*H_), 128, ATTN_SMEM>>>(qhp, qlp, khp, klp, vhp, vlp, ah, al);

    out_mma<<<dim3(C_/128, M_/128), 256, gsmem>>>(ah, al, bo, out);
}

// round 12
// speedup vs baseline: 2.5166x; 1.2525x over previous
#include <cuda_runtime.h>
#include <cuda_bf16.h>
#include <mma.h>
#include <math.h>
#include <stdint.h>

using namespace nvcuda;

#define B_ 2
#define T_ 2048
#define C_ 1024
#define H_ 16
#define D_ 64
#define M_ (B_*T_)
#define QSCALE 0.1803368801111437f  // (1/sqrt(64)) * log2(e)

typedef __nv_bfloat16 bf16;

// ---------------------------------------------------------------------------
// Scratch (allocation-free contract: __device__ globals)
// ---------------------------------------------------------------------------
__device__ float2 g_cs[T_*32];
__device__ bf16 g_x_hi[M_*C_],  g_x_lo[M_*C_];
__device__ bf16 g_a_hi[M_*C_],  g_a_lo[M_*C_];
__device__ bf16 g_w_hi[4][C_*C_], g_w_lo[4][C_*C_];
__device__ bf16 g_qh[B_*H_*T_*D_], g_ql[B_*H_*T_*D_];
__device__ bf16 g_kh[B_*H_*T_*D_], g_kl[B_*H_*T_*D_];
__device__ bf16 g_vh[B_*H_*T_*D_], g_vl[B_*H_*T_*D_];

// ---------------------------------------------------------------------------
// cp.async / ldmatrix / mma helpers
// ---------------------------------------------------------------------------
#define CP_ASYNC16(dst, src) \
    asm volatile("cp.async.cg.shared.global [%0], [%1], 16;" :: "r"(dst), "l"(src) : "memory")
#define CP_COMMIT() asm volatile("cp.async.commit_group;" ::: "memory")
#define CP_WAIT0()  asm volatile("cp.async.wait_group 0;" ::: "memory")
#define CP_WAIT1()  asm volatile("cp.async.wait_group 1;" ::: "memory")

#define LDSM_X4(r0,r1,r2,r3, a) \
    asm volatile("ldmatrix.sync.aligned.m8n8.x4.shared.b16 {%0,%1,%2,%3}, [%4];" \
        : "=r"(r0),"=r"(r1),"=r"(r2),"=r"(r3) : "r"(a))
#define LDSM_X4T(r0,r1,r2,r3, a) \
    asm volatile("ldmatrix.sync.aligned.m8n8.x4.trans.shared.b16 {%0,%1,%2,%3}, [%4];" \
        : "=r"(r0),"=r"(r1),"=r"(r2),"=r"(r3) : "r"(a))

#define MMA_BF16(d, a0,a1,a2,a3, b0,b1) \
    asm volatile("mma.sync.aligned.m16n8k16.row.col.f32.bf16.bf16.f32 " \
        "{%0,%1,%2,%3},{%4,%5,%6,%7},{%8,%9},{%0,%1,%2,%3};" \
        : "+f"((d)[0]),"+f"((d)[1]),"+f"((d)[2]),"+f"((d)[3]) \
        : "r"(a0),"r"(a1),"r"(a2),"r"(a3), "r"(b0),"r"(b1))

// pack two fp32 -> bf16x2 (lo = first arg)
#define PACK_BF2(d, lo, hi) \
    asm("cvt.rn.bf16x2.f32 %0, %1, %2;" : "=r"(d) : "f"(hi), "f"(lo))

__device__ __forceinline__ uint32_t smem_u32(const void* p) {
    uint32_t a;
    asm("{ .reg .u64 t; cvta.to.shared.u64 t, %1; cvt.u32.u64 %0, t; }" : "=r"(a) : "l"(p));
    return a;
}

// ---------------------------------------------------------------------------
// FMA-pipe exp2: x <= 0
// ---------------------------------------------------------------------------
__device__ __forceinline__ float exp2p(float x)
{
    x = fmaxf(x, -125.0f);
    const float r = rintf(x);
    const float f = x - r;
    float p = 0.0013333558f;
    p = fmaf(p, f, 0.0096181291f);
    p = fmaf(p, f, 0.0555041087f);
    p = fmaf(p, f, 0.2402265070f);
    p = fmaf(p, f, 0.6931471806f);
    p = fmaf(p, f, 1.0f);
    const int e = (int)r;
    return p * __int_as_float((e + 127) << 23);
}

// ---------------------------------------------------------------------------
// RoPE table
// ---------------------------------------------------------------------------
__global__ void rope_table(float2* __restrict__ tab)
{
    const int idx = blockIdx.x * blockDim.x + threadIdx.x;
    if (idx >= T_*32) return;
    const int t = idx >> 5, i = idx & 31;
    const double inv = pow(10000.0, -(double)(2*i) / 64.0);
    const double ang = (double)t * inv;
    tab[idx] = make_float2((float)cos(ang), (float)sin(ang));
}

// ---------------------------------------------------------------------------
// fp32 -> (bf16 hi, bf16 lo) split
// ---------------------------------------------------------------------------
__global__ __launch_bounds__(256)
void cvt_split(const float* __restrict__ in, bf16* __restrict__ hi,
               bf16* __restrict__ lo, int n4)
{
    const int i = blockIdx.x * blockDim.x + threadIdx.x;
    if (i >= n4) return;
    const float4 v = ((const float4*)in)[i];
    float f[4] = {v.x, v.y, v.z, v.w};
    bf16 h[4], l[4];
#pragma unroll
    for (int j = 0; j < 4; j++) {
        h[j] = __float2bfloat16(f[j]);
        l[j] = __float2bfloat16(f[j] - __bfloat162float(h[j]));
    }
    ((__nv_bfloat162*)hi)[2*i]   = __nv_bfloat162(h[0], h[1]);
    ((__nv_bfloat162*)hi)[2*i+1] = __nv_bfloat162(h[2], h[3]);
    ((__nv_bfloat162*)lo)[2*i]   = __nv_bfloat162(l[0], l[1]);
    ((__nv_bfloat162*)lo)[2*i+1] = __nv_bfloat162(l[2], l[3]);
}

// ---------------------------------------------------------------------------
// Pipelined wmma bf16 GEMM (cp.async double buffer) — unchanged (R10/R11).
// ---------------------------------------------------------------------------
#define SLDB 40
#define TILE_BG (128*SLDB*2)
#define STAGE_BG (4*TILE_BG)
#define LDE 132
#define NCH2 (C_/32)

__device__ __forceinline__
void mma_gemm_body(const bf16* __restrict__ Ah, const bf16* __restrict__ Al,
                   const bf16* __restrict__ Wh, const bf16* __restrict__ Wl,
                   const float* __restrict__ bias,
                   bf16* __restrict__ oh, bf16* __restrict__ ol,
                   float* __restrict__ of,
                   const float2* __restrict__ cs, int z)
{
    extern __shared__ char smem[];
    const uint32_t sbase = smem_u32(smem);
    float* sEpi   = (float*)smem;
    float* bias_s = (float*)(smem + 2*STAGE_BG);

    const int tid = threadIdx.x;
    const int wid = tid >> 5;
    const int wm = wid >> 2;
    const int wn = wid & 3;
    const int m0 = blockIdx.y << 7, n0 = blockIdx.x << 7;

    if (tid < 128) bias_s[tid] = bias[n0 + tid];

    const bf16* srcs[4] = {Ah, Al, Wh, Wl};
    const int row0[4] = {m0, m0, n0, n0};

    int jtile[8], jr[8], jv[8];
#pragma unroll
    for (int it = 0; it < 8; it++) {
        const int job = it * 256 + tid;
        jtile[it] = job >> 9;
        const int idx = job & 511;
        jr[it] = idx >> 2;
        jv[it] = idx & 3;
    }

#pragma unroll
    for (int it = 0; it < 8; it++) {
        const bf16* g = srcs[jtile[it]] + (size_t)(row0[jtile[it]] + jr[it]) * C_ + jv[it]*8;
        CP_ASYNC16(sbase + jtile[it]*TILE_BG + jr[it]*80 + jv[it]*16, g);
    }
    CP_COMMIT();

    wmma::fragment<wmma::accumulator, 16, 16, 16, float> acc[4][2];
#pragma unroll
    for (int mt = 0; mt < 4; mt++)
#pragma unroll
        for (int nt = 0; nt < 2; nt++) wmma::fill_fragment(acc[mt][nt], 0.f);

    for (int kc = 0; kc < NCH2; kc++) {
        const int s = kc & 1;
        if (kc + 1 < NCH2) {
            const uint32_t db = sbase + (s^1)*STAGE_BG;
            const int koff = (kc+1)*32;
#pragma unroll
            for (int it = 0; it < 8; it++) {
                const bf16* g = srcs[jtile[it]] + (size_t)(row0[jtile[it]] + jr[it]) * C_ + koff + jv[it]*8;
                CP_ASYNC16(db + jtile[it]*TILE_BG + jr[it]*80 + jv[it]*16, g);
            }
            CP_COMMIT();
            CP_WAIT1();
        } else {
            CP_WAIT0();
        }
        __syncthreads();

        bf16* sT = (bf16*)(smem + s*STAGE_BG);
#pragma unroll
        for (int ks = 0; ks < 2; ks++) {
            wmma::fragment<wmma::matrix_b, 16, 16, 16, bf16, wmma::col_major> fwh[2], fwl[2];
#pragma unroll
            for (int nt = 0; nt < 2; nt++) {
                wmma::load_matrix_sync(fwh[nt], sT + 2*(128*SLDB) + (wn*32 + nt*16)*SLDB + ks*16, SLDB);
                wmma::load_matrix_sync(fwl[nt], sT + 3*(128*SLDB) + (wn*32 + nt*16)*SLDB + ks*16, SLDB);
            }
#pragma unroll
            for (int mt = 0; mt < 4; mt++) {
                wmma::fragment<wmma::matrix_a, 16, 16, 16, bf16, wmma::row_major> fah, fal;
                wmma::load_matrix_sync(fah, sT + 0*(128*SLDB) + (wm*64 + mt*16)*SLDB + ks*16, SLDB);
                wmma::load_matrix_sync(fal, sT + 1*(128*SLDB) + (wm*64 + mt*16)*SLDB + ks*16, SLDB);
#pragma unroll
                for (int nt = 0; nt < 2; nt++) {
                    wmma::mma_sync(acc[mt][nt], fah, fwh[nt], acc[mt][nt]);
                    wmma::mma_sync(acc[mt][nt], fah, fwl[nt], acc[mt][nt]);
                    wmma::mma_sync(acc[mt][nt], fal, fwh[nt], acc[mt][nt]);
                }
            }
        }
        __syncthreads();
    }

#pragma unroll
    for (int mt = 0; mt < 4; mt++)
#pragma unroll
        for (int nt = 0; nt < 2; nt++)
            wmma::store_matrix_sync(sEpi + (wm*64 + mt*16)*LDE + wn*32 + nt*16,
                                    acc[mt][nt], LDE, wmma::mem_row_major);
    __syncthreads();

    const int tx = tid & 15, ty = tid >> 4;
    const int n_base = n0 + 8*tx;
    const float4 b0 = *(const float4*)&bias_s[8*tx];
    const float4 b1 = *(const float4*)&bias_s[8*tx + 4];
    const float bb[8] = {b0.x, b0.y, b0.z, b0.w, b1.x, b1.y, b1.z, b1.w};

#pragma unroll
    for (int r = 0; r < 8; r++) {
        const int lrow = 8*ty + r;
        const int m = m0 + lrow;
        float o[8];
#pragma unroll
        for (int j = 0; j < 8; j++) o[j] = sEpi[lrow*LDE + 8*tx + j] + bb[j];

        if (z < 2) {
            const int t = m & (T_-1);
#pragma unroll
            for (int p = 0; p < 4; p++) {
                const int i = ((n_base + 2*p) & 63) >> 1;
                const float2 csv = cs[t*32 + i];
                const float x1 = o[2*p], x2 = o[2*p+1];
                o[2*p]   = x1*csv.x - x2*csv.y;
                o[2*p+1] = x1*csv.y + x2*csv.x;
            }
        }
        if (z == 0) {
#pragma unroll
            for (int j = 0; j < 8; j++) o[j] *= QSCALE;
        }

        if (z <= 2) {
            bf16 h8[8], l8[8];
#pragma unroll
            for (int j = 0; j < 8; j++) {
                h8[j] = __float2bfloat16(o[j]);
                l8[j] = __float2bfloat16(o[j] - __bfloat162float(h8[j]));
            }
            const int b = m >> 11, t = m & (T_-1);
            const int h = n_base >> 6, d = n_base & 63;
            const size_t doff = (((size_t)(b*H_ + h) * T_) + t) * D_ + d;
            *(uint4*)(oh + doff) = *(uint4*)h8;
            *(uint4*)(ol + doff) = *(uint4*)l8;
        } else {
            float* dst = of + (size_t)m * C_ + n_base;
            *(float4*)dst = make_float4(o[0], o[1], o[2], o[3]);
            *(float4*)(dst + 4) = make_float4(o[4], o[5], o[6], o[7]);
        }
    }
}

__global__ __launch_bounds__(256, 2)
void qkv_mma(const bf16* __restrict__ xh, const bf16* __restrict__ xl,
             const float* __restrict__ bq, const float* __restrict__ bk,
             const float* __restrict__ bv, const float2* __restrict__ cs)
{
    const int z = blockIdx.z;
    const float* bias = (z == 0) ? bq : (z == 1) ? bk : bv;
    bf16* oh = (z == 0) ? g_qh : (z == 1) ? g_kh : g_vh;
    bf16* ol = (z == 0) ? g_ql : (z == 1) ? g_kl : g_vl;
    mma_gemm_body(xh, xl, g_w_hi[z], g_w_lo[z], bias, oh, ol, nullptr, cs, z);
}

__global__ __launch_bounds__(256, 2)
void out_mma(const bf16* __restrict__ ah, const bf16* __restrict__ al,
             const float* __restrict__ bias, float* __restrict__ out)
{
    mma_gemm_body(ah, al, g_w_hi[3], g_w_lo[3], bias, nullptr, nullptr, out, nullptr, 3);
}

// ---------------------------------------------------------------------------
// Register-resident FA2 attention (raw mma.sync), causal.
// 128 threads = 4 warps; CTA tile 64q; warp w owns rows w*16..w*16+15.
// Q frags in regs (from gmem), K/V hi/lo double-buffered smem via cp.async,
// S and O live in mma fragments; softmax in registers (quad shfl).
// ---------------------------------------------------------------------------
#define ROWB 144                 // smem row stride bytes (72 bf16)
#define KVBUF 36864              // 4 tiles * 64 rows * 144B
#define ATTN_SMEM (2*KVBUF)      // 73728

__global__ __launch_bounds__(128, 2)
void attn_fa2(const bf16* __restrict__ qh, const bf16* __restrict__ ql,
              const bf16* __restrict__ kh, const bf16* __restrict__ kl,
              const bf16* __restrict__ vh, const bf16* __restrict__ vl,
              bf16* __restrict__ ah_out, bf16* __restrict__ al_out)
{
    extern __shared__ char smem[];
    const uint32_t sbase = smem_u32(smem);

    const int tid  = threadIdx.x;
    const int w    = tid >> 5;
    const int lane = tid & 31;
    const int tig  = lane & 3;          // thread-in-group
    const int grp  = lane >> 2;         // row within 8
    const int bh = blockIdx.y;
    const int b = bh >> 4, h = bh & (H_-1);
    const int qt = gridDim.x - 1 - blockIdx.x;
    const int q0 = qt << 6;

    const size_t hb = (size_t)bh * T_ * D_;
    const bf16* qhb = qh + hb; const bf16* qlb = ql + hb;
    const bf16* khb = kh + hb; const bf16* klb = kl + hb;
    const bf16* vhb = vh + hb; const bf16* vlb = vl + hb;

    // --- prefetch job decode (16 x 16B per thread per iteration) ---
    int jtile[16], jr[16], jv[16];
#pragma unroll
    for (int it = 0; it < 16; it++) {
        const int job = it * 128 + tid;
        jtile[it] = job >> 9;            // 0:kh 1:kl 2:vh 3:vl
        jr[it] = (job >> 3) & 63;
        jv[it] = job & 7;
    }
    const bf16* ksrc[4] = {khb, klb, vhb, vlb};

    // prologue: prefetch kt=0 into buf 0
#pragma unroll
    for (int it = 0; it < 16; it++) {
        CP_ASYNC16(sbase + jtile[it]*9216 + jr[it]*ROWB + jv[it]*16,
                   ksrc[jtile[it]] + (size_t)jr[it]*D_ + jv[it]*8);
    }
    CP_COMMIT();

    // --- Q fragments from gmem (bf16x2 = LDG.32), kept for whole kernel ---
    uint32_t qfh[4][4], qfl[4][4];
    {
        const int r0 = q0 + w*16 + grp;
#pragma unroll
        for (int ks = 0; ks < 4; ks++) {
            const int c = ks*16 + tig*2;
            qfh[ks][0] = *(const uint32_t*)(qhb + (size_t)r0*D_ + c);
            qfh[ks][1] = *(const uint32_t*)(qhb + (size_t)(r0+8)*D_ + c);
            qfh[ks][2] = *(const uint32_t*)(qhb + (size_t)r0*D_ + c + 8);
            qfh[ks][3] = *(const uint32_t*)(qhb + (size_t)(r0+8)*D_ + c + 8);
            qfl[ks][0] = *(const uint32_t*)(qlb + (size_t)r0*D_ + c);
            qfl[ks][1] = *(const uint32_t*)(qlb + (size_t)(r0+8)*D_ + c);
            qfl[ks][2] = *(const uint32_t*)(qlb + (size_t)r0*D_ + c + 8);
            qfl[ks][3] = *(const uint32_t*)(qlb + (size_t)(r0+8)*D_ + c + 8);
        }
    }

    // O accumulator fragments: 8 d-tiles x 4 (rows grp/grp+8, col pair)
    float o[8][4];
#pragma unroll
    for (int t = 0; t < 8; t++)
#pragma unroll
        for (int e = 0; e < 4; e++) o[t][e] = 0.f;

    float m0 = -1e30f, m1 = -1e30f, l0 = 0.f, l1 = 0.f;

    // per-lane ldmatrix addresses (offsets within a KV buffer)
    //  K (non-trans): tile t, kk2: row = t*8 + (lane&7); colB = kk2*64 + (lane>>3)*16
    const uint32_t koffA = (uint32_t)((lane & 7) * ROWB + (lane >> 3) * 16);
    //  V (trans): key = kk2*32 + (lane>>3)*8 + (lane&7); colB = t*16
    const uint32_t voffA = (uint32_t)(((lane >> 3) * 8 + (lane & 7)) * ROWB);

    for (int kt = 0; kt <= qt; kt++) {
        const int buf = kt & 1;
        const uint32_t kb = sbase + buf*KVBUF;          // kh tile
        const uint32_t lb = kb + 9216;                  // kl
        const uint32_t vb = kb + 18432;                 // vh
        const uint32_t wb = kb + 27648;                 // vl

        if (kt > 0) __syncthreads();     // all warps done with buf being refilled
        if (kt < qt) {
            const uint32_t db = sbase + ((kt+1)&1)*KVBUF;
            const size_t soff = (size_t)(kt+1)*64*D_;
#pragma unroll
            for (int it = 0; it < 16; it++) {
                CP_ASYNC16(db + jtile[it]*9216 + jr[it]*ROWB + jv[it]*16,
                           ksrc[jtile[it]] + soff + (size_t)jr[it]*D_ + jv[it]*8);
            }
            CP_COMMIT();
            CP_WAIT1();
        } else {
            CP_WAIT0();
        }
        __syncthreads();

        // ---- QK^T: S[8 n-tiles][4] ----
        float s[8][4];
#pragma unroll
        for (int t = 0; t < 8; t++)
#pragma unroll
            for (int e = 0; e < 4; e++) s[t][e] = 0.f;

#pragma unroll
        for (int t = 0; t < 8; t++) {
#pragma unroll
            for (int kk2 = 0; kk2 < 2; kk2++) {
                uint32_t h0,h1,h2,h3, x0,x1,x2,x3;
                const uint32_t ka = kb + (uint32_t)(t*8*ROWB) + (uint32_t)(kk2*64) + koffA;
                const uint32_t la = lb + (uint32_t)(t*8*ROWB) + (uint32_t)(kk2*64) + koffA;
                LDSM_X4(h0,h1,h2,h3, ka);
                LDSM_X4(x0,x1,x2,x3, la);
                const int ks0 = 2*kk2, ks1 = 2*kk2 + 1;
                MMA_BF16(s[t], qfh[ks0][0],qfh[ks0][1],qfh[ks0][2],qfh[ks0][3], h0,h1);
                MMA_BF16(s[t], qfh[ks0][0],qfh[ks0][1],qfh[ks0][2],qfh[ks0][3], x0,x1);
                MMA_BF16(s[t], qfl[ks0][0],qfl[ks0][1],qfl[ks0][2],qfl[ks0][3], h0,h1);
                MMA_BF16(s[t], qfh[ks1][0],qfh[ks1][1],qfh[ks1][2],qfh[ks1][3], h2,h3);
                MMA_BF16(s[t], qfh[ks1][0],qfh[ks1][1],qfh[ks1][2],qfh[ks1][3], x2,x3);
                MMA_BF16(s[t], qfl[ks1][0],qfl[ks1][1],qfl[ks1][2],qfl[ks1][3], h2,h3);
            }
        }

        // ---- mask (diag tile only) ----
        if (kt == qt) {
            const int i0 = w*16 + grp, i1 = i0 + 8;
#pragma unroll
            for (int t = 0; t < 8; t++) {
                const int j = t*8 + tig*2;
                if (j   > i0) s[t][0] = -1e30f;
                if (j+1 > i0) s[t][1] = -1e30f;
                if (j   > i1) s[t][2] = -1e30f;
                if (j+1 > i1) s[t][3] = -1e30f;
            }
        }

        // ---- online softmax in registers ----
        float mx0 = -1e30f, mx1 = -1e30f;
#pragma unroll
        for (int t = 0; t < 8; t++) {
            mx0 = fmaxf(mx0, fmaxf(s[t][0], s[t][1]));
            mx1 = fmaxf(mx1, fmaxf(s[t][2], s[t][3]));
        }
        mx0 = fmaxf(mx0, __shfl_xor_sync(0xffffffffu, mx0, 1));
        mx0 = fmaxf(mx0, __shfl_xor_sync(0xffffffffu, mx0, 2));
        mx1 = fmaxf(mx1, __shfl_xor_sync(0xffffffffu, mx1, 1));
        mx1 = fmaxf(mx1, __shfl_xor_sync(0xffffffffu, mx1, 2));

        const float mn0 = fmaxf(m0, mx0), mn1 = fmaxf(m1, mx1);
        const float al0 = exp2p(m0 - mn0), al1 = exp2p(m1 - mn1);
        m0 = mn0; m1 = mn1;

        uint32_t pah0[8], pah1[8], pal0[8], pal1[8];
        float ps0 = 0.f, ps1 = 0.f;
#pragma unroll
        for (int t = 0; t < 8; t++) {
            const float p00 = exp2p(s[t][0] - mn0);
            const float p01 = exp2p(s[t][1] - mn0);
            const float p10 = exp2p(s[t][2] - mn1);
            const float p11 = exp2p(s[t][3] - mn1);
            ps0 += p00 + p01; ps1 += p10 + p11;
            PACK_BF2(pah0[t], p00, p01);
            PACK_BF2(pah1[t], p10, p11);
            const float r00 = p00 - __int_as_float(pah0[t] << 16);
            const float r01 = p01 - __int_as_float(pah0[t] & 0xffff0000u);
            const float r10 = p10 - __int_as_float(pah1[t] << 16);
            const float r11 = p11 - __int_as_float(pah1[t] & 0xffff0000u);
            PACK_BF2(pal0[t], r00, r01);
            PACK_BF2(pal1[t], r10, r11);
        }
        ps0 += __shfl_xor_sync(0xffffffffu, ps0, 1);
        ps0 += __shfl_xor_sync(0xffffffffu, ps0, 2);
        ps1 += __shfl_xor_sync(0xffffffffu, ps1, 1);
        ps1 += __shfl_xor_sync(0xffffffffu, ps1, 2);
        l0 = l0 * al0 + ps0;
        l1 = l1 * al1 + ps1;

        // rescale O
#pragma unroll
        for (int t = 0; t < 8; t++) {
            o[t][0] *= al0; o[t][1] *= al0;
            o[t][2] *= al1; o[t][3] *= al1;
        }

        // ---- PV: O += P * V ----
#pragma unroll
        for (int t = 0; t < 8; t++) {
#pragma unroll
            for (int kk2 = 0; kk2 < 2; kk2++) {
                uint32_t h0,h1,h2,h3, x0,x1,x2,x3;
                const uint32_t va = vb + (uint32_t)(kk2*32*ROWB) + (uint32_t)(t*16) + voffA;
                const uint32_t wa = wb + (uint32_t)(kk2*32*ROWB) + (uint32_t)(t*16) + voffA;
                LDSM_X4T(h0,h1,h2,h3, va);
                LDSM_X4T(x0,x1,x2,x3, wa);
                const int ks0 = 2*kk2, ks1 = 2*kk2 + 1;
                MMA_BF16(o[t], pah0[2*ks0],pah1[2*ks0],pah0[2*ks0+1],pah1[2*ks0+1], h0,h1);
                MMA_BF16(o[t], pah0[2*ks0],pah1[2*ks0],pah0[2*ks0+1],pah1[2*ks0+1], x0,x1);
                MMA_BF16(o[t], pal0[2*ks0],pal1[2*ks0],pal0[2*ks0+1],pal1[2*ks0+1], h0,h1);
                MMA_BF16(o[t], pah0[2*ks1],pah1[2*ks1],pah0[2*ks1+1],pah1[2*ks1+1], h2,h3);
                MMA_BF16(o[t], pah0[2*ks1],pah1[2*ks1],pah0[2*ks1+1],pah1[2*ks1+1], x2,x3);
                MMA_BF16(o[t], pal0[2*ks1],pal1[2*ks1],pal0[2*ks1+1],pal1[2*ks1+1], h2,h3);
            }
        }
    }

    // ---- epilogue: normalize, split, store [M, C] bf16 hi/lo ----
    const float il0 = 1.f / l0, il1 = 1.f / l1;
    const int r0g = q0 + w*16 + grp;
    const size_t base0 = ((size_t)(b*T_ + r0g)) * C_ + h*D_ + tig*2;
    const size_t base1 = ((size_t)(b*T_ + r0g + 8)) * C_ + h*D_ + tig*2;
#pragma unroll
    for (int t = 0; t < 8; t++) {
        const float v00 = o[t][0]*il0, v01 = o[t][1]*il0;
        const float v10 = o[t][2]*il1, v11 = o[t][3]*il1;
        uint32_t h0, h1, lo0, lo1;
        PACK_BF2(h0, v00, v01);
        PACK_BF2(h1, v10, v11);
        const float q00 = v00 - __int_as_float(h0 << 16);
        const float q01 = v01 - __int_as_float(h0 & 0xffff0000u);
        const float q10 = v10 - __int_as_float(h1 << 16);
        const float q11 = v11 - __int_as_float(h1 & 0xffff0000u);
        PACK_BF2(lo0, q00, q01);
        PACK_BF2(lo1, q10, q11);
        *(uint32_t*)(ah_out + base0 + t*8) = h0;
        *(uint32_t*)(ah_out + base1 + t*8) = h1;
        *(uint32_t*)(al_out + base0 + t*8) = lo0;
        *(uint32_t*)(al_out + base1 + t*8) = lo1;
    }
}

// ---------------------------------------------------------------------------
extern "C" void kernel_launch(void* const* d_in, const int* in_sizes, int n_in,
                              void* d_out, int out_size)
{
    const float* x  = (const float*)d_in[0];
    const float* Wq = (const float*)d_in[1];
    const float* bq = (const float*)d_in[2];
    const float* Wk = (const float*)d_in[3];
    const float* bk = (const float*)d_in[4];
    const float* Wv = (const float*)d_in[5];
    const float* bv = (const float*)d_in[6];
    const float* Wo = (const float*)d_in[7];
    const float* bo = (const float*)d_in[8];
    float* out = (float*)d_out;

    float2* csp;
    bf16 *xh, *xl, *ah, *al, *wh, *wl;
    bf16 *qhp, *qlp, *khp, *klp, *vhp, *vlp;
    cudaGetSymbolAddress((void**)&csp,  g_cs);
    cudaGetSymbolAddress((void**)&xh,   g_x_hi);
    cudaGetSymbolAddress((void**)&xl,   g_x_lo);
    cudaGetSymbolAddress((void**)&ah,   g_a_hi);
    cudaGetSymbolAddress((void**)&al,   g_a_lo);
    cudaGetSymbolAddress((void**)&wh,   g_w_hi);
    cudaGetSymbolAddress((void**)&wl,   g_w_lo);
    cudaGetSymbolAddress((void**)&qhp,  g_qh);
    cudaGetSymbolAddress((void**)&qlp,  g_ql);
    cudaGetSymbolAddress((void**)&khp,  g_kh);
    cudaGetSymbolAddress((void**)&klp,  g_kl);
    cudaGetSymbolAddress((void**)&vhp,  g_vh);
    cudaGetSymbolAddress((void**)&vlp,  g_vl);

    rope_table<<<(T_*32)/256, 256>>>(csp);

    cvt_split<<<(M_*C_/4)/256, 256>>>(x,  xh, xl, M_*C_/4);
    cvt_split<<<(C_*C_/4)/256, 256>>>(Wq, wh + 0*(size_t)C_*C_, wl + 0*(size_t)C_*C_, C_*C_/4);
    cvt_split<<<(C_*C_/4)/256, 256>>>(Wk, wh + 1*(size_t)C_*C_, wl + 1*(size_t)C_*C_, C_*C_/4);
    cvt_split<<<(C_*C_/4)/256, 256>>>(Wv, wh + 2*(size_t)C_*C_, wl + 2*(size_t)C_*C_, C_*C_/4);
    cvt_split<<<(C_*C_/4)/256, 256>>>(Wo, wh + 3*(size_t)C_*C_, wl + 3*(size_t)C_*C_, C_*C_/4);

    const size_t gsmem = 2*STAGE_BG + 512;
    cudaFuncSetAttribute(qkv_mma, cudaFuncAttributeMaxDynamicSharedMemorySize, (int)gsmem);
    cudaFuncSetAttribute(out_mma, cudaFuncAttributeMaxDynamicSharedMemorySize, (int)gsmem);
    cudaFuncSetAttribute(attn_fa2, cudaFuncAttributeMaxDynamicSharedMemorySize, ATTN_SMEM);

    qkv_mma<<<dim3(C_/128, M_/128, 3), 256, gsmem>>>(xh, xl, bq, bk, bv, csp);

    attn_fa2<<<dim3(T_/64, B_*H_), 128, ATTN_SMEM>>>(qhp, qlp, khp, klp, vhp, vlp, ah, al);

    out_mma<<<dim3(C_/128, M_/128), 256, gsmem>>>(ah, al, bo, out);
}

// round 13
// speedup vs baseline: 2.5559x; 1.0156x over previous
#include <cuda_runtime.h>
#include <cuda_bf16.h>
#include <mma.h>
#include <math.h>
#include <stdint.h>

using namespace nvcuda;

#define B_ 2
#define T_ 2048
#define C_ 1024
#define H_ 16
#define D_ 64
#define M_ (B_*T_)
#define QSCALE 0.1803368801111437f  // (1/sqrt(64)) * log2(e)

typedef __nv_bfloat16 bf16;

// ---------------------------------------------------------------------------
// Scratch (allocation-free contract: __device__ globals)
// ---------------------------------------------------------------------------
__device__ float2 g_cs[T_*32];
__device__ bf16 g_x_hi[M_*C_],  g_x_lo[M_*C_];
__device__ bf16 g_a_hi[M_*C_],  g_a_lo[M_*C_];
__device__ bf16 g_w_hi[4][C_*C_], g_w_lo[4][C_*C_];
__device__ bf16 g_qh[B_*H_*T_*D_], g_ql[B_*H_*T_*D_];
__device__ bf16 g_kh[B_*H_*T_*D_], g_kl[B_*H_*T_*D_];
__device__ bf16 g_vh[B_*H_*T_*D_], g_vl[B_*H_*T_*D_];

// ---------------------------------------------------------------------------
// cp.async / ldmatrix / mma helpers
// ---------------------------------------------------------------------------
#define CP_ASYNC16(dst, src) \
    asm volatile("cp.async.cg.shared.global [%0], [%1], 16;" :: "r"(dst), "l"(src) : "memory")
#define CP_COMMIT() asm volatile("cp.async.commit_group;" ::: "memory")
#define CP_WAIT0()  asm volatile("cp.async.wait_group 0;" ::: "memory")
#define CP_WAIT1()  asm volatile("cp.async.wait_group 1;" ::: "memory")

#define LDSM_X4(r0,r1,r2,r3, a) \
    asm volatile("ldmatrix.sync.aligned.m8n8.x4.shared.b16 {%0,%1,%2,%3}, [%4];" \
        : "=r"(r0),"=r"(r1),"=r"(r2),"=r"(r3) : "r"(a))
#define LDSM_X4T(r0,r1,r2,r3, a) \
    asm volatile("ldmatrix.sync.aligned.m8n8.x4.trans.shared.b16 {%0,%1,%2,%3}, [%4];" \
        : "=r"(r0),"=r"(r1),"=r"(r2),"=r"(r3) : "r"(a))

#define MMA_BF16(d, a0,a1,a2,a3, b0,b1) \
    asm volatile("mma.sync.aligned.m16n8k16.row.col.f32.bf16.bf16.f32 " \
        "{%0,%1,%2,%3},{%4,%5,%6,%7},{%8,%9},{%0,%1,%2,%3};" \
        : "+f"((d)[0]),"+f"((d)[1]),"+f"((d)[2]),"+f"((d)[3]) \
        : "r"(a0),"r"(a1),"r"(a2),"r"(a3), "r"(b0),"r"(b1))

#define PACK_BF2(d, lo, hi) \
    asm("cvt.rn.bf16x2.f32 %0, %1, %2;" : "=r"(d) : "f"(hi), "f"(lo))

__device__ __forceinline__ uint32_t smem_u32(const void* p) {
    uint32_t a;
    asm("{ .reg .u64 t; cvta.to.shared.u64 t, %1; cvt.u32.u64 %0, t; }" : "=r"(a) : "l"(p));
    return a;
}

// ---------------------------------------------------------------------------
// FMA-pipe exp2: x <= 0
// ---------------------------------------------------------------------------
__device__ __forceinline__ float exp2p(float x)
{
    x = fmaxf(x, -125.0f);
    const float r = rintf(x);
    const float f = x - r;
    float p = 0.0013333558f;
    p = fmaf(p, f, 0.0096181291f);
    p = fmaf(p, f, 0.0555041087f);
    p = fmaf(p, f, 0.2402265070f);
    p = fmaf(p, f, 0.6931471806f);
    p = fmaf(p, f, 1.0f);
    const int e = (int)r;
    return p * __int_as_float((e + 127) << 23);
}

// ---------------------------------------------------------------------------
// RoPE table
// ---------------------------------------------------------------------------
__global__ void rope_table(float2* __restrict__ tab)
{
    const int idx = blockIdx.x * blockDim.x + threadIdx.x;
    if (idx >= T_*32) return;
    const int t = idx >> 5, i = idx & 31;
    const double inv = pow(10000.0, -(double)(2*i) / 64.0);
    const double ang = (double)t * inv;
    tab[idx] = make_float2((float)cos(ang), (float)sin(ang));
}

// ---------------------------------------------------------------------------
// fp32 -> (bf16 hi, bf16 lo) split
// ---------------------------------------------------------------------------
__device__ __forceinline__
void cvt_body(const float* __restrict__ in, bf16* __restrict__ hi,
              bf16* __restrict__ lo, int i)
{
    const float4 v = ((const float4*)in)[i];
    float f[4] = {v.x, v.y, v.z, v.w};
    bf16 h[4], l[4];
#pragma unroll
    for (int j = 0; j < 4; j++) {
        h[j] = __float2bfloat16(f[j]);
        l[j] = __float2bfloat16(f[j] - __bfloat162float(h[j]));
    }
    ((__nv_bfloat162*)hi)[2*i]   = __nv_bfloat162(h[0], h[1]);
    ((__nv_bfloat162*)hi)[2*i+1] = __nv_bfloat162(h[2], h[3]);
    ((__nv_bfloat162*)lo)[2*i]   = __nv_bfloat162(l[0], l[1]);
    ((__nv_bfloat162*)lo)[2*i+1] = __nv_bfloat162(l[2], l[3]);
}

__global__ __launch_bounds__(256)
void cvt_split(const float* __restrict__ in, bf16* __restrict__ hi,
               bf16* __restrict__ lo, int n4)
{
    const int i = blockIdx.x * blockDim.x + threadIdx.x;
    if (i >= n4) return;
    cvt_body(in, hi, lo, i);
}

// all 4 weights in one launch (z selects)
__global__ __launch_bounds__(256)
void cvt_split_w(const float* __restrict__ w0, const float* __restrict__ w1,
                 const float* __restrict__ w2, const float* __restrict__ w3)
{
    const int i = blockIdx.x * blockDim.x + threadIdx.x;
    if (i >= C_*C_/4) return;
    const int z = blockIdx.z;
    const float* in = (z == 0) ? w0 : (z == 1) ? w1 : (z == 2) ? w2 : w3;
    cvt_body(in, g_w_hi[z], g_w_lo[z], i);
}

// ---------------------------------------------------------------------------
// Pipelined wmma bf16 GEMM (cp.async double buffer) — unchanged.
// ---------------------------------------------------------------------------
#define SLDB 40
#define TILE_BG (128*SLDB*2)
#define STAGE_BG (4*TILE_BG)
#define LDE 132
#define NCH2 (C_/32)

__device__ __forceinline__
void mma_gemm_body(const bf16* __restrict__ Ah, const bf16* __restrict__ Al,
                   const bf16* __restrict__ Wh, const bf16* __restrict__ Wl,
                   const float* __restrict__ bias,
                   bf16* __restrict__ oh, bf16* __restrict__ ol,
                   float* __restrict__ of,
                   const float2* __restrict__ cs, int z)
{
    extern __shared__ char smem[];
    const uint32_t sbase = smem_u32(smem);
    float* sEpi   = (float*)smem;
    float* bias_s = (float*)(smem + 2*STAGE_BG);

    const int tid = threadIdx.x;
    const int wid = tid >> 5;
    const int wm = wid >> 2;
    const int wn = wid & 3;
    const int m0 = blockIdx.y << 7, n0 = blockIdx.x << 7;

    if (tid < 128) bias_s[tid] = bias[n0 + tid];

    const bf16* srcs[4] = {Ah, Al, Wh, Wl};
    const int row0[4] = {m0, m0, n0, n0};

    int jtile[8], jr[8], jv[8];
#pragma unroll
    for (int it = 0; it < 8; it++) {
        const int job = it * 256 + tid;
        jtile[it] = job >> 9;
        const int idx = job & 511;
        jr[it] = idx >> 2;
        jv[it] = idx & 3;
    }

#pragma unroll
    for (int it = 0; it < 8; it++) {
        const bf16* g = srcs[jtile[it]] + (size_t)(row0[jtile[it]] + jr[it]) * C_ + jv[it]*8;
        CP_ASYNC16(sbase + jtile[it]*TILE_BG + jr[it]*80 + jv[it]*16, g);
    }
    CP_COMMIT();

    wmma::fragment<wmma::accumulator, 16, 16, 16, float> acc[4][2];
#pragma unroll
    for (int mt = 0; mt < 4; mt++)
#pragma unroll
        for (int nt = 0; nt < 2; nt++) wmma::fill_fragment(acc[mt][nt], 0.f);

    for (int kc = 0; kc < NCH2; kc++) {
        const int s = kc & 1;
        if (kc + 1 < NCH2) {
            const uint32_t db = sbase + (s^1)*STAGE_BG;
            const int koff = (kc+1)*32;
#pragma unroll
            for (int it = 0; it < 8; it++) {
                const bf16* g = srcs[jtile[it]] + (size_t)(row0[jtile[it]] + jr[it]) * C_ + koff + jv[it]*8;
                CP_ASYNC16(db + jtile[it]*TILE_BG + jr[it]*80 + jv[it]*16, g);
            }
            CP_COMMIT();
            CP_WAIT1();
        } else {
            CP_WAIT0();
        }
        __syncthreads();

        bf16* sT = (bf16*)(smem + s*STAGE_BG);
#pragma unroll
        for (int ks = 0; ks < 2; ks++) {
            wmma::fragment<wmma::matrix_b, 16, 16, 16, bf16, wmma::col_major> fwh[2], fwl[2];
#pragma unroll
            for (int nt = 0; nt < 2; nt++) {
                wmma::load_matrix_sync(fwh[nt], sT + 2*(128*SLDB) + (wn*32 + nt*16)*SLDB + ks*16, SLDB);
                wmma::load_matrix_sync(fwl[nt], sT + 3*(128*SLDB) + (wn*32 + nt*16)*SLDB + ks*16, SLDB);
            }
#pragma unroll
            for (int mt = 0; mt < 4; mt++) {
                wmma::fragment<wmma::matrix_a, 16, 16, 16, bf16, wmma::row_major> fah, fal;
                wmma::load_matrix_sync(fah, sT + 0*(128*SLDB) + (wm*64 + mt*16)*SLDB + ks*16, SLDB);
                wmma::load_matrix_sync(fal, sT + 1*(128*SLDB) + (wm*64 + mt*16)*SLDB + ks*16, SLDB);
#pragma unroll
                for (int nt = 0; nt < 2; nt++) {
                    wmma::mma_sync(acc[mt][nt], fah, fwh[nt], acc[mt][nt]);
                    wmma::mma_sync(acc[mt][nt], fah, fwl[nt], acc[mt][nt]);
                    wmma::mma_sync(acc[mt][nt], fal, fwh[nt], acc[mt][nt]);
                }
            }
        }
        __syncthreads();
    }

#pragma unroll
    for (int mt = 0; mt < 4; mt++)
#pragma unroll
        for (int nt = 0; nt < 2; nt++)
            wmma::store_matrix_sync(sEpi + (wm*64 + mt*16)*LDE + wn*32 + nt*16,
                                    acc[mt][nt], LDE, wmma::mem_row_major);
    __syncthreads();

    const int tx = tid & 15, ty = tid >> 4;
    const int n_base = n0 + 8*tx;
    const float4 b0 = *(const float4*)&bias_s[8*tx];
    const float4 b1 = *(const float4*)&bias_s[8*tx + 4];
    const float bb[8] = {b0.x, b0.y, b0.z, b0.w, b1.x, b1.y, b1.z, b1.w};

#pragma unroll
    for (int r = 0; r < 8; r++) {
        const int lrow = 8*ty + r;
        const int m = m0 + lrow;
        float o[8];
#pragma unroll
        for (int j = 0; j < 8; j++) o[j] = sEpi[lrow*LDE + 8*tx + j] + bb[j];

        if (z < 2) {
            const int t = m & (T_-1);
#pragma unroll
            for (int p = 0; p < 4; p++) {
                const int i = ((n_base + 2*p) & 63) >> 1;
                const float2 csv = cs[t*32 + i];
                const float x1 = o[2*p], x2 = o[2*p+1];
                o[2*p]   = x1*csv.x - x2*csv.y;
                o[2*p+1] = x1*csv.y + x2*csv.x;
            }
        }
        if (z == 0) {
#pragma unroll
            for (int j = 0; j < 8; j++) o[j] *= QSCALE;
        }

        if (z <= 2) {
            bf16 h8[8], l8[8];
#pragma unroll
            for (int j = 0; j < 8; j++) {
                h8[j] = __float2bfloat16(o[j]);
                l8[j] = __float2bfloat16(o[j] - __bfloat162float(h8[j]));
            }
            const int b = m >> 11, t = m & (T_-1);
            const int h = n_base >> 6, d = n_base & 63;
            const size_t doff = (((size_t)(b*H_ + h) * T_) + t) * D_ + d;
            *(uint4*)(oh + doff) = *(uint4*)h8;
            *(uint4*)(ol + doff) = *(uint4*)l8;
        } else {
            float* dst = of + (size_t)m * C_ + n_base;
            *(float4*)dst = make_float4(o[0], o[1], o[2], o[3]);
            *(float4*)(dst + 4) = make_float4(o[4], o[5], o[6], o[7]);
        }
    }
}

__global__ __launch_bounds__(256, 2)
void qkv_mma(const bf16* __restrict__ xh, const bf16* __restrict__ xl,
             const float* __restrict__ bq, const float* __restrict__ bk,
             const float* __restrict__ bv, const float2* __restrict__ cs)
{
    const int z = blockIdx.z;
    const float* bias = (z == 0) ? bq : (z == 1) ? bk : bv;
    bf16* oh = (z == 0) ? g_qh : (z == 1) ? g_kh : g_vh;
    bf16* ol = (z == 0) ? g_ql : (z == 1) ? g_kl : g_vl;
    mma_gemm_body(xh, xl, g_w_hi[z], g_w_lo[z], bias, oh, ol, nullptr, cs, z);
}

__global__ __launch_bounds__(256, 2)
void out_mma(const bf16* __restrict__ ah, const bf16* __restrict__ al,
             const float* __restrict__ bias, float* __restrict__ out)
{
    mma_gemm_body(ah, al, g_w_hi[3], g_w_lo[3], bias, nullptr, nullptr, out, nullptr, 3);
}

// ---------------------------------------------------------------------------
// Register-resident FA2 attention, triple-buffered cp.async K/V pipeline.
// 128 threads = 4 warps; CTA tile 64q; one __syncthreads per k-iteration,
// distance-2 prefetch (2 iterations of load slack).
// ---------------------------------------------------------------------------
#define ROWB 144
#define KVBUF 36864
#define ATTN_SMEM (3*KVBUF)      // 110592

__global__ __launch_bounds__(128, 2)
void attn_fa2(const bf16* __restrict__ qh, const bf16* __restrict__ ql,
              const bf16* __restrict__ kh, const bf16* __restrict__ kl,
              const bf16* __restrict__ vh, const bf16* __restrict__ vl,
              bf16* __restrict__ ah_out, bf16* __restrict__ al_out)
{
    extern __shared__ char smem[];
    const uint32_t sbase = smem_u32(smem);

    const int tid  = threadIdx.x;
    const int w    = tid >> 5;
    const int lane = tid & 31;
    const int tig  = lane & 3;
    const int grp  = lane >> 2;
    const int bh = blockIdx.y;
    const int b = bh >> 4, h = bh & (H_-1);
    const int qt = gridDim.x - 1 - blockIdx.x;
    const int q0 = qt << 6;

    const size_t hb = (size_t)bh * T_ * D_;
    const bf16* qhb = qh + hb; const bf16* qlb = ql + hb;
    const bf16* khb = kh + hb; const bf16* klb = kl + hb;
    const bf16* vhb = vh + hb; const bf16* vlb = vl + hb;

    int jtile[16], jr[16], jv[16];
#pragma unroll
    for (int it = 0; it < 16; it++) {
        const int job = it * 128 + tid;
        jtile[it] = job >> 9;
        jr[it] = (job >> 3) & 63;
        jv[it] = job & 7;
    }
    const bf16* ksrc[4] = {khb, klb, vhb, vlb};

    // prologue: prefetch kt=0 (buf 0) and kt=1 (buf 1)
#pragma unroll
    for (int it = 0; it < 16; it++)
        CP_ASYNC16(sbase + jtile[it]*9216 + jr[it]*ROWB + jv[it]*16,
                   ksrc[jtile[it]] + (size_t)jr[it]*D_ + jv[it]*8);
    CP_COMMIT();
    if (qt >= 1) {
#pragma unroll
        for (int it = 0; it < 16; it++)
            CP_ASYNC16(sbase + KVBUF + jtile[it]*9216 + jr[it]*ROWB + jv[it]*16,
                       ksrc[jtile[it]] + (size_t)(64*D_) + (size_t)jr[it]*D_ + jv[it]*8);
        CP_COMMIT();
    }

    // Q fragments from gmem, kept for whole kernel
    uint32_t qfh[4][4], qfl[4][4];
    {
        const int r0 = q0 + w*16 + grp;
#pragma unroll
        for (int ks = 0; ks < 4; ks++) {
            const int c = ks*16 + tig*2;
            qfh[ks][0] = *(const uint32_t*)(qhb + (size_t)r0*D_ + c);
            qfh[ks][1] = *(const uint32_t*)(qhb + (size_t)(r0+8)*D_ + c);
            qfh[ks][2] = *(const uint32_t*)(qhb + (size_t)r0*D_ + c + 8);
            qfh[ks][3] = *(const uint32_t*)(qhb + (size_t)(r0+8)*D_ + c + 8);
            qfl[ks][0] = *(const uint32_t*)(qlb + (size_t)r0*D_ + c);
            qfl[ks][1] = *(const uint32_t*)(qlb + (size_t)(r0+8)*D_ + c);
            qfl[ks][2] = *(const uint32_t*)(qlb + (size_t)r0*D_ + c + 8);
            qfl[ks][3] = *(const uint32_t*)(qlb + (size_t)(r0+8)*D_ + c + 8);
        }
    }

    float o[8][4];
#pragma unroll
    for (int t = 0; t < 8; t++)
#pragma unroll
        for (int e = 0; e < 4; e++) o[t][e] = 0.f;

    float m0 = -1e30f, m1 = -1e30f, l0 = 0.f, l1 = 0.f;

    const uint32_t koffA = (uint32_t)((lane & 7) * ROWB + (lane >> 3) * 16);
    const uint32_t voffA = (uint32_t)(((lane >> 3) * 8 + (lane & 7)) * ROWB);

    for (int kt = 0; kt <= qt; kt++) {
        const uint32_t kb = sbase + (kt % 3)*KVBUF;
        const uint32_t lb = kb + 9216;
        const uint32_t vb = kb + 18432;
        const uint32_t wb = kb + 27648;

        if (kt < qt) { CP_WAIT1(); } else { CP_WAIT0(); }
        __syncthreads();

        if (kt + 2 <= qt) {
            const uint32_t db = sbase + ((kt+2) % 3)*KVBUF;
            const size_t soff = (size_t)(kt+2)*64*D_;
#pragma unroll
            for (int it = 0; it < 16; it++)
                CP_ASYNC16(db + jtile[it]*9216 + jr[it]*ROWB + jv[it]*16,
                           ksrc[jtile[it]] + soff + (size_t)jr[it]*D_ + jv[it]*8);
            CP_COMMIT();
        }

        // ---- QK^T ----
        float s[8][4];
#pragma unroll
        for (int t = 0; t < 8; t++)
#pragma unroll
            for (int e = 0; e < 4; e++) s[t][e] = 0.f;

#pragma unroll
        for (int t = 0; t < 8; t++) {
#pragma unroll
            for (int kk2 = 0; kk2 < 2; kk2++) {
                uint32_t h0,h1,h2,h3, x0,x1,x2,x3;
                const uint32_t ka = kb + (uint32_t)(t*8*ROWB) + (uint32_t)(kk2*64) + koffA;
                const uint32_t la = lb + (uint32_t)(t*8*ROWB) + (uint32_t)(kk2*64) + koffA;
                LDSM_X4(h0,h1,h2,h3, ka);
                LDSM_X4(x0,x1,x2,x3, la);
                const int ks0 = 2*kk2, ks1 = 2*kk2 + 1;
                MMA_BF16(s[t], qfh[ks0][0],qfh[ks0][1],qfh[ks0][2],qfh[ks0][3], h0,h1);
                MMA_BF16(s[t], qfh[ks0][0],qfh[ks0][1],qfh[ks0][2],qfh[ks0][3], x0,x1);
                MMA_BF16(s[t], qfl[ks0][0],qfl[ks0][1],qfl[ks0][2],qfl[ks0][3], h0,h1);
                MMA_BF16(s[t], qfh[ks1][0],qfh[ks1][1],qfh[ks1][2],qfh[ks1][3], h2,h3);
                MMA_BF16(s[t], qfh[ks1][0],qfh[ks1][1],qfh[ks1][2],qfh[ks1][3], x2,x3);
                MMA_BF16(s[t], qfl[ks1][0],qfl[ks1][1],qfl[ks1][2],qfl[ks1][3], h2,h3);
            }
        }

        // ---- mask (diag tile only) ----
        if (kt == qt) {
            const int i0 = w*16 + grp, i1 = i0 + 8;
#pragma unroll
            for (int t = 0; t < 8; t++) {
                const int j = t*8 + tig*2;
                if (j   > i0) s[t][0] = -1e30f;
                if (j+1 > i0) s[t][1] = -1e30f;
                if (j   > i1) s[t][2] = -1e30f;
                if (j+1 > i1) s[t][3] = -1e30f;
            }
        }

        // ---- online softmax in registers ----
        float mx0 = -1e30f, mx1 = -1e30f;
#pragma unroll
        for (int t = 0; t < 8; t++) {
            mx0 = fmaxf(mx0, fmaxf(s[t][0], s[t][1]));
            mx1 = fmaxf(mx1, fmaxf(s[t][2], s[t][3]));
        }
        mx0 = fmaxf(mx0, __shfl_xor_sync(0xffffffffu, mx0, 1));
        mx0 = fmaxf(mx0, __shfl_xor_sync(0xffffffffu, mx0, 2));
        mx1 = fmaxf(mx1, __shfl_xor_sync(0xffffffffu, mx1, 1));
        mx1 = fmaxf(mx1, __shfl_xor_sync(0xffffffffu, mx1, 2));

        const float mn0 = fmaxf(m0, mx0), mn1 = fmaxf(m1, mx1);
        const float al0 = exp2p(m0 - mn0), al1 = exp2p(m1 - mn1);
        m0 = mn0; m1 = mn1;

        uint32_t pah0[8], pah1[8], pal0[8], pal1[8];
        float ps0 = 0.f, ps1 = 0.f;
#pragma unroll
        for (int t = 0; t < 8; t++) {
            const float p00 = exp2p(s[t][0] - mn0);
            const float p01 = exp2p(s[t][1] - mn0);
            const float p10 = exp2p(s[t][2] - mn1);
            const float p11 = exp2p(s[t][3] - mn1);
            ps0 += p00 + p01; ps1 += p10 + p11;
            PACK_BF2(pah0[t], p00, p01);
            PACK_BF2(pah1[t], p10, p11);
            const float r00 = p00 - __int_as_float(pah0[t] << 16);
            const float r01 = p01 - __int_as_float(pah0[t] & 0xffff0000u);
            const float r10 = p10 - __int_as_float(pah1[t] << 16);
            const float r11 = p11 - __int_as_float(pah1[t] & 0xffff0000u);
            PACK_BF2(pal0[t], r00, r01);
            PACK_BF2(pal1[t], r10, r11);
        }
        ps0 += __shfl_xor_sync(0xffffffffu, ps0, 1);
        ps0 += __shfl_xor_sync(0xffffffffu, ps0, 2);
        ps1 += __shfl_xor_sync(0xffffffffu, ps1, 1);
        ps1 += __shfl_xor_sync(0xffffffffu, ps1, 2);
        l0 = l0 * al0 + ps0;
        l1 = l1 * al1 + ps1;

#pragma unroll
        for (int t = 0; t < 8; t++) {
            o[t][0] *= al0; o[t][1] *= al0;
            o[t][2] *= al1; o[t][3] *= al1;
        }

        // ---- PV ----
#pragma unroll
        for (int t = 0; t < 8; t++) {
#pragma unroll
            for (int kk2 = 0; kk2 < 2; kk2++) {
                uint32_t h0,h1,h2,h3, x0,x1,x2,x3;
                const uint32_t va = vb + (uint32_t)(kk2*32*ROWB) + (uint32_t)(t*16) + voffA;
                const uint32_t wa = wb + (uint32_t)(kk2*32*ROWB) + (uint32_t)(t*16) + voffA;
                LDSM_X4T(h0,h1,h2,h3, va);
                LDSM_X4T(x0,x1,x2,x3, wa);
                const int ks0 = 2*kk2, ks1 = 2*kk2 + 1;
                MMA_BF16(o[t], pah0[2*ks0],pah1[2*ks0],pah0[2*ks0+1],pah1[2*ks0+1], h0,h1);
                MMA_BF16(o[t], pah0[2*ks0],pah1[2*ks0],pah0[2*ks0+1],pah1[2*ks0+1], x0,x1);
                MMA_BF16(o[t], pal0[2*ks0],pal1[2*ks0],pal0[2*ks0+1],pal1[2*ks0+1], h0,h1);
                MMA_BF16(o[t], pah0[2*ks1],pah1[2*ks1],pah0[2*ks1+1],pah1[2*ks1+1], h2,h3);
                MMA_BF16(o[t], pah0[2*ks1],pah1[2*ks1],pah0[2*ks1+1],pah1[2*ks1+1], x2,x3);
                MMA_BF16(o[t], pal0[2*ks1],pal1[2*ks1],pal0[2*ks1+1],pal1[2*ks1+1], h2,h3);
            }
        }
    }

    // ---- epilogue ----
    const float il0 = 1.f / l0, il1 = 1.f / l1;
    const int r0g = q0 + w*16 + grp;
    const size_t base0 = ((size_t)(b*T_ + r0g)) * C_ + h*D_ + tig*2;
    const size_t base1 = ((size_t)(b*T_ + r0g + 8)) * C_ + h*D_ + tig*2;
#pragma unroll
    for (int t = 0; t < 8; t++) {
        const float v00 = o[t][0]*il0, v01 = o[t][1]*il0;
        const float v10 = o[t][2]*il1, v11 = o[t][3]*il1;
        uint32_t h0, h1, lo0, lo1;
        PACK_BF2(h0, v00, v01);
        PACK_BF2(h1, v10, v11);
        const float q00 = v00 - __int_as_float(h0 << 16);
        const float q01 = v01 - __int_as_float(h0 & 0xffff0000u);
        const float q10 = v10 - __int_as_float(h1 << 16);
        const float q11 = v11 - __int_as_float(h1 & 0xffff0000u);
        PACK_BF2(lo0, q00, q01);
        PACK_BF2(lo1, q10, q11);
        *(uint32_t*)(ah_out + base0 + t*8) = h0;
        *(uint32_t*)(ah_out + base1 + t*8) = h1;
        *(uint32_t*)(al_out + base0 + t*8) = lo0;
        *(uint32_t*)(al_out + base1 + t*8) = lo1;
    }
}

// ---------------------------------------------------------------------------
extern "C" void kernel_launch(void* const* d_in, const int* in_sizes, int n_in,
                              void* d_out, int out_size)
{
    const float* x  = (const float*)d_in[0];
    const float* Wq = (const float*)d_in[1];
    const float* bq = (const float*)d_in[2];
    const float* Wk = (const float*)d_in[3];
    const float* bk = (const float*)d_in[4];
    const float* Wv = (const float*)d_in[5];
    const float* bv = (const float*)d_in[6];
    const float* Wo = (const float*)d_in[7];
    const float* bo = (const float*)d_in[8];
    float* out = (float*)d_out;

    float2* csp;
    bf16 *xh, *xl, *ah, *al;
    bf16 *qhp, *qlp, *khp, *klp, *vhp, *vlp;
    cudaGetSymbolAddress((void**)&csp,  g_cs);
    cudaGetSymbolAddress((void**)&xh,   g_x_hi);
    cudaGetSymbolAddress((void**)&xl,   g_x_lo);
    cudaGetSymbolAddress((void**)&ah,   g_a_hi);
    cudaGetSymbolAddress((void**)&al,   g_a_lo);
    cudaGetSymbolAddress((void**)&qhp,  g_qh);
    cudaGetSymbolAddress((void**)&qlp,  g_ql);
    cudaGetSymbolAddress((void**)&khp,  g_kh);
    cudaGetSymbolAddress((void**)&klp,  g_kl);
    cudaGetSymbolAddress((void**)&vhp,  g_vh);
    cudaGetSymbolAddress((void**)&vlp,  g_vl);

    rope_table<<<(T_*32)/256, 256>>>(csp);

    cvt_split<<<(M_*C_/4)/256, 256>>>(x, xh, xl, M_*C_/4);
    cvt_split_w<<<dim3((C_*C_/4)/256, 1, 4), 256>>>(Wq, Wk, Wv, Wo);

    const size_t gsmem = 2*STAGE_BG + 512;
    cudaFuncSetAttribute(qkv_mma, cudaFuncAttributeMaxDynamicSharedMemorySize, (int)gsmem);
    cudaFuncSetAttribute(out_mma, cudaFuncAttributeMaxDynamicSharedMemorySize, (int)gsmem);
    cudaFuncSetAttribute(attn_fa2, cudaFuncAttributeMaxDynamicSharedMemorySize, ATTN_SMEM);

    qkv_mma<<<dim3(C_/128, M_/128, 3), 256, gsmem>>>(xh, xl, bq, bk, bv, csp);

    attn_fa2<<<dim3(T_/64, B_*H_), 128, ATTN_SMEM>>>(qhp, qlp, khp, klp, vhp, vlp, ah, al);

    out_mma<<<dim3(C_/128, M_/128), 256, gsmem>>>(ah, al, bo, out);
}

// round 14
// speedup vs baseline: 3.2702x; 1.2795x over previous
#include <cuda_runtime.h>
#include <cuda_bf16.h>
#include <cuda_fp16.h>
#include <mma.h>
#include <math.h>
#include <stdint.h>

using namespace nvcuda;

#define B_ 2
#define T_ 2048
#define C_ 1024
#define H_ 16
#define D_ 64
#define M_ (B_*T_)
#define QSCALE 0.1803368801111437f  // (1/sqrt(64)) * log2(e)

typedef __nv_bfloat16 bf16;
typedef __half hf;

// ---------------------------------------------------------------------------
// Scratch (allocation-free contract: __device__ globals)
// ---------------------------------------------------------------------------
__device__ float2 g_cs[T_*32];
__device__ hf g_xh[M_*C_], g_xl[M_*C_];          // x split (fp16 2-term)
__device__ hf g_ah[M_*C_], g_al[M_*C_];          // attention out split
__device__ hf g_wh4[4][C_*C_];                    // weights single fp16
__device__ bf16 g_qh[B_*H_*T_*D_], g_ql[B_*H_*T_*D_];  // attention operands (bf16 3-term)
__device__ bf16 g_kh[B_*H_*T_*D_], g_kl[B_*H_*T_*D_];
__device__ bf16 g_vh[B_*H_*T_*D_], g_vl[B_*H_*T_*D_];

// ---------------------------------------------------------------------------
// cp.async / ldmatrix / mma helpers
// ---------------------------------------------------------------------------
#define CP_ASYNC16(dst, src) \
    asm volatile("cp.async.cg.shared.global [%0], [%1], 16;" :: "r"(dst), "l"(src) : "memory")
#define CP_COMMIT() asm volatile("cp.async.commit_group;" ::: "memory")
#define CP_WAIT0()  asm volatile("cp.async.wait_group 0;" ::: "memory")
#define CP_WAIT1()  asm volatile("cp.async.wait_group 1;" ::: "memory")

#define LDSM_X4(r0,r1,r2,r3, a) \
    asm volatile("ldmatrix.sync.aligned.m8n8.x4.shared.b16 {%0,%1,%2,%3}, [%4];" \
        : "=r"(r0),"=r"(r1),"=r"(r2),"=r"(r3) : "r"(a))
#define LDSM_X4T(r0,r1,r2,r3, a) \
    asm volatile("ldmatrix.sync.aligned.m8n8.x4.trans.shared.b16 {%0,%1,%2,%3}, [%4];" \
        : "=r"(r0),"=r"(r1),"=r"(r2),"=r"(r3) : "r"(a))

#define MMA_BF16(d, a0,a1,a2,a3, b0,b1) \
    asm volatile("mma.sync.aligned.m16n8k16.row.col.f32.bf16.bf16.f32 " \
        "{%0,%1,%2,%3},{%4,%5,%6,%7},{%8,%9},{%0,%1,%2,%3};" \
        : "+f"((d)[0]),"+f"((d)[1]),"+f"((d)[2]),"+f"((d)[3]) \
        : "r"(a0),"r"(a1),"r"(a2),"r"(a3), "r"(b0),"r"(b1))

#define PACK_BF2(d, lo, hi) \
    asm("cvt.rn.bf16x2.f32 %0, %1, %2;" : "=r"(d) : "f"(hi), "f"(lo))

__device__ __forceinline__ uint32_t smem_u32(const void* p) {
    uint32_t a;
    asm("{ .reg .u64 t; cvta.to.shared.u64 t, %1; cvt.u32.u64 %0, t; }" : "=r"(a) : "l"(p));
    return a;
}

// ---------------------------------------------------------------------------
// FMA-pipe exp2: x <= 0
// ---------------------------------------------------------------------------
__device__ __forceinline__ float exp2p(float x)
{
    x = fmaxf(x, -125.0f);
    const float r = rintf(x);
    const float f = x - r;
    float p = 0.0013333558f;
    p = fmaf(p, f, 0.0096181291f);
    p = fmaf(p, f, 0.0555041087f);
    p = fmaf(p, f, 0.2402265070f);
    p = fmaf(p, f, 0.6931471806f);
    p = fmaf(p, f, 1.0f);
    const int e = (int)r;
    return p * __int_as_float((e + 127) << 23);
}

// ---------------------------------------------------------------------------
// RoPE table
// ---------------------------------------------------------------------------
__global__ void rope_table(float2* __restrict__ tab)
{
    const int idx = blockIdx.x * blockDim.x + threadIdx.x;
    if (idx >= T_*32) return;
    const int t = idx >> 5, i = idx & 31;
    const double inv = pow(10000.0, -(double)(2*i) / 64.0);
    const double ang = (double)t * inv;
    tab[idx] = make_float2((float)cos(ang), (float)sin(ang));
}

// ---------------------------------------------------------------------------
// fp32 -> (fp16 hi, fp16 lo) split for activations
// ---------------------------------------------------------------------------
__global__ __launch_bounds__(256)
void cvt_split_h(const float* __restrict__ in, hf* __restrict__ hi,
                 hf* __restrict__ lo, int n4)
{
    const int i = blockIdx.x * blockDim.x + threadIdx.x;
    if (i >= n4) return;
    const float4 v = ((const float4*)in)[i];
    const float f[4] = {v.x, v.y, v.z, v.w};
    hf h[4], l[4];
#pragma unroll
    for (int j = 0; j < 4; j++) {
        h[j] = __float2half_rn(f[j]);
        l[j] = __float2half_rn(f[j] - __half2float(h[j]));
    }
    ((__half2*)hi)[2*i]   = __half2(h[0], h[1]);
    ((__half2*)hi)[2*i+1] = __half2(h[2], h[3]);
    ((__half2*)lo)[2*i]   = __half2(l[0], l[1]);
    ((__half2*)lo)[2*i+1] = __half2(l[2], l[3]);
}

// all 4 weights -> single fp16, one launch
__global__ __launch_bounds__(256)
void cvt_w_h(const float* __restrict__ w0, const float* __restrict__ w1,
             const float* __restrict__ w2, const float* __restrict__ w3)
{
    const int i = blockIdx.x * blockDim.x + threadIdx.x;
    if (i >= C_*C_/4) return;
    const int z = blockIdx.z;
    const float* in = (z == 0) ? w0 : (z == 1) ? w1 : (z == 2) ? w2 : w3;
    const float4 v = ((const float4*)in)[i];
    hf* dst = g_wh4[z];
    ((__half2*)dst)[2*i]   = __floats2half2_rn(v.x, v.y);
    ((__half2*)dst)[2*i+1] = __floats2half2_rn(v.z, v.w);
}

// ---------------------------------------------------------------------------
// Pipelined wmma fp16 GEMM (cp.async double buffer), 2-term split:
// D = Ah*Wh + Al*Wh, fp32 accum. 3 smem tiles per stage.
// z=0: q (rope+qscale, bf16-split->scatter), z=1: k, z=2: v, z=3: fp32 out.
// ---------------------------------------------------------------------------
#define SLDB 40                       // fp16 leading dim (80B rows)
#define TILE_HB (128*SLDB*2)          // 10240 B per tile
#define STAGE_HB (3*TILE_HB)          // 30720 B per stage
#define LDE 132
#define NCH2 (C_/32)

__device__ __forceinline__
void mma_gemm_body(const hf* __restrict__ Ah, const hf* __restrict__ Al,
                   const hf* __restrict__ Wh,
                   const float* __restrict__ bias,
                   bf16* __restrict__ oh, bf16* __restrict__ ol,
                   float* __restrict__ of,
                   const float2* __restrict__ cs, int z)
{
    extern __shared__ char smem[];
    const uint32_t sbase = smem_u32(smem);
    float* sEpi   = (float*)smem;                    // 128*132*4 = 67584 B
    float* bias_s = (float*)(smem + 67584);

    const int tid = threadIdx.x;
    const int wid = tid >> 5;
    const int wm = wid >> 2;
    const int wn = wid & 3;
    const int m0 = blockIdx.y << 7, n0 = blockIdx.x << 7;

    if (tid < 128) bias_s[tid] = bias[n0 + tid];

    const hf* srcs[3] = {Ah, Al, Wh};
    const int row0[3] = {m0, m0, n0};

    // 1536 16B-vec jobs per chunk, 6 per thread
    int jtile[6], jr[6], jv[6];
#pragma unroll
    for (int it = 0; it < 6; it++) {
        const int job = it * 256 + tid;
        jtile[it] = job >> 9;
        const int idx = job & 511;
        jr[it] = idx >> 2;
        jv[it] = idx & 3;
    }

#pragma unroll
    for (int it = 0; it < 6; it++) {
        const hf* g = srcs[jtile[it]] + (size_t)(row0[jtile[it]] + jr[it]) * C_ + jv[it]*8;
        CP_ASYNC16(sbase + jtile[it]*TILE_HB + jr[it]*80 + jv[it]*16, g);
    }
    CP_COMMIT();

    wmma::fragment<wmma::accumulator, 16, 16, 16, float> acc[4][2];
#pragma unroll
    for (int mt = 0; mt < 4; mt++)
#pragma unroll
        for (int nt = 0; nt < 2; nt++) wmma::fill_fragment(acc[mt][nt], 0.f);

    for (int kc = 0; kc < NCH2; kc++) {
        const int s = kc & 1;
        if (kc + 1 < NCH2) {
            const uint32_t db = sbase + (s^1)*STAGE_HB;
            const int koff = (kc+1)*32;
#pragma unroll
            for (int it = 0; it < 6; it++) {
                const hf* g = srcs[jtile[it]] + (size_t)(row0[jtile[it]] + jr[it]) * C_ + koff + jv[it]*8;
                CP_ASYNC16(db + jtile[it]*TILE_HB + jr[it]*80 + jv[it]*16, g);
            }
            CP_COMMIT();
            CP_WAIT1();
        } else {
            CP_WAIT0();
        }
        __syncthreads();

        hf* sT = (hf*)(smem + s*STAGE_HB);
#pragma unroll
        for (int ks = 0; ks < 2; ks++) {
            wmma::fragment<wmma::matrix_b, 16, 16, 16, hf, wmma::col_major> fwh[2];
#pragma unroll
            for (int nt = 0; nt < 2; nt++)
                wmma::load_matrix_sync(fwh[nt], sT + 2*(128*SLDB) + (wn*32 + nt*16)*SLDB + ks*16, SLDB);
#pragma unroll
            for (int mt = 0; mt < 4; mt++) {
                wmma::fragment<wmma::matrix_a, 16, 16, 16, hf, wmma::row_major> fah, fal;
                wmma::load_matrix_sync(fah, sT + 0*(128*SLDB) + (wm*64 + mt*16)*SLDB + ks*16, SLDB);
                wmma::load_matrix_sync(fal, sT + 1*(128*SLDB) + (wm*64 + mt*16)*SLDB + ks*16, SLDB);
#pragma unroll
                for (int nt = 0; nt < 2; nt++) {
                    wmma::mma_sync(acc[mt][nt], fah, fwh[nt], acc[mt][nt]);
                    wmma::mma_sync(acc[mt][nt], fal, fwh[nt], acc[mt][nt]);
                }
            }
        }
        __syncthreads();
    }

#pragma unroll
    for (int mt = 0; mt < 4; mt++)
#pragma unroll
        for (int nt = 0; nt < 2; nt++)
            wmma::store_matrix_sync(sEpi + (wm*64 + mt*16)*LDE + wn*32 + nt*16,
                                    acc[mt][nt], LDE, wmma::mem_row_major);
    __syncthreads();

    const int tx = tid & 15, ty = tid >> 4;
    const int n_base = n0 + 8*tx;
    const float4 b0 = *(const float4*)&bias_s[8*tx];
    const float4 b1 = *(const float4*)&bias_s[8*tx + 4];
    const float bb[8] = {b0.x, b0.y, b0.z, b0.w, b1.x, b1.y, b1.z, b1.w};

#pragma unroll
    for (int r = 0; r < 8; r++) {
        const int lrow = 8*ty + r;
        const int m = m0 + lrow;
        float o[8];
#pragma unroll
        for (int j = 0; j < 8; j++) o[j] = sEpi[lrow*LDE + 8*tx + j] + bb[j];

        if (z < 2) {  // RoPE
            const int t = m & (T_-1);
#pragma unroll
            for (int p = 0; p < 4; p++) {
                const int i = ((n_base + 2*p) & 63) >> 1;
                const float2 csv = cs[t*32 + i];
                const float x1 = o[2*p], x2 = o[2*p+1];
                o[2*p]   = x1*csv.x - x2*csv.y;
                o[2*p+1] = x1*csv.y + x2*csv.x;
            }
        }
        if (z == 0) {
#pragma unroll
            for (int j = 0; j < 8; j++) o[j] *= QSCALE;
        }

        if (z <= 2) {  // bf16 split -> scatter [B,H,T,D] (attention operands)
            bf16 h8[8], l8[8];
#pragma unroll
            for (int j = 0; j < 8; j++) {
                h8[j] = __float2bfloat16(o[j]);
                l8[j] = __float2bfloat16(o[j] - __bfloat162float(h8[j]));
            }
            const int b = m >> 11, t = m & (T_-1);
            const int h = n_base >> 6, d = n_base & 63;
            const size_t doff = (((size_t)(b*H_ + h) * T_) + t) * D_ + d;
            *(uint4*)(oh + doff) = *(uint4*)h8;
            *(uint4*)(ol + doff) = *(uint4*)l8;
        } else {
            float* dst = of + (size_t)m * C_ + n_base;
            *(float4*)dst = make_float4(o[0], o[1], o[2], o[3]);
            *(float4*)(dst + 4) = make_float4(o[4], o[5], o[6], o[7]);
        }
    }
}

__global__ __launch_bounds__(256, 2)
void qkv_mma(const hf* __restrict__ xh, const hf* __restrict__ xl,
             const float* __restrict__ bq, const float* __restrict__ bk,
             const float* __restrict__ bv, const float2* __restrict__ cs)
{
    const int z = blockIdx.z;
    const float* bias = (z == 0) ? bq : (z == 1) ? bk : bv;
    bf16* oh = (z == 0) ? g_qh : (z == 1) ? g_kh : g_vh;
    bf16* ol = (z == 0) ? g_ql : (z == 1) ? g_kl : g_vl;
    mma_gemm_body(xh, xl, g_wh4[z], bias, oh, ol, nullptr, cs, z);
}

__global__ __launch_bounds__(256, 2)
void out_mma(const hf* __restrict__ ah, const hf* __restrict__ al,
             const float* __restrict__ bias, float* __restrict__ out)
{
    mma_gemm_body(ah, al, g_wh4[3], bias, nullptr, nullptr, out, nullptr, 3);
}

// ---------------------------------------------------------------------------
// Register-resident FA2 attention (bf16 3-term, unchanged math),
// triple-buffered cp.async K/V pipeline. Output split now fp16 hi/lo.
// ---------------------------------------------------------------------------
#define ROWB 144
#define KVBUF 36864
#define ATTN_SMEM (3*KVBUF)

__global__ __launch_bounds__(128, 2)
void attn_fa2(const bf16* __restrict__ qh, const bf16* __restrict__ ql,
              const bf16* __restrict__ kh, const bf16* __restrict__ kl,
              const bf16* __restrict__ vh, const bf16* __restrict__ vl,
              hf* __restrict__ ah_out, hf* __restrict__ al_out)
{
    extern __shared__ char smem[];
    const uint32_t sbase = smem_u32(smem);

    const int tid  = threadIdx.x;
    const int w    = tid >> 5;
    const int lane = tid & 31;
    const int tig  = lane & 3;
    const int grp  = lane >> 2;
    const int bh = blockIdx.y;
    const int b = bh >> 4, h = bh & (H_-1);
    const int qt = gridDim.x - 1 - blockIdx.x;
    const int q0 = qt << 6;

    const size_t hb = (size_t)bh * T_ * D_;
    const bf16* qhb = qh + hb; const bf16* qlb = ql + hb;
    const bf16* khb = kh + hb; const bf16* klb = kl + hb;
    const bf16* vhb = vh + hb; const bf16* vlb = vl + hb;

    int jtile[16], jr[16], jv[16];
#pragma unroll
    for (int it = 0; it < 16; it++) {
        const int job = it * 128 + tid;
        jtile[it] = job >> 9;
        jr[it] = (job >> 3) & 63;
        jv[it] = job & 7;
    }
    const bf16* ksrc[4] = {khb, klb, vhb, vlb};

#pragma unroll
    for (int it = 0; it < 16; it++)
        CP_ASYNC16(sbase + jtile[it]*9216 + jr[it]*ROWB + jv[it]*16,
                   ksrc[jtile[it]] + (size_t)jr[it]*D_ + jv[it]*8);
    CP_COMMIT();
    if (qt >= 1) {
#pragma unroll
        for (int it = 0; it < 16; it++)
            CP_ASYNC16(sbase + KVBUF + jtile[it]*9216 + jr[it]*ROWB + jv[it]*16,
                       ksrc[jtile[it]] + (size_t)(64*D_) + (size_t)jr[it]*D_ + jv[it]*8);
        CP_COMMIT();
    }

    uint32_t qfh[4][4], qfl[4][4];
    {
        const int r0 = q0 + w*16 + grp;
#pragma unroll
        for (int ks = 0; ks < 4; ks++) {
            const int c = ks*16 + tig*2;
            qfh[ks][0] = *(const uint32_t*)(qhb + (size_t)r0*D_ + c);
            qfh[ks][1] = *(const uint32_t*)(qhb + (size_t)(r0+8)*D_ + c);
            qfh[ks][2] = *(const uint32_t*)(qhb + (size_t)r0*D_ + c + 8);
            qfh[ks][3] = *(const uint32_t*)(qhb + (size_t)(r0+8)*D_ + c + 8);
            qfl[ks][0] = *(const uint32_t*)(qlb + (size_t)r0*D_ + c);
            qfl[ks][1] = *(const uint32_t*)(qlb + (size_t)(r0+8)*D_ + c);
            qfl[ks][2] = *(const uint32_t*)(qlb + (size_t)r0*D_ + c + 8);
            qfl[ks][3] = *(const uint32_t*)(qlb + (size_t)(r0+8)*D_ + c + 8);
        }
    }

    float o[8][4];
#pragma unroll
    for (int t = 0; t < 8; t++)
#pragma unroll
        for (int e = 0; e < 4; e++) o[t][e] = 0.f;

    float m0 = -1e30f, m1 = -1e30f, l0 = 0.f, l1 = 0.f;

    const uint32_t koffA = (uint32_t)((lane & 7) * ROWB + (lane >> 3) * 16);
    const uint32_t voffA = (uint32_t)(((lane >> 3) * 8 + (lane & 7)) * ROWB);

    for (int kt = 0; kt <= qt; kt++) {
        const uint32_t kb = sbase + (kt % 3)*KVBUF;
        const uint32_t lb = kb + 9216;
        const uint32_t vb = kb + 18432;
        const uint32_t wb = kb + 27648;

        if (kt < qt) { CP_WAIT1(); } else { CP_WAIT0(); }
        __syncthreads();

        if (kt + 2 <= qt) {
            const uint32_t db = sbase + ((kt+2) % 3)*KVBUF;
            const size_t soff = (size_t)(kt+2)*64*D_;
#pragma unroll
            for (int it = 0; it < 16; it++)
                CP_ASYNC16(db + jtile[it]*9216 + jr[it]*ROWB + jv[it]*16,
                           ksrc[jtile[it]] + soff + (size_t)jr[it]*D_ + jv[it]*8);
            CP_COMMIT();
        }

        float s[8][4];
#pragma unroll
        for (int t = 0; t < 8; t++)
#pragma unroll
            for (int e = 0; e < 4; e++) s[t][e] = 0.f;

#pragma unroll
        for (int t = 0; t < 8; t++) {
#pragma unroll
            for (int kk2 = 0; kk2 < 2; kk2++) {
                uint32_t h0,h1,h2,h3, x0,x1,x2,x3;
                const uint32_t ka = kb + (uint32_t)(t*8*ROWB) + (uint32_t)(kk2*64) + koffA;
                const uint32_t la = lb + (uint32_t)(t*8*ROWB) + (uint32_t)(kk2*64) + koffA;
                LDSM_X4(h0,h1,h2,h3, ka);
                LDSM_X4(x0,x1,x2,x3, la);
                const int ks0 = 2*kk2, ks1 = 2*kk2 + 1;
                MMA_BF16(s[t], qfh[ks0][0],qfh[ks0][1],qfh[ks0][2],qfh[ks0][3], h0,h1);
                MMA_BF16(s[t], qfh[ks0][0],qfh[ks0][1],qfh[ks0][2],qfh[ks0][3], x0,x1);
                MMA_BF16(s[t], qfl[ks0][0],qfl[ks0][1],qfl[ks0][2],qfl[ks0][3], h0,h1);
                MMA_BF16(s[t], qfh[ks1][0],qfh[ks1][1],qfh[ks1][2],qfh[ks1][3], h2,h3);
                MMA_BF16(s[t], qfh[ks1][0],qfh[ks1][1],qfh[ks1][2],qfh[ks1][3], x2,x3);
                MMA_BF16(s[t], qfl[ks1][0],qfl[ks1][1],qfl[ks1][2],qfl[ks1][3], h2,h3);
            }
        }

        if (kt == qt) {
            const int i0 = w*16 + grp, i1 = i0 + 8;
#pragma unroll
            for (int t = 0; t < 8; t++) {
                const int j = t*8 + tig*2;
                if (j   > i0) s[t][0] = -1e30f;
                if (j+1 > i0) s[t][1] = -1e30f;
                if (j   > i1) s[t][2] = -1e30f;
                if (j+1 > i1) s[t][3] = -1e30f;
            }
        }

        float mx0 = -1e30f, mx1 = -1e30f;
#pragma unroll
        for (int t = 0; t < 8; t++) {
            mx0 = fmaxf(mx0, fmaxf(s[t][0], s[t][1]));
            mx1 = fmaxf(mx1, fmaxf(s[t][2], s[t][3]));
        }
        mx0 = fmaxf(mx0, __shfl_xor_sync(0xffffffffu, mx0, 1));
        mx0 = fmaxf(mx0, __shfl_xor_sync(0xffffffffu, mx0, 2));
        mx1 = fmaxf(mx1, __shfl_xor_sync(0xffffffffu, mx1, 1));
        mx1 = fmaxf(mx1, __shfl_xor_sync(0xffffffffu, mx1, 2));

        const float mn0 = fmaxf(m0, mx0), mn1 = fmaxf(m1, mx1);
        const float al0 = exp2p(m0 - mn0), al1 = exp2p(m1 - mn1);
        m0 = mn0; m1 = mn1;

        uint32_t pah0[8], pah1[8], pal0[8], pal1[8];
        float ps0 = 0.f, ps1 = 0.f;
#pragma unroll
        for (int t = 0; t < 8; t++) {
            const float p00 = exp2p(s[t][0] - mn0);
            const float p01 = exp2p(s[t][1] - mn0);
            const float p10 = exp2p(s[t][2] - mn1);
            const float p11 = exp2p(s[t][3] - mn1);
            ps0 += p00 + p01; ps1 += p10 + p11;
            PACK_BF2(pah0[t], p00, p01);
            PACK_BF2(pah1[t], p10, p11);
            const float r00 = p00 - __int_as_float(pah0[t] << 16);
            const float r01 = p01 - __int_as_float(pah0[t] & 0xffff0000u);
            const float r10 = p10 - __int_as_float(pah1[t] << 16);
            const float r11 = p11 - __int_as_float(pah1[t] & 0xffff0000u);
            PACK_BF2(pal0[t], r00, r01);
            PACK_BF2(pal1[t], r10, r11);
        }
        ps0 += __shfl_xor_sync(0xffffffffu, ps0, 1);
        ps0 += __shfl_xor_sync(0xffffffffu, ps0, 2);
        ps1 += __shfl_xor_sync(0xffffffffu, ps1, 1);
        ps1 += __shfl_xor_sync(0xffffffffu, ps1, 2);
        l0 = l0 * al0 + ps0;
        l1 = l1 * al1 + ps1;

#pragma unroll
        for (int t = 0; t < 8; t++) {
            o[t][0] *= al0; o[t][1] *= al0;
            o[t][2] *= al1; o[t][3] *= al1;
        }

#pragma unroll
        for (int t = 0; t < 8; t++) {
#pragma unroll
            for (int kk2 = 0; kk2 < 2; kk2++) {
                uint32_t h0,h1,h2,h3, x0,x1,x2,x3;
                const uint32_t va = vb + (uint32_t)(kk2*32*ROWB) + (uint32_t)(t*16) + voffA;
                const uint32_t wa = wb + (uint32_t)(kk2*32*ROWB) + (uint32_t)(t*16) + voffA;
                LDSM_X4T(h0,h1,h2,h3, va);
                LDSM_X4T(x0,x1,x2,x3, wa);
                const int ks0 = 2*kk2, ks1 = 2*kk2 + 1;
                MMA_BF16(o[t], pah0[2*ks0],pah1[2*ks0],pah0[2*ks0+1],pah1[2*ks0+1], h0,h1);
                MMA_BF16(o[t], pah0[2*ks0],pah1[2*ks0],pah0[2*ks0+1],pah1[2*ks0+1], x0,x1);
                MMA_BF16(o[t], pal0[2*ks0],pal1[2*ks0],pal0[2*ks0+1],pal1[2*ks0+1], h0,h1);
                MMA_BF16(o[t], pah0[2*ks1],pah1[2*ks1],pah0[2*ks1+1],pah1[2*ks1+1], h2,h3);
                MMA_BF16(o[t], pah0[2*ks1],pah1[2*ks1],pah0[2*ks1+1],pah1[2*ks1+1], x2,x3);
                MMA_BF16(o[t], pal0[2*ks1],pal1[2*ks1],pal0[2*ks1+1],pal1[2*ks1+1], h2,h3);
            }
        }
    }

    // ---- epilogue: normalize, fp16 split, store [M, C] ----
    const float il0 = 1.f / l0, il1 = 1.f / l1;
    const int r0g = q0 + w*16 + grp;
    const size_t base0 = ((size_t)(b*T_ + r0g)) * C_ + h*D_ + tig*2;
    const size_t base1 = ((size_t)(b*T_ + r0g + 8)) * C_ + h*D_ + tig*2;
#pragma unroll
    for (int t = 0; t < 8; t++) {
        const float v00 = o[t][0]*il0, v01 = o[t][1]*il0;
        const float v10 = o[t][2]*il1, v11 = o[t][3]*il1;
        const __half2 hp0 = __floats2half2_rn(v00, v01);
        const __half2 hp1 = __floats2half2_rn(v10, v11);
        const __half2 lp0 = __floats2half2_rn(v00 - __low2float(hp0), v01 - __high2float(hp0));
        const __half2 lp1 = __floats2half2_rn(v10 - __low2float(hp1), v11 - __high2float(hp1));
        *(__half2*)(ah_out + base0 + t*8) = hp0;
        *(__half2*)(ah_out + base1 + t*8) = hp1;
        *(__half2*)(al_out + base0 + t*8) = lp0;
        *(__half2*)(al_out + base1 + t*8) = lp1;
    }
}

// ---------------------------------------------------------------------------
extern "C" void kernel_launch(void* const* d_in, const int* in_sizes, int n_in,
                              void* d_out, int out_size)
{
    const float* x  = (const float*)d_in[0];
    const float* Wq = (const float*)d_in[1];
    const float* bq = (const float*)d_in[2];
    const float* Wk = (const float*)d_in[3];
    const float* bk = (const float*)d_in[4];
    const float* Wv = (const float*)d_in[5];
    const float* bv = (const float*)d_in[6];
    const float* Wo = (const float*)d_in[7];
    const float* bo = (const float*)d_in[8];
    float* out = (float*)d_out;

    float2* csp;
    hf *xh, *xl, *ah, *al;
    bf16 *qhp, *qlp, *khp, *klp, *vhp, *vlp;
    cudaGetSymbolAddress((void**)&csp,  g_cs);
    cudaGetSymbolAddress((void**)&xh,   g_xh);
    cudaGetSymbolAddress((void**)&xl,   g_xl);
    cudaGetSymbolAddress((void**)&ah,   g_ah);
    cudaGetSymbolAddress((void**)&al,   g_al);
    cudaGetSymbolAddress((void**)&qhp,  g_qh);
    cudaGetSymbolAddress((void**)&qlp,  g_ql);
    cudaGetSymbolAddress((void**)&khp,  g_kh);
    cudaGetSymbolAddress((void**)&klp,  g_kl);
    cudaGetSymbolAddress((void**)&vhp,  g_vh);
    cudaGetSymbolAddress((void**)&vlp,  g_vl);

    rope_table<<<(T_*32)/256, 256>>>(csp);

    cvt_split_h<<<(M_*C_/4)/256, 256>>>(x, xh, xl, M_*C_/4);
    cvt_w_h<<<dim3((C_*C_/4)/256, 1, 4), 256>>>(Wq, Wk, Wv, Wo);

    const size_t gsmem = 68096;  // sEpi(67584) + bias(512); stages alias (61440)
    cudaFuncSetAttribute(qkv_mma, cudaFuncAttributeMaxDynamicSharedMemorySize, (int)gsmem);
    cudaFuncSetAttribute(out_mma, cudaFuncAttributeMaxDynamicSharedMemorySize, (int)gsmem);
    cudaFuncSetAttribute(attn_fa2, cudaFuncAttributeMaxDynamicSharedMemorySize, ATTN_SMEM);

    qkv_mma<<<dim3(C_/128, M_/128, 3), 256, gsmem>>>(xh, xl, bq, bk, bv, csp);

    attn_fa2<<<dim3(T_/64, B_*H_), 128, ATTN_SMEM>>>(qhp, qlp, khp, klp, vhp, vlp, ah, al);

    out_mma<<<dim3(C_/128, M_/128), 256, gsmem>>>(ah, al, bo, out);
}